// round 5
// baseline (speedup 1.0000x reference)
#include <cuda_runtime.h>
#include <cuda_bf16.h>
#include <cuda_fp16.h>
#include <mma.h>
#include <cstdint>
#include <math.h>

using namespace nvcuda;

#define LEN    19947
#define NHEAD  8
#define DH     32
#define NLVL   4
#define NPTS   4

// ---------------------------------------------------------------------------
// Scratch (device globals)
// ---------------------------------------------------------------------------
__device__ __half g_value_h[LEN * 256];
__device__ float  g_off [LEN * 256];
__device__ float  g_attn[LEN * 128];
__device__ __nv_bfloat16 g_mid_hi[LEN * 256], g_mid_lo[LEN * 256];
__device__ __nv_bfloat16 g_q_hi [LEN * 256], g_q_lo [LEN * 256];
__device__ __nv_bfloat16 g_f_hi [LEN * 256], g_f_lo [LEN * 256];
// packed weights: [0,256)=W_val^T, [256,640)=[W_off|W_attn]^T, [640,896)=W_out^T
__device__ __nv_bfloat16 g_w_hi[896 * 256], g_w_lo[896 * 256];

__device__ __forceinline__ uint32_t smem_u32(const void* p) {
    uint32_t a;
    asm("{ .reg .u64 t; cvta.to.shared.u64 t, %1; cvt.u32.u64 %0, t; }" : "=r"(a) : "l"(p));
    return a;
}

// ---------------------------------------------------------------------------
// Prep kernels
// ---------------------------------------------------------------------------
__global__ void prep_weights_kernel(const float* __restrict__ W_val,
                                    const float* __restrict__ W_off,
                                    const float* __restrict__ W_attn,
                                    const float* __restrict__ W_out,
                                    __nv_bfloat16* __restrict__ hi,
                                    __nv_bfloat16* __restrict__ lo)
{
    int id = blockIdx.x * blockDim.x + threadIdx.x;
    if (id >= 896 * 256) return;
    int n = id >> 8;
    int k = id & 255;
    float x;
    if (n < 256)       x = W_val [k * 256 + n];
    else if (n < 512)  x = W_off [k * 256 + (n - 256)];
    else if (n < 640)  x = W_attn[k * 128 + (n - 512)];
    else               x = W_out [k * 256 + (n - 640)];
    __nv_bfloat16 h = __float2bfloat16_rn(x);
    hi[id] = h;
    lo[id] = __float2bfloat16_rn(x - __bfloat162float(h));
}

__global__ void prep_split_kernel(const float* __restrict__ query,
                                  const float* __restrict__ inflat,
                                  __nv_bfloat16* __restrict__ qhi, __nv_bfloat16* __restrict__ qlo,
                                  __nv_bfloat16* __restrict__ fhi, __nv_bfloat16* __restrict__ flo)
{
    const int total4 = LEN * 256 / 4;
    int id = blockIdx.x * blockDim.x + threadIdx.x;
    if (id >= 2 * total4) return;
    const float* src;
    __nv_bfloat16 *dhi, *dlo;
    int i4 = id;
    if (id < total4) { src = query;  dhi = qhi; dlo = qlo; }
    else             { src = inflat; dhi = fhi; dlo = flo; i4 -= total4; }
    float4 v = *reinterpret_cast<const float4*>(src + (size_t)i4 * 4);
    float f[4] = {v.x, v.y, v.z, v.w};
    __nv_bfloat16 h[4], l[4];
#pragma unroll
    for (int e = 0; e < 4; e++) {
        h[e] = __float2bfloat16_rn(f[e]);
        l[e] = __float2bfloat16_rn(f[e] - __bfloat162float(h[e]));
    }
    *reinterpret_cast<uint2*>(dhi + (size_t)i4 * 4) = *reinterpret_cast<uint2*>(h);
    *reinterpret_cast<uint2*>(dlo + (size_t)i4 * 4) = *reinterpret_cast<uint2*>(l);
}

// ---------------------------------------------------------------------------
// GEMM: 512 threads, 16 warps, warp tile 32x32, BK=32, 2-stage cp.async.
// bf16x3: acc = Ah*Bh + Al*Bh + Ah*Bl (fp32 accumulate).
// ---------------------------------------------------------------------------
#define ASTR 40
#define BUFB 10240
#define STAGEB (4 * BUFB)
#define CSTRIDE 132
#define GEMM_SMEM (2 * STAGEB)

#define CP16(dst, src, sz) \
    asm volatile("cp.async.cg.shared.global [%0], [%1], 16, %2;" \
                 :: "r"(dst), "l"(src), "r"(sz))
#define CP_COMMIT() asm volatile("cp.async.commit_group;")
#define CP_WAIT1()  asm volatile("cp.async.wait_group 1;")
#define CP_WAIT0()  asm volatile("cp.async.wait_group 0;")

__global__ __launch_bounds__(512, 1)
void gemm_bf16x3_kernel(const __nv_bfloat16* __restrict__ Ahi,
                        const __nv_bfloat16* __restrict__ Alo,
                        const __nv_bfloat16* __restrict__ Bhi,
                        const __nv_bfloat16* __restrict__ Blo,
                        const float* __restrict__ bias1,
                        const float* __restrict__ bias2,
                        const unsigned char* __restrict__ mask,
                        void* __restrict__ C1v, void* __restrict__ C2v,
                        int Mrows, int mode)
{
    extern __shared__ char smem[];
    const int tid  = threadIdx.x;
    const int warp = tid >> 5;
    const int wm   = warp & 3;     // 4 m-tiles of 32
    const int wn   = warp >> 2;    // 4 n-tiles of 32
    const int block_m = blockIdx.y * 128;
    const int block_n = blockIdx.x * 128;
    const uint32_t sb = smem_u32(smem);

    wmma::fragment<wmma::accumulator, 16, 16, 16, float> acc[2][2];
#pragma unroll
    for (int i = 0; i < 2; i++)
#pragma unroll
        for (int j = 0; j < 2; j++) wmma::fill_fragment(acc[i][j], 0.f);

    // cp.async: 512 chunks of 16B per buffer; thread t -> chunk t in each buffer
    const int lrow = tid >> 2;
    const int lprt = (tid & 3) * 8;
    const uint32_t so = (uint32_t)(lrow * ASTR + lprt) * 2;
    const int ga  = block_m + lrow;
    const int asz = (ga < Mrows) ? 16 : 0;

    auto issue = [&](int chunk) {
        const int s = chunk & 1;
        const int k0 = chunk * 32;
        const uint32_t sbase = sb + s * STAGEB;
        const size_t aoff = (size_t)ga * 256 + k0 + lprt;
        CP16(sbase + 0 * BUFB + so, Ahi + aoff, asz);
        CP16(sbase + 1 * BUFB + so, Alo + aoff, asz);
        const size_t boff = (size_t)(block_n + lrow) * 256 + k0 + lprt;
        CP16(sbase + 2 * BUFB + so, Bhi + boff, 16);
        CP16(sbase + 3 * BUFB + so, Blo + boff, 16);
    };

    issue(0);
    CP_COMMIT();

    for (int chunk = 0; chunk < 8; chunk++) {
        if (chunk < 7) { issue(chunk + 1); CP_COMMIT(); CP_WAIT1(); }
        else           { CP_WAIT0(); }
        __syncthreads();

        const int s = chunk & 1;
        const __nv_bfloat16* ahib = reinterpret_cast<const __nv_bfloat16*>(smem + s * STAGEB);
        const __nv_bfloat16* alob = ahib + 128 * ASTR;
        const __nv_bfloat16* bhib = alob + 128 * ASTR;
        const __nv_bfloat16* blob = bhib + 128 * ASTR;

#pragma unroll
        for (int ks = 0; ks < 32; ks += 16) {
            wmma::fragment<wmma::matrix_a, 16, 16, 16, __nv_bfloat16, wmma::row_major> fah[2], fal[2];
            wmma::fragment<wmma::matrix_b, 16, 16, 16, __nv_bfloat16, wmma::col_major> fbh[2], fbl[2];
#pragma unroll
            for (int i = 0; i < 2; i++)
                wmma::load_matrix_sync(fah[i], ahib + (wm * 32 + i * 16) * ASTR + ks, ASTR);
#pragma unroll
            for (int j = 0; j < 2; j++)
                wmma::load_matrix_sync(fbh[j], bhib + (wn * 32 + j * 16) * ASTR + ks, ASTR);
#pragma unroll
            for (int i = 0; i < 2; i++)
#pragma unroll
                for (int j = 0; j < 2; j++) wmma::mma_sync(acc[i][j], fah[i], fbh[j], acc[i][j]);
#pragma unroll
            for (int i = 0; i < 2; i++)
                wmma::load_matrix_sync(fal[i], alob + (wm * 32 + i * 16) * ASTR + ks, ASTR);
#pragma unroll
            for (int i = 0; i < 2; i++)
#pragma unroll
                for (int j = 0; j < 2; j++) wmma::mma_sync(acc[i][j], fal[i], fbh[j], acc[i][j]);
#pragma unroll
            for (int j = 0; j < 2; j++)
                wmma::load_matrix_sync(fbl[j], blob + (wn * 32 + j * 16) * ASTR + ks, ASTR);
#pragma unroll
            for (int i = 0; i < 2; i++)
#pragma unroll
                for (int j = 0; j < 2; j++) wmma::mma_sync(acc[i][j], fah[i], fbl[j], acc[i][j]);
        }
        __syncthreads();
    }

    // ---- stage accumulators (reuses pipeline smem) ----
    float* stage = reinterpret_cast<float*>(smem);
#pragma unroll
    for (int i = 0; i < 2; i++)
#pragma unroll
        for (int j = 0; j < 2; j++)
            wmma::store_matrix_sync(stage + (wm * 32 + i * 16) * CSTRIDE + wn * 32 + j * 16,
                                    acc[i][j], CSTRIDE, wmma::mem_row_major);
    __syncthreads();

    // ---- epilogue: r = tid>>2, 32 cols per thread ----
    {
        const int r  = tid >> 2;
        const int gr = block_m + r;
        if (gr < Mrows) {
            const int colb = (tid & 3) * 32;
#pragma unroll
            for (int g = 0; g < 32; g += 16) {
                const int gcol = block_n + colb + g;
                float v[16];
                if (mode == 2 && gcol >= 256) {
#pragma unroll
                    for (int c = 0; c < 16; c++)
                        v[c] = stage[r * CSTRIDE + colb + g + c] + __ldg(bias2 + gcol - 256 + c);
                    float mx = -1e30f;
#pragma unroll
                    for (int c = 0; c < 16; c++) mx = fmaxf(mx, v[c]);
                    float sum = 0.f;
#pragma unroll
                    for (int c = 0; c < 16; c++) { v[c] = __expf(v[c] - mx); sum += v[c]; }
                    float inv = 1.f / sum;
                    float* C2 = reinterpret_cast<float*>(C2v);
#pragma unroll
                    for (int c = 0; c < 16; c += 4) {
                        float4 o = make_float4(v[c]*inv, v[c+1]*inv, v[c+2]*inv, v[c+3]*inv);
                        *reinterpret_cast<float4*>(C2 + (size_t)gr * 128 + gcol - 256 + c) = o;
                    }
                } else {
#pragma unroll
                    for (int c = 0; c < 16; c++)
                        v[c] = stage[r * CSTRIDE + colb + g + c] + __ldg(bias1 + gcol + c);
                    if (mode == 1) {
                        float scale = (mask != nullptr && mask[gr]) ? 0.f : 1.f;
                        __half* C1 = reinterpret_cast<__half*>(C1v);
                        __half hbuf[16];
#pragma unroll
                        for (int c = 0; c < 16; c++) hbuf[c] = __float2half_rn(v[c] * scale);
#pragma unroll
                        for (int c = 0; c < 16; c += 8)
                            *reinterpret_cast<uint4*>(C1 + (size_t)gr * 256 + gcol + c) =
                                *reinterpret_cast<uint4*>(hbuf + c);
                    } else {
                        float* C1 = reinterpret_cast<float*>(C1v);
#pragma unroll
                        for (int c = 0; c < 16; c += 4) {
                            float4 o = make_float4(v[c], v[c+1], v[c+2], v[c+3]);
                            *reinterpret_cast<float4*>(C1 + (size_t)gr * 256 + gcol + c) = o;
                        }
                    }
                }
            }
        }
    }
}

// ---------------------------------------------------------------------------
// Sampler: block per query, warp per head, lane = channel.
// Coalesced off/aw/ref loads + shfl broadcast; unconditional clamped gathers
// with validity folded into weights -> maximal MLP.
// ---------------------------------------------------------------------------
__global__ __launch_bounds__(256)
void sample_kernel(const __half* __restrict__ value,
                   const float* __restrict__ off,
                   const float* __restrict__ aw,
                   const float* __restrict__ refp,
                   __nv_bfloat16* __restrict__ midhi,
                   __nv_bfloat16* __restrict__ midlo)
{
    const int q    = blockIdx.x;
    const int m    = threadIdx.x >> 5;
    const int lane = threadIdx.x & 31;

    // coalesced parameter loads (one 128B + one 64B + one 32B load per warp)
    const float offv = __ldg(off + (size_t)q * 256 + m * 32 + lane);          // 32 floats/head
    const float awv  = (lane < 16) ? __ldg(aw + (size_t)q * 128 + m * 16 + lane) : 0.f;
    const float rfv  = (lane < 8)  ? __ldg(refp + (size_t)q * 8 + lane) : 0.f; // (l,xy)

    const __half* vbase = value + m * DH + lane;
    float acc = 0.f;

    const int   HH[NLVL] = {100, 50, 25, 13};
    const int   WW[NLVL] = {150, 75, 38, 19};
    const int   ST[NLVL] = {0, 15000, 18750, 19700};

#pragma unroll
    for (int l = 0; l < NLVL; l++) {
        const float rx = __shfl_sync(0xffffffffu, rfv, l * 2 + 0);
        const float ry = __shfl_sync(0xffffffffu, rfv, l * 2 + 1);
        const int W = WW[l], H = HH[l], start = ST[l];
        const float Wf = (float)W, Hf = (float)H;

#pragma unroll
        for (int p = 0; p < NPTS; p++) {
            const int pi = l * NPTS + p;
            const float ox = __shfl_sync(0xffffffffu, offv, pi * 2 + 0);
            const float oy = __shfl_sync(0xffffffffu, offv, pi * 2 + 1);
            const float a  = __shfl_sync(0xffffffffu, awv,  pi);

            float gx = 2.f * (rx + ox / Wf) - 1.f;
            float gy = 2.f * (ry + oy / Hf) - 1.f;
            gx = fminf(fmaxf(gx, -2.f), 2.f);
            gy = fminf(fmaxf(gy, -2.f), 2.f);

            const float x = (gx + 1.f) * (Wf * 0.5f) - 0.5f;
            const float y = (gy + 1.f) * (Hf * 0.5f) - 0.5f;

            const float x0f = floorf(x), y0f = floorf(y);
            const float wx1 = x - x0f, wx0 = 1.f - wx1;
            const float wy1 = y - y0f, wy0 = 1.f - wy1;
            const int x0 = (int)x0f, y0 = (int)y0f;
            const int x1 = x0 + 1,  y1 = y0 + 1;

            // validity folded into weights; indices clamped (no branches)
            const float fx0 = (x0 >= 0 && x0 < W) ? wx0 : 0.f;
            const float fx1 = (x1 >= 0 && x1 < W) ? wx1 : 0.f;
            const float fy0 = (y0 >= 0 && y0 < H) ? wy0 : 0.f;
            const float fy1 = (y1 >= 0 && y1 < H) ? wy1 : 0.f;

            const int cx0 = min(max(x0, 0), W - 1);
            const int cx1 = min(max(x1, 0), W - 1);
            const int cy0 = min(max(y0, 0), H - 1);
            const int cy1 = min(max(y1, 0), H - 1);

            const float v00 = __half2float(__ldg(vbase + (size_t)(start + cy0 * W + cx0) * 256));
            const float v01 = __half2float(__ldg(vbase + (size_t)(start + cy0 * W + cx1) * 256));
            const float v10 = __half2float(__ldg(vbase + (size_t)(start + cy1 * W + cx0) * 256));
            const float v11 = __half2float(__ldg(vbase + (size_t)(start + cy1 * W + cx1) * 256));

            float s = fx0 * fy0 * v00;
            s = fmaf(fx1 * fy0, v01, s);
            s = fmaf(fx0 * fy1, v10, s);
            s = fmaf(fx1 * fy1, v11, s);
            acc = fmaf(a, s, acc);
        }
    }
    const size_t oi = (size_t)q * 256 + m * DH + lane;
    __nv_bfloat16 h = __float2bfloat16_rn(acc);
    midhi[oi] = h;
    midlo[oi] = __float2bfloat16_rn(acc - __bfloat162float(h));
}

// ---------------------------------------------------------------------------
// Launch
// ---------------------------------------------------------------------------
extern "C" void kernel_launch(void* const* d_in, const int* in_sizes, int n_in,
                              void* d_out, int out_size)
{
    const float* query  = (const float*)d_in[0];
    const float* refp   = (const float*)d_in[1];
    const float* inflat = (const float*)d_in[2];
    const unsigned char* pmask = (const unsigned char*)d_in[3];
    const float* W_off  = (const float*)d_in[4];
    const float* b_off  = (const float*)d_in[5];
    const float* W_attn = (const float*)d_in[6];
    const float* b_attn = (const float*)d_in[7];
    const float* W_val  = (const float*)d_in[8];
    const float* b_val  = (const float*)d_in[9];
    const float* W_out  = (const float*)d_in[10];
    const float* b_out  = (const float*)d_in[11];
    float* out = (float*)d_out;

    __half* pval;   cudaGetSymbolAddress((void**)&pval,  g_value_h);
    float*  poff;   cudaGetSymbolAddress((void**)&poff,  g_off);
    float*  pattn;  cudaGetSymbolAddress((void**)&pattn, g_attn);
    __nv_bfloat16 *mid_hi, *mid_lo, *q_hi, *q_lo, *f_hi, *f_lo, *w_hi, *w_lo;
    cudaGetSymbolAddress((void**)&mid_hi, g_mid_hi);
    cudaGetSymbolAddress((void**)&mid_lo, g_mid_lo);
    cudaGetSymbolAddress((void**)&q_hi, g_q_hi);
    cudaGetSymbolAddress((void**)&q_lo, g_q_lo);
    cudaGetSymbolAddress((void**)&f_hi, g_f_hi);
    cudaGetSymbolAddress((void**)&f_lo, g_f_lo);
    cudaGetSymbolAddress((void**)&w_hi, g_w_hi);
    cudaGetSymbolAddress((void**)&w_lo, g_w_lo);

    cudaFuncSetAttribute(gemm_bf16x3_kernel,
                         cudaFuncAttributeMaxDynamicSharedMemorySize, GEMM_SMEM);

    const int Mr = LEN;
    const int mtiles = (Mr + 127) / 128;

    prep_weights_kernel<<<(896 * 256 + 255) / 256, 256>>>(W_val, W_off, W_attn, W_out, w_hi, w_lo);
    prep_split_kernel<<<(2 * LEN * 64 + 255) / 256, 256>>>(query, inflat, q_hi, q_lo, f_hi, f_lo);

    const __nv_bfloat16* wv_hi = w_hi;              const __nv_bfloat16* wv_lo = w_lo;
    const __nv_bfloat16* woa_hi = w_hi + 256 * 256; const __nv_bfloat16* woa_lo = w_lo + 256 * 256;
    const __nv_bfloat16* wu_hi = w_hi + 640 * 256;  const __nv_bfloat16* wu_lo = w_lo + 640 * 256;

    // 1. value projection -> fp16 (mode 1, mask)
    gemm_bf16x3_kernel<<<dim3(2, mtiles), 512, GEMM_SMEM>>>(
        f_hi, f_lo, wv_hi, wv_lo, b_val, nullptr, pmask, pval, nullptr, Mr, 1);
    // 2. offsets + attn logits + softmax (mode 2, N=384)
    gemm_bf16x3_kernel<<<dim3(3, mtiles), 512, GEMM_SMEM>>>(
        q_hi, q_lo, woa_hi, woa_lo, b_off, b_attn, nullptr, poff, pattn, Mr, 2);
    // 3. sampler
    sample_kernel<<<Mr, 256>>>(pval, poff, pattn, refp, mid_hi, mid_lo);
    // 4. output projection (mode 0)
    gemm_bf16x3_kernel<<<dim3(2, mtiles), 512, GEMM_SMEM>>>(
        mid_hi, mid_lo, wu_hi, wu_lo, b_out, nullptr, nullptr, out, nullptr, Mr, 0);
}

// round 6
// speedup vs baseline: 1.3353x; 1.3353x over previous
#include <cuda_runtime.h>
#include <cuda_bf16.h>
#include <cuda_fp16.h>
#include <mma.h>
#include <cstdint>
#include <math.h>

using namespace nvcuda;

#define LEN    19947
#define NHEAD  8
#define DH     32
#define NLVL   4
#define NPTS   4

// ---------------------------------------------------------------------------
// Scratch (device globals)
// ---------------------------------------------------------------------------
__device__ __half g_value_h[LEN * 256];
__device__ float  g_off [LEN * 256];
__device__ float  g_attn[LEN * 128];
__device__ __nv_bfloat16 g_mid_hi[LEN * 256], g_mid_lo[LEN * 256];
__device__ __half g_q_h[LEN * 256];     // query fp16
__device__ __half g_f_h[LEN * 256];     // inflat fp16
// fp16 weights: [0,256)=W_val^T, [256,640)=[W_off|W_attn]^T
__device__ __half g_w_h[640 * 256];
// bf16 hi/lo W_out^T for compensated out-projection
__device__ __nv_bfloat16 g_wu_hi[256 * 256], g_wu_lo[256 * 256];

__device__ __forceinline__ uint32_t smem_u32(const void* p) {
    uint32_t a;
    asm("{ .reg .u64 t; cvta.to.shared.u64 t, %1; cvt.u32.u64 %0, t; }" : "=r"(a) : "l"(p));
    return a;
}

// ---------------------------------------------------------------------------
// Prep kernels
// ---------------------------------------------------------------------------
__global__ void prep_weights_kernel(const float* __restrict__ W_val,
                                    const float* __restrict__ W_off,
                                    const float* __restrict__ W_attn,
                                    const float* __restrict__ W_out,
                                    __half* __restrict__ wh,
                                    __nv_bfloat16* __restrict__ uhi,
                                    __nv_bfloat16* __restrict__ ulo)
{
    int id = blockIdx.x * blockDim.x + threadIdx.x;
    if (id >= 896 * 256) return;
    int n = id >> 8;
    int k = id & 255;
    if (n < 640) {
        float x;
        if (n < 256)      x = W_val [k * 256 + n];
        else if (n < 512) x = W_off [k * 256 + (n - 256)];
        else              x = W_attn[k * 128 + (n - 512)];
        wh[id] = __float2half_rn(x);
    } else {
        float x = W_out[k * 256 + (n - 640)];
        __nv_bfloat16 h = __float2bfloat16_rn(x);
        uhi[(n - 640) * 256 + k] = h;
        ulo[(n - 640) * 256 + k] = __float2bfloat16_rn(x - __bfloat162float(h));
    }
}

__global__ void prep_split_kernel(const float* __restrict__ query,
                                  const float* __restrict__ inflat,
                                  __half* __restrict__ qh,
                                  __half* __restrict__ fh)
{
    const int total4 = LEN * 256 / 4;
    int id = blockIdx.x * blockDim.x + threadIdx.x;
    if (id >= 2 * total4) return;
    const float* src;
    __half* dst;
    int i4 = id;
    if (id < total4) { src = query;  dst = qh; }
    else             { src = inflat; dst = fh; i4 -= total4; }
    float4 v = *reinterpret_cast<const float4*>(src + (size_t)i4 * 4);
    __half h[4] = {__float2half_rn(v.x), __float2half_rn(v.y),
                   __float2half_rn(v.z), __float2half_rn(v.w)};
    *reinterpret_cast<uint2*>(dst + (size_t)i4 * 4) = *reinterpret_cast<uint2*>(h);
}

// ---------------------------------------------------------------------------
// common cp.async macros
// ---------------------------------------------------------------------------
#define CP16(dst, src, sz) \
    asm volatile("cp.async.cg.shared.global [%0], [%1], 16, %2;" \
                 :: "r"(dst), "l"(src), "r"(sz))
#define CP_COMMIT() asm volatile("cp.async.commit_group;")
#define CP_WAIT1()  asm volatile("cp.async.wait_group 1;")
#define CP_WAIT0()  asm volatile("cp.async.wait_group 0;")

#define ASTR 40
#define BUFB 10240                 // 128*40*2 bytes
#define CSTRIDE 132

// ---------------------------------------------------------------------------
// fp16 single-pass GEMM: C = A @ B^T + bias.
// 256 threads, 8 warps (warp tile 32x64), BK=32, 2-stage cp.async pipeline.
// mode 1: half out C1 (+bias1, mask zeroing)  [value projection]
// mode 2: dual: col<256 -> float C1 (+bias1); col>=256 -> softmax16 C2 (+bias2)
// ---------------------------------------------------------------------------
#define H_STAGEB (2 * BUFB)                  // 20480 per stage (A + B)
#define H_SMEM   (128 * CSTRIDE * 4)         // 67584 (epilogue stage dominates)

__global__ __launch_bounds__(256, 2)
void gemm_fp16_kernel(const __half* __restrict__ A,
                      const __half* __restrict__ B,
                      const float* __restrict__ bias1,
                      const float* __restrict__ bias2,
                      const unsigned char* __restrict__ mask,
                      void* __restrict__ C1v, void* __restrict__ C2v,
                      int Mrows, int mode)
{
    extern __shared__ char smem[];
    const int tid  = threadIdx.x;
    const int warp = tid >> 5;
    const int wm   = warp & 3;
    const int wn   = warp >> 2;
    const int block_m = blockIdx.y * 128;
    const int block_n = blockIdx.x * 128;
    const uint32_t sb = smem_u32(smem);

    wmma::fragment<wmma::accumulator, 16, 16, 16, float> acc[2][4];
#pragma unroll
    for (int i = 0; i < 2; i++)
#pragma unroll
        for (int j = 0; j < 4; j++) wmma::fill_fragment(acc[i][j], 0.f);

    auto issue = [&](int chunk) {
        const int s = chunk & 1;
        const int k0 = chunk * 32;
        const uint32_t sbase = sb + s * H_STAGEB;
#pragma unroll
        for (int h = 0; h < 2; h++) {
            const int c   = tid + h * 256;
            const int row = c >> 2;
            const int prt = (c & 3) * 8;
            const uint32_t so = (uint32_t)(row * ASTR + prt) * 2;
            const int ga  = block_m + row;
            const int asz = (ga < Mrows) ? 16 : 0;
            CP16(sbase + 0 * BUFB + so, A + (size_t)ga * 256 + k0 + prt, asz);
            CP16(sbase + 1 * BUFB + so, B + (size_t)(block_n + row) * 256 + k0 + prt, 16);
        }
    };

    issue(0);
    CP_COMMIT();

    for (int chunk = 0; chunk < 8; chunk++) {
        if (chunk < 7) { issue(chunk + 1); CP_COMMIT(); CP_WAIT1(); }
        else           { CP_WAIT0(); }
        __syncthreads();

        const int s = chunk & 1;
        const __half* ab = reinterpret_cast<const __half*>(smem + s * H_STAGEB);
        const __half* bb = ab + 128 * ASTR;

#pragma unroll
        for (int ks = 0; ks < 32; ks += 16) {
            wmma::fragment<wmma::matrix_a, 16, 16, 16, __half, wmma::row_major> fa[2];
            wmma::fragment<wmma::matrix_b, 16, 16, 16, __half, wmma::col_major> fb[4];
#pragma unroll
            for (int i = 0; i < 2; i++)
                wmma::load_matrix_sync(fa[i], ab + (wm * 32 + i * 16) * ASTR + ks, ASTR);
#pragma unroll
            for (int j = 0; j < 4; j++)
                wmma::load_matrix_sync(fb[j], bb + (wn * 64 + j * 16) * ASTR + ks, ASTR);
#pragma unroll
            for (int i = 0; i < 2; i++)
#pragma unroll
                for (int j = 0; j < 4; j++) wmma::mma_sync(acc[i][j], fa[i], fb[j], acc[i][j]);
        }
        __syncthreads();
    }

    float* stage = reinterpret_cast<float*>(smem);
#pragma unroll
    for (int i = 0; i < 2; i++)
#pragma unroll
        for (int j = 0; j < 4; j++)
            wmma::store_matrix_sync(stage + (wm * 32 + i * 16) * CSTRIDE + wn * 64 + j * 16,
                                    acc[i][j], CSTRIDE, wmma::mem_row_major);
    __syncthreads();

    {
        const int r  = tid >> 1;
        const int gr = block_m + r;
        if (gr < Mrows) {
            const int colb = (tid & 1) * 64;
#pragma unroll
            for (int g = 0; g < 64; g += 16) {
                const int gcol = block_n + colb + g;
                float v[16];
                if (mode == 2 && gcol >= 256) {
#pragma unroll
                    for (int c = 0; c < 16; c++)
                        v[c] = stage[r * CSTRIDE + colb + g + c] + __ldg(bias2 + gcol - 256 + c);
                    float mx = -1e30f;
#pragma unroll
                    for (int c = 0; c < 16; c++) mx = fmaxf(mx, v[c]);
                    float sum = 0.f;
#pragma unroll
                    for (int c = 0; c < 16; c++) { v[c] = __expf(v[c] - mx); sum += v[c]; }
                    float inv = 1.f / sum;
                    float* C2 = reinterpret_cast<float*>(C2v);
#pragma unroll
                    for (int c = 0; c < 16; c += 4) {
                        float4 o = make_float4(v[c]*inv, v[c+1]*inv, v[c+2]*inv, v[c+3]*inv);
                        *reinterpret_cast<float4*>(C2 + (size_t)gr * 128 + gcol - 256 + c) = o;
                    }
                } else {
#pragma unroll
                    for (int c = 0; c < 16; c++)
                        v[c] = stage[r * CSTRIDE + colb + g + c] + __ldg(bias1 + gcol + c);
                    if (mode == 1) {
                        float scale = (mask != nullptr && mask[gr]) ? 0.f : 1.f;
                        __half* C1 = reinterpret_cast<__half*>(C1v);
                        __half hbuf[16];
#pragma unroll
                        for (int c = 0; c < 16; c++) hbuf[c] = __float2half_rn(v[c] * scale);
#pragma unroll
                        for (int c = 0; c < 16; c += 8)
                            *reinterpret_cast<uint4*>(C1 + (size_t)gr * 256 + gcol + c) =
                                *reinterpret_cast<uint4*>(hbuf + c);
                    } else {
                        float* C1 = reinterpret_cast<float*>(C1v);
#pragma unroll
                        for (int c = 0; c < 16; c += 4) {
                            float4 o = make_float4(v[c], v[c+1], v[c+2], v[c+3]);
                            *reinterpret_cast<float4*>(C1 + (size_t)gr * 256 + gcol + c) = o;
                        }
                    }
                }
            }
        }
    }
}

// ---------------------------------------------------------------------------
// bf16x3 compensated GEMM (round-4 proven config) — output projection only.
// 256 threads, warp tile 32x64, BK=32, 2-stage cp.async.
// ---------------------------------------------------------------------------
#define STAGEB (4 * BUFB)
#define GEMM_SMEM (2 * STAGEB)

__global__ __launch_bounds__(256, 1)
void gemm_bf16x3_kernel(const __nv_bfloat16* __restrict__ Ahi,
                        const __nv_bfloat16* __restrict__ Alo,
                        const __nv_bfloat16* __restrict__ Bhi,
                        const __nv_bfloat16* __restrict__ Blo,
                        const float* __restrict__ bias1,
                        float* __restrict__ C1,
                        int Mrows)
{
    extern __shared__ char smem[];
    const int tid  = threadIdx.x;
    const int warp = tid >> 5;
    const int wm   = warp & 3;
    const int wn   = warp >> 2;
    const int block_m = blockIdx.y * 128;
    const int block_n = blockIdx.x * 128;
    const uint32_t sb = smem_u32(smem);

    wmma::fragment<wmma::accumulator, 16, 16, 16, float> acc[2][4];
#pragma unroll
    for (int i = 0; i < 2; i++)
#pragma unroll
        for (int j = 0; j < 4; j++) wmma::fill_fragment(acc[i][j], 0.f);

    auto issue = [&](int chunk) {
        const int s = chunk & 1;
        const int k0 = chunk * 32;
        const uint32_t sbase = sb + s * STAGEB;
#pragma unroll
        for (int h = 0; h < 2; h++) {
            const int c   = tid + h * 256;
            const int row = c >> 2;
            const int prt = (c & 3) * 8;
            const uint32_t so = (uint32_t)(row * ASTR + prt) * 2;
            const int ga  = block_m + row;
            const int asz = (ga < Mrows) ? 16 : 0;
            const size_t aoff = (size_t)ga * 256 + k0 + prt;
            CP16(sbase + 0 * BUFB + so, Ahi + aoff, asz);
            CP16(sbase + 1 * BUFB + so, Alo + aoff, asz);
            const size_t boff = (size_t)(block_n + row) * 256 + k0 + prt;
            CP16(sbase + 2 * BUFB + so, Bhi + boff, 16);
            CP16(sbase + 3 * BUFB + so, Blo + boff, 16);
        }
    };

    issue(0);
    CP_COMMIT();

    for (int chunk = 0; chunk < 8; chunk++) {
        if (chunk < 7) { issue(chunk + 1); CP_COMMIT(); CP_WAIT1(); }
        else           { CP_WAIT0(); }
        __syncthreads();

        const int s = chunk & 1;
        const __nv_bfloat16* ahib = reinterpret_cast<const __nv_bfloat16*>(smem + s * STAGEB);
        const __nv_bfloat16* alob = ahib + 128 * ASTR;
        const __nv_bfloat16* bhib = alob + 128 * ASTR;
        const __nv_bfloat16* blob = bhib + 128 * ASTR;

#pragma unroll
        for (int ks = 0; ks < 32; ks += 16) {
            wmma::fragment<wmma::matrix_a, 16, 16, 16, __nv_bfloat16, wmma::row_major> fah[2], fal[2];
            wmma::fragment<wmma::matrix_b, 16, 16, 16, __nv_bfloat16, wmma::col_major> fbh[4], fbl[4];
#pragma unroll
            for (int i = 0; i < 2; i++)
                wmma::load_matrix_sync(fah[i], ahib + (wm * 32 + i * 16) * ASTR + ks, ASTR);
#pragma unroll
            for (int j = 0; j < 4; j++)
                wmma::load_matrix_sync(fbh[j], bhib + (wn * 64 + j * 16) * ASTR + ks, ASTR);
#pragma unroll
            for (int i = 0; i < 2; i++)
#pragma unroll
                for (int j = 0; j < 4; j++) wmma::mma_sync(acc[i][j], fah[i], fbh[j], acc[i][j]);
#pragma unroll
            for (int i = 0; i < 2; i++)
                wmma::load_matrix_sync(fal[i], alob + (wm * 32 + i * 16) * ASTR + ks, ASTR);
#pragma unroll
            for (int i = 0; i < 2; i++)
#pragma unroll
                for (int j = 0; j < 4; j++) wmma::mma_sync(acc[i][j], fal[i], fbh[j], acc[i][j]);
#pragma unroll
            for (int j = 0; j < 4; j++)
                wmma::load_matrix_sync(fbl[j], blob + (wn * 64 + j * 16) * ASTR + ks, ASTR);
#pragma unroll
            for (int i = 0; i < 2; i++)
#pragma unroll
                for (int j = 0; j < 4; j++) wmma::mma_sync(acc[i][j], fah[i], fbl[j], acc[i][j]);
        }
        __syncthreads();
    }

    float* stage = reinterpret_cast<float*>(smem);
#pragma unroll
    for (int i = 0; i < 2; i++)
#pragma unroll
        for (int j = 0; j < 4; j++)
            wmma::store_matrix_sync(stage + (wm * 32 + i * 16) * CSTRIDE + wn * 64 + j * 16,
                                    acc[i][j], CSTRIDE, wmma::mem_row_major);
    __syncthreads();

    {
        const int r  = tid >> 1;
        const int gr = block_m + r;
        if (gr < Mrows) {
            const int colb = (tid & 1) * 64;
#pragma unroll
            for (int g = 0; g < 64; g += 16) {
                const int gcol = block_n + colb + g;
                float v[16];
#pragma unroll
                for (int c = 0; c < 16; c++)
                    v[c] = stage[r * CSTRIDE + colb + g + c] + __ldg(bias1 + gcol + c);
#pragma unroll
                for (int c = 0; c < 16; c += 4) {
                    float4 o = make_float4(v[c], v[c+1], v[c+2], v[c+3]);
                    *reinterpret_cast<float4*>(C1 + (size_t)gr * 256 + gcol + c) = o;
                }
            }
        }
    }
}

// ---------------------------------------------------------------------------
// Sampler (round-4 proven version): block per query, warp per head, lane=chan.
// ---------------------------------------------------------------------------
__global__ __launch_bounds__(256)
void sample_kernel(const __half* __restrict__ value,
                   const float* __restrict__ off,
                   const float* __restrict__ aw,
                   const float* __restrict__ refp,
                   __nv_bfloat16* __restrict__ midhi,
                   __nv_bfloat16* __restrict__ midlo)
{
    const int q    = blockIdx.x;
    const int m    = threadIdx.x >> 5;
    const int lane = threadIdx.x & 31;

    const int HH[NLVL] = {100, 50, 25, 13};
    const int WW[NLVL] = {150, 75, 38, 19};
    const int ST[NLVL] = {0, 15000, 18750, 19700};

    const __half* vbase = value + m * DH + lane;
    float acc = 0.f;

#pragma unroll
    for (int l = 0; l < NLVL; l++) {
        const float rx = __ldg(refp + ((size_t)q * NLVL + l) * 2 + 0);
        const float ry = __ldg(refp + ((size_t)q * NLVL + l) * 2 + 1);
        const int W = WW[l], H = HH[l], start = ST[l];
        const float Wf = (float)W, Hf = (float)H;

#pragma unroll
        for (int p = 0; p < NPTS; p++) {
            const int oc = ((m * NLVL + l) * NPTS + p) * 2;
            const float ox = __ldg(off + (size_t)q * 256 + oc + 0);
            const float oy = __ldg(off + (size_t)q * 256 + oc + 1);

            float gx = 2.f * (rx + ox / Wf) - 1.f;
            float gy = 2.f * (ry + oy / Hf) - 1.f;
            gx = fminf(fmaxf(gx, -2.f), 2.f);
            gy = fminf(fmaxf(gy, -2.f), 2.f);

            const float x = (gx + 1.f) * (Wf * 0.5f) - 0.5f;
            const float y = (gy + 1.f) * (Hf * 0.5f) - 0.5f;

            const float x0f = floorf(x), y0f = floorf(y);
            const float wx1 = x - x0f, wx0 = 1.f - wx1;
            const float wy1 = y - y0f, wy0 = 1.f - wy1;
            const int x0 = (int)x0f, y0 = (int)y0f;
            const int x1 = x0 + 1,  y1 = y0 + 1;

            const bool vx0 = (x0 >= 0) & (x0 < W);
            const bool vx1 = (x1 >= 0) & (x1 < W);
            const bool vy0 = (y0 >= 0) & (y0 < H);
            const bool vy1 = (y1 >= 0) & (y1 < H);

            float s = 0.f;
            if (vx0 & vy0) s += (wx0 * wy0) * __half2float(__ldg(vbase + (size_t)(start + y0 * W + x0) * 256));
            if (vx1 & vy0) s += (wx1 * wy0) * __half2float(__ldg(vbase + (size_t)(start + y0 * W + x1) * 256));
            if (vx0 & vy1) s += (wx0 * wy1) * __half2float(__ldg(vbase + (size_t)(start + y1 * W + x0) * 256));
            if (vx1 & vy1) s += (wx1 * wy1) * __half2float(__ldg(vbase + (size_t)(start + y1 * W + x1) * 256));

            const float a = __ldg(aw + (size_t)q * 128 + m * 16 + l * NPTS + p);
            acc = fmaf(a, s, acc);
        }
    }
    const size_t oi = (size_t)q * 256 + m * DH + lane;
    __nv_bfloat16 h = __float2bfloat16_rn(acc);
    midhi[oi] = h;
    midlo[oi] = __float2bfloat16_rn(acc - __bfloat162float(h));
}

// ---------------------------------------------------------------------------
// Launch
// ---------------------------------------------------------------------------
extern "C" void kernel_launch(void* const* d_in, const int* in_sizes, int n_in,
                              void* d_out, int out_size)
{
    const float* query  = (const float*)d_in[0];
    const float* refp   = (const float*)d_in[1];
    const float* inflat = (const float*)d_in[2];
    const unsigned char* pmask = (const unsigned char*)d_in[3];
    const float* W_off  = (const float*)d_in[4];
    const float* b_off  = (const float*)d_in[5];
    const float* W_attn = (const float*)d_in[6];
    const float* b_attn = (const float*)d_in[7];
    const float* W_val  = (const float*)d_in[8];
    const float* b_val  = (const float*)d_in[9];
    const float* W_out  = (const float*)d_in[10];
    const float* b_out  = (const float*)d_in[11];
    float* out = (float*)d_out;

    __half* pval;   cudaGetSymbolAddress((void**)&pval,  g_value_h);
    float*  poff;   cudaGetSymbolAddress((void**)&poff,  g_off);
    float*  pattn;  cudaGetSymbolAddress((void**)&pattn, g_attn);
    __half *q_h, *f_h, *w_h;
    cudaGetSymbolAddress((void**)&q_h, g_q_h);
    cudaGetSymbolAddress((void**)&f_h, g_f_h);
    cudaGetSymbolAddress((void**)&w_h, g_w_h);
    __nv_bfloat16 *mid_hi, *mid_lo, *wu_hi, *wu_lo;
    cudaGetSymbolAddress((void**)&mid_hi, g_mid_hi);
    cudaGetSymbolAddress((void**)&mid_lo, g_mid_lo);
    cudaGetSymbolAddress((void**)&wu_hi, g_wu_hi);
    cudaGetSymbolAddress((void**)&wu_lo, g_wu_lo);

    cudaFuncSetAttribute(gemm_fp16_kernel,
                         cudaFuncAttributeMaxDynamicSharedMemorySize, H_SMEM);
    cudaFuncSetAttribute(gemm_bf16x3_kernel,
                         cudaFuncAttributeMaxDynamicSharedMemorySize, GEMM_SMEM);

    const int Mr = LEN;
    const int mtiles = (Mr + 127) / 128;

    prep_weights_kernel<<<(896 * 256 + 255) / 256, 256>>>(W_val, W_off, W_attn, W_out,
                                                          w_h, wu_hi, wu_lo);
    prep_split_kernel<<<(2 * LEN * 64 + 255) / 256, 256>>>(query, inflat, q_h, f_h);

    const __half* wv = w_h;                // rows [0,256)
    const __half* woa = w_h + 256 * 256;   // rows [256,640)

    // 1. value projection -> fp16 (mode 1, mask)
    gemm_fp16_kernel<<<dim3(2, mtiles), 256, H_SMEM>>>(
        f_h, wv, b_val, nullptr, pmask, pval, nullptr, Mr, 1);
    // 2. offsets + attn logits + fused softmax (mode 2, N=384)
    gemm_fp16_kernel<<<dim3(3, mtiles), 256, H_SMEM>>>(
        q_h, woa, b_off, b_attn, nullptr, poff, pattn, Mr, 2);
    // 3. sampler
    sample_kernel<<<Mr, 256>>>(pval, poff, pattn, refp, mid_hi, mid_lo);
    // 4. output projection (bf16x3 compensated)
    gemm_bf16x3_kernel<<<dim3(2, mtiles), 256, GEMM_SMEM>>>(
        mid_hi, mid_lo, wu_hi, wu_lo, b_out, out, Mr);
}

// round 7
// speedup vs baseline: 1.8529x; 1.3876x over previous
#include <cuda_runtime.h>
#include <cuda_fp16.h>
#include <mma.h>
#include <cstdint>
#include <math.h>

using namespace nvcuda;

#define LEN    19947
#define NHEAD  8
#define DH     32
#define NLVL   4
#define NPTS   4

// ---------------------------------------------------------------------------
// Scratch (device globals)
// ---------------------------------------------------------------------------
__device__ __half g_value_h[LEN * 256];
__device__ float  g_off [LEN * 256];
__device__ float  g_attn[LEN * 128];
__device__ __half g_mid_h[LEN * 256];
__device__ __half g_q_h[LEN * 256];
__device__ __half g_f_h[LEN * 256];
// fp16 weights: [0,256)=W_val^T, [256,640)=[W_off|W_attn]^T, [640,896)=W_out^T
__device__ __half g_w_h[896 * 256];

__device__ __forceinline__ uint32_t smem_u32(const void* p) {
    uint32_t a;
    asm("{ .reg .u64 t; cvta.to.shared.u64 t, %1; cvt.u32.u64 %0, t; }" : "=r"(a) : "l"(p));
    return a;
}

// ---------------------------------------------------------------------------
// Prep kernels
// ---------------------------------------------------------------------------
__global__ void prep_weights_kernel(const float* __restrict__ W_val,
                                    const float* __restrict__ W_off,
                                    const float* __restrict__ W_attn,
                                    const float* __restrict__ W_out,
                                    __half* __restrict__ wh)
{
    int id = blockIdx.x * blockDim.x + threadIdx.x;
    if (id >= 896 * 256) return;
    int n = id >> 8;
    int k = id & 255;
    float x;
    if (n < 256)      x = W_val [k * 256 + n];
    else if (n < 512) x = W_off [k * 256 + (n - 256)];
    else if (n < 640) x = W_attn[k * 128 + (n - 512)];
    else              x = W_out [k * 256 + (n - 640)];
    wh[id] = __float2half_rn(x);
}

__global__ void prep_split_kernel(const float* __restrict__ query,
                                  const float* __restrict__ inflat,
                                  __half* __restrict__ qh,
                                  __half* __restrict__ fh)
{
    const int total4 = LEN * 256 / 4;
    int id = blockIdx.x * blockDim.x + threadIdx.x;
    if (id >= 2 * total4) return;
    const float* src;
    __half* dst;
    int i4 = id;
    if (id < total4) { src = query;  dst = qh; }
    else             { src = inflat; dst = fh; i4 -= total4; }
    float4 v = *reinterpret_cast<const float4*>(src + (size_t)i4 * 4);
    __half h[4] = {__float2half_rn(v.x), __float2half_rn(v.y),
                   __float2half_rn(v.z), __float2half_rn(v.w)};
    *reinterpret_cast<uint2*>(dst + (size_t)i4 * 4) = *reinterpret_cast<uint2*>(h);
}

// ---------------------------------------------------------------------------
// cp.async macros
// ---------------------------------------------------------------------------
#define CP16(dst, src, sz) \
    asm volatile("cp.async.cg.shared.global [%0], [%1], 16, %2;" \
                 :: "r"(dst), "l"(src), "r"(sz))
#define CP_COMMIT() asm volatile("cp.async.commit_group;")
#define CP_WAIT1()  asm volatile("cp.async.wait_group 1;")
#define CP_WAIT0()  asm volatile("cp.async.wait_group 0;")

#define ASTR 40
#define BUFB 10240
#define CSTRIDE 132

// ---------------------------------------------------------------------------
// fp16 single-pass GEMM: C = A @ B^T + bias.
// 256 threads, 8 warps (warp tile 32x64), BK=32, 2-stage cp.async pipeline.
// mode 0: float out C1 (+bias1)                       [output projection]
// mode 1: half  out C1 (+bias1, mask zeroing)         [value projection]
// mode 2: dual: col<256 -> float C1 (+bias1); col>=256 -> softmax16 C2 (+bias2)
// ---------------------------------------------------------------------------
#define H_STAGEB (2 * BUFB)
#define H_SMEM   (128 * CSTRIDE * 4)

__global__ __launch_bounds__(256, 2)
void gemm_fp16_kernel(const __half* __restrict__ A,
                      const __half* __restrict__ B,
                      const float* __restrict__ bias1,
                      const float* __restrict__ bias2,
                      const unsigned char* __restrict__ mask,
                      void* __restrict__ C1v, void* __restrict__ C2v,
                      int Mrows, int mode)
{
    extern __shared__ char smem[];
    const int tid  = threadIdx.x;
    const int warp = tid >> 5;
    const int wm   = warp & 3;
    const int wn   = warp >> 2;
    const int block_m = blockIdx.y * 128;
    const int block_n = blockIdx.x * 128;
    const uint32_t sb = smem_u32(smem);

    wmma::fragment<wmma::accumulator, 16, 16, 16, float> acc[2][4];
#pragma unroll
    for (int i = 0; i < 2; i++)
#pragma unroll
        for (int j = 0; j < 4; j++) wmma::fill_fragment(acc[i][j], 0.f);

    auto issue = [&](int chunk) {
        const int s = chunk & 1;
        const int k0 = chunk * 32;
        const uint32_t sbase = sb + s * H_STAGEB;
#pragma unroll
        for (int h = 0; h < 2; h++) {
            const int c   = tid + h * 256;
            const int row = c >> 2;
            const int prt = (c & 3) * 8;
            const uint32_t so = (uint32_t)(row * ASTR + prt) * 2;
            const int ga  = block_m + row;
            const int asz = (ga < Mrows) ? 16 : 0;
            CP16(sbase + 0 * BUFB + so, A + (size_t)ga * 256 + k0 + prt, asz);
            CP16(sbase + 1 * BUFB + so, B + (size_t)(block_n + row) * 256 + k0 + prt, 16);
        }
    };

    issue(0);
    CP_COMMIT();

    for (int chunk = 0; chunk < 8; chunk++) {
        if (chunk < 7) { issue(chunk + 1); CP_COMMIT(); CP_WAIT1(); }
        else           { CP_WAIT0(); }
        __syncthreads();

        const int s = chunk & 1;
        const __half* ab = reinterpret_cast<const __half*>(smem + s * H_STAGEB);
        const __half* bb = ab + 128 * ASTR;

#pragma unroll
        for (int ks = 0; ks < 32; ks += 16) {
            wmma::fragment<wmma::matrix_a, 16, 16, 16, __half, wmma::row_major> fa[2];
            wmma::fragment<wmma::matrix_b, 16, 16, 16, __half, wmma::col_major> fb[4];
#pragma unroll
            for (int i = 0; i < 2; i++)
                wmma::load_matrix_sync(fa[i], ab + (wm * 32 + i * 16) * ASTR + ks, ASTR);
#pragma unroll
            for (int j = 0; j < 4; j++)
                wmma::load_matrix_sync(fb[j], bb + (wn * 64 + j * 16) * ASTR + ks, ASTR);
#pragma unroll
            for (int i = 0; i < 2; i++)
#pragma unroll
                for (int j = 0; j < 4; j++) wmma::mma_sync(acc[i][j], fa[i], fb[j], acc[i][j]);
        }
        __syncthreads();
    }

    float* stage = reinterpret_cast<float*>(smem);
#pragma unroll
    for (int i = 0; i < 2; i++)
#pragma unroll
        for (int j = 0; j < 4; j++)
            wmma::store_matrix_sync(stage + (wm * 32 + i * 16) * CSTRIDE + wn * 64 + j * 16,
                                    acc[i][j], CSTRIDE, wmma::mem_row_major);
    __syncthreads();

    {
        const int r  = tid >> 1;
        const int gr = block_m + r;
        if (gr < Mrows) {
            const int colb = (tid & 1) * 64;
#pragma unroll
            for (int g = 0; g < 64; g += 16) {
                const int gcol = block_n + colb + g;
                float v[16];
                if (mode == 2 && gcol >= 256) {
#pragma unroll
                    for (int c = 0; c < 16; c++)
                        v[c] = stage[r * CSTRIDE + colb + g + c] + __ldg(bias2 + gcol - 256 + c);
                    float mx = -1e30f;
#pragma unroll
                    for (int c = 0; c < 16; c++) mx = fmaxf(mx, v[c]);
                    float sum = 0.f;
#pragma unroll
                    for (int c = 0; c < 16; c++) { v[c] = __expf(v[c] - mx); sum += v[c]; }
                    float inv = 1.f / sum;
                    float* C2 = reinterpret_cast<float*>(C2v);
#pragma unroll
                    for (int c = 0; c < 16; c += 4) {
                        float4 o = make_float4(v[c]*inv, v[c+1]*inv, v[c+2]*inv, v[c+3]*inv);
                        *reinterpret_cast<float4*>(C2 + (size_t)gr * 128 + gcol - 256 + c) = o;
                    }
                } else {
#pragma unroll
                    for (int c = 0; c < 16; c++)
                        v[c] = stage[r * CSTRIDE + colb + g + c] + __ldg(bias1 + gcol + c);
                    if (mode == 1) {
                        float scale = (mask != nullptr && mask[gr]) ? 0.f : 1.f;
                        __half* C1 = reinterpret_cast<__half*>(C1v);
                        __half hbuf[16];
#pragma unroll
                        for (int c = 0; c < 16; c++) hbuf[c] = __float2half_rn(v[c] * scale);
#pragma unroll
                        for (int c = 0; c < 16; c += 8)
                            *reinterpret_cast<uint4*>(C1 + (size_t)gr * 256 + gcol + c) =
                                *reinterpret_cast<uint4*>(hbuf + c);
                    } else {
                        float* C1 = reinterpret_cast<float*>(C1v);
#pragma unroll
                        for (int c = 0; c < 16; c += 4) {
                            float4 o = make_float4(v[c], v[c+1], v[c+2], v[c+3]);
                            *reinterpret_cast<float4*>(C1 + (size_t)gr * 256 + gcol + c) = o;
                        }
                    }
                }
            }
        }
    }
}

// ---------------------------------------------------------------------------
// Sampler v3: warp = (q, head). lane = (sub, c2): sub = point-pair selector,
// c2 = half2 channel pair. 2 points x 16 half2-lanes concurrent per warp,
// 8 unrolled iterations, branch-free clamped gathers (validity in weights).
// ---------------------------------------------------------------------------
__global__ __launch_bounds__(256)
void sample_kernel(const __half* __restrict__ value,
                   const float* __restrict__ off,
                   const float* __restrict__ aw,
                   const float* __restrict__ refp,
                   __half* __restrict__ mid)
{
    const int q    = blockIdx.x;
    const int m    = threadIdx.x >> 5;
    const int lane = threadIdx.x & 31;
    const int sub  = lane >> 4;      // 0/1: which point of the pair
    const int c2   = lane & 15;      // half2 channel pair (channels 2c2, 2c2+1)

    // coalesced parameter loads, one per warp each
    const float offv = __ldg(off  + (size_t)q * 256 + m * 32 + lane);
    const float awv  = __ldg(aw   + (size_t)q * 128 + m * 16 + (lane & 15));
    const float rfv  = __ldg(refp + (size_t)q * 8 + (lane & 7));

    const __half* vbase = value + m * DH + 2 * c2;
    float accx = 0.f, accy = 0.f;

    const int HH[NLVL] = {100, 50, 25, 13};
    const int WW[NLVL] = {150, 75, 38, 19};
    const int ST[NLVL] = {0, 15000, 18750, 19700};

#pragma unroll
    for (int it = 0; it < 8; it++) {
        const int l  = it >> 1;
        const int pt = it * 2 + sub;
        const float rx = __shfl_sync(0xffffffffu, rfv, l * 2 + 0);
        const float ry = __shfl_sync(0xffffffffu, rfv, l * 2 + 1);
        const float ox = __shfl_sync(0xffffffffu, offv, pt * 2 + 0);
        const float oy = __shfl_sync(0xffffffffu, offv, pt * 2 + 1);
        const float a  = __shfl_sync(0xffffffffu, awv,  pt);

        const int W = WW[l], H = HH[l], start = ST[l];
        const float Wf = (float)W, Hf = (float)H;

        float gx = 2.f * (rx + ox / Wf) - 1.f;
        float gy = 2.f * (ry + oy / Hf) - 1.f;
        gx = fminf(fmaxf(gx, -2.f), 2.f);
        gy = fminf(fmaxf(gy, -2.f), 2.f);

        const float x = (gx + 1.f) * (Wf * 0.5f) - 0.5f;
        const float y = (gy + 1.f) * (Hf * 0.5f) - 0.5f;

        const float x0f = floorf(x), y0f = floorf(y);
        const float wx1 = x - x0f, wx0 = 1.f - wx1;
        const float wy1 = y - y0f, wy0 = 1.f - wy1;
        const int x0 = (int)x0f, y0 = (int)y0f;
        const int x1 = x0 + 1,  y1 = y0 + 1;

        const float fx0 = (x0 >= 0 && x0 < W) ? wx0 : 0.f;
        const float fx1 = (x1 >= 0 && x1 < W) ? wx1 : 0.f;
        const float fy0 = (y0 >= 0 && y0 < H) ? wy0 : 0.f;
        const float fy1 = (y1 >= 0 && y1 < H) ? wy1 : 0.f;

        const int cx0 = min(max(x0, 0), W - 1);
        const int cx1 = min(max(x1, 0), W - 1);
        const int cy0 = min(max(y0, 0), H - 1);
        const int cy1 = min(max(y1, 0), H - 1);

        const __half2 h00 = __ldg(reinterpret_cast<const __half2*>(vbase + (size_t)(start + cy0 * W + cx0) * 256));
        const __half2 h01 = __ldg(reinterpret_cast<const __half2*>(vbase + (size_t)(start + cy0 * W + cx1) * 256));
        const __half2 h10 = __ldg(reinterpret_cast<const __half2*>(vbase + (size_t)(start + cy1 * W + cx0) * 256));
        const __half2 h11 = __ldg(reinterpret_cast<const __half2*>(vbase + (size_t)(start + cy1 * W + cx1) * 256));

        const float2 f00 = __half22float2(h00);
        const float2 f01 = __half22float2(h01);
        const float2 f10 = __half22float2(h10);
        const float2 f11 = __half22float2(h11);

        const float w00 = fx0 * fy0, w01 = fx1 * fy0;
        const float w10 = fx0 * fy1, w11 = fx1 * fy1;

        float sx = w00 * f00.x;
        sx = fmaf(w01, f01.x, sx);
        sx = fmaf(w10, f10.x, sx);
        sx = fmaf(w11, f11.x, sx);
        float sy = w00 * f00.y;
        sy = fmaf(w01, f01.y, sy);
        sy = fmaf(w10, f10.y, sy);
        sy = fmaf(w11, f11.y, sy);

        accx = fmaf(a, sx, accx);
        accy = fmaf(a, sy, accy);
    }

    // combine the two point-subsets
    accx += __shfl_xor_sync(0xffffffffu, accx, 16);
    accy += __shfl_xor_sync(0xffffffffu, accy, 16);

    if (sub == 0) {
        __half2 h = __floats2half2_rn(accx, accy);
        *reinterpret_cast<__half2*>(mid + (size_t)q * 256 + m * DH + 2 * c2) = h;
    }
}

// ---------------------------------------------------------------------------
// Launch
// ---------------------------------------------------------------------------
extern "C" void kernel_launch(void* const* d_in, const int* in_sizes, int n_in,
                              void* d_out, int out_size)
{
    const float* query  = (const float*)d_in[0];
    const float* refp   = (const float*)d_in[1];
    const float* inflat = (const float*)d_in[2];
    const unsigned char* pmask = (const unsigned char*)d_in[3];
    const float* W_off  = (const float*)d_in[4];
    const float* b_off  = (const float*)d_in[5];
    const float* W_attn = (const float*)d_in[6];
    const float* b_attn = (const float*)d_in[7];
    const float* W_val  = (const float*)d_in[8];
    const float* b_val  = (const float*)d_in[9];
    const float* W_out  = (const float*)d_in[10];
    const float* b_out  = (const float*)d_in[11];
    float* out = (float*)d_out;

    __half* pval;  cudaGetSymbolAddress((void**)&pval,  g_value_h);
    float*  poff;  cudaGetSymbolAddress((void**)&poff,  g_off);
    float*  pattn; cudaGetSymbolAddress((void**)&pattn, g_attn);
    __half *q_h, *f_h, *w_h, *mid_h;
    cudaGetSymbolAddress((void**)&q_h,   g_q_h);
    cudaGetSymbolAddress((void**)&f_h,   g_f_h);
    cudaGetSymbolAddress((void**)&w_h,   g_w_h);
    cudaGetSymbolAddress((void**)&mid_h, g_mid_h);

    cudaFuncSetAttribute(gemm_fp16_kernel,
                         cudaFuncAttributeMaxDynamicSharedMemorySize, H_SMEM);

    const int Mr = LEN;
    const int mtiles = (Mr + 127) / 128;

    prep_weights_kernel<<<(896 * 256 + 255) / 256, 256>>>(W_val, W_off, W_attn, W_out, w_h);
    prep_split_kernel<<<(2 * LEN * 64 + 255) / 256, 256>>>(query, inflat, q_h, f_h);

    const __half* wv  = w_h;                // rows [0,256)
    const __half* woa = w_h + 256 * 256;    // rows [256,640)
    const __half* wu  = w_h + 640 * 256;    // rows [640,896)

    // 1. value projection -> fp16 (mode 1, mask)
    gemm_fp16_kernel<<<dim3(2, mtiles), 256, H_SMEM>>>(
        f_h, wv, b_val, nullptr, pmask, pval, nullptr, Mr, 1);
    // 2. offsets + attn logits + fused softmax (mode 2, N=384)
    gemm_fp16_kernel<<<dim3(3, mtiles), 256, H_SMEM>>>(
        q_h, woa, b_off, b_attn, nullptr, poff, pattn, Mr, 2);
    // 3. sampler (fp16 in, fp16 mid out)
    sample_kernel<<<Mr, 256>>>(pval, poff, pattn, refp, mid_h);
    // 4. output projection (mode 0, fp16 single pass, float out)
    gemm_fp16_kernel<<<dim3(2, mtiles), 256, H_SMEM>>>(
        mid_h, wu, b_out, nullptr, nullptr, out, nullptr, Mr, 0);
}

// round 8
// speedup vs baseline: 2.5773x; 1.3909x over previous
#include <cuda_runtime.h>
#include <cuda_fp16.h>
#include <mma.h>
#include <cstdint>
#include <math.h>

using namespace nvcuda;

#define LEN    19947
#define NHEAD  8
#define DH     32
#define NLVL   4
#define NPTS   4

// ---------------------------------------------------------------------------
// Scratch (device globals)
// ---------------------------------------------------------------------------
__device__ __half g_value_h[LEN * 256];
__device__ float  g_off [LEN * 256];
__device__ float  g_attn[LEN * 128];
__device__ __half g_mid_h[LEN * 256];
__device__ __half g_q_h[LEN * 256];
__device__ __half g_f_h[LEN * 256];
// fp16 weights: [0,256)=W_val^T, [256,640)=[W_off|W_attn]^T, [640,896)=W_out^T
__device__ __half g_w_h[896 * 256];

__device__ __forceinline__ uint32_t smem_u32(const void* p) {
    uint32_t a;
    asm("{ .reg .u64 t; cvta.to.shared.u64 t, %1; cvt.u32.u64 %0, t; }" : "=r"(a) : "l"(p));
    return a;
}

// ---------------------------------------------------------------------------
// Prep kernels
// ---------------------------------------------------------------------------
__global__ void prep_weights_kernel(const float* __restrict__ W_val,
                                    const float* __restrict__ W_off,
                                    const float* __restrict__ W_attn,
                                    const float* __restrict__ W_out,
                                    __half* __restrict__ wh)
{
    int id = blockIdx.x * blockDim.x + threadIdx.x;
    if (id >= 896 * 256) return;
    int n = id >> 8;
    int k = id & 255;
    float x;
    if (n < 256)      x = W_val [k * 256 + n];
    else if (n < 512) x = W_off [k * 256 + (n - 256)];
    else if (n < 640) x = W_attn[k * 128 + (n - 512)];
    else              x = W_out [k * 256 + (n - 640)];
    wh[id] = __float2half_rn(x);
}

__global__ void prep_split_kernel(const float* __restrict__ query,
                                  const float* __restrict__ inflat,
                                  __half* __restrict__ qh,
                                  __half* __restrict__ fh)
{
    const int total4 = LEN * 256 / 4;
    int id = blockIdx.x * blockDim.x + threadIdx.x;
    if (id >= 2 * total4) return;
    const float* src;
    __half* dst;
    int i4 = id;
    if (id < total4) { src = query;  dst = qh; }
    else             { src = inflat; dst = fh; i4 -= total4; }
    float4 v = *reinterpret_cast<const float4*>(src + (size_t)i4 * 4);
    __half h[4] = {__float2half_rn(v.x), __float2half_rn(v.y),
                   __float2half_rn(v.z), __float2half_rn(v.w)};
    *reinterpret_cast<uint2*>(dst + (size_t)i4 * 4) = *reinterpret_cast<uint2*>(h);
}

// ---------------------------------------------------------------------------
// cp.async macros
// ---------------------------------------------------------------------------
#define CP16(dst, src, sz) \
    asm volatile("cp.async.cg.shared.global [%0], [%1], 16, %2;" \
                 :: "r"(dst), "l"(src), "r"(sz))
#define CP_COMMIT() asm volatile("cp.async.commit_group;")
#define CP_WAIT1()  asm volatile("cp.async.wait_group 1;")
#define CP_WAIT0()  asm volatile("cp.async.wait_group 0;")

#define ASTR 40
#define BUFB 10240
#define CSTRIDE 132
#define H_STAGEB (2 * BUFB)
#define H_SMEM   (128 * CSTRIDE * 4)

// ---------------------------------------------------------------------------
// GEMM body (shared by both kernels): loads A/B through a 2-stage pipeline,
// leaves 128x128 fp32 result staged in smem.
// ---------------------------------------------------------------------------
__device__ __forceinline__ void gemm_body(const __half* __restrict__ A,
                                          const __half* __restrict__ B,
                                          char* smem, int block_m, int block_n,
                                          int Mrows)
{
    const int tid  = threadIdx.x;
    const int warp = tid >> 5;
    const int wm   = warp & 3;
    const int wn   = warp >> 2;
    const uint32_t sb = smem_u32(smem);

    wmma::fragment<wmma::accumulator, 16, 16, 16, float> acc[2][4];
#pragma unroll
    for (int i = 0; i < 2; i++)
#pragma unroll
        for (int j = 0; j < 4; j++) wmma::fill_fragment(acc[i][j], 0.f);

    auto issue = [&](int chunk) {
        const int s = chunk & 1;
        const int k0 = chunk * 32;
        const uint32_t sbase = sb + s * H_STAGEB;
#pragma unroll
        for (int h = 0; h < 2; h++) {
            const int c   = tid + h * 256;
            const int row = c >> 2;
            const int prt = (c & 3) * 8;
            const uint32_t so = (uint32_t)(row * ASTR + prt) * 2;
            const int ga  = block_m + row;
            const int asz = (ga < Mrows) ? 16 : 0;
            CP16(sbase + 0 * BUFB + so, A + (size_t)ga * 256 + k0 + prt, asz);
            CP16(sbase + 1 * BUFB + so, B + (size_t)(block_n + row) * 256 + k0 + prt, 16);
        }
    };

    issue(0);
    CP_COMMIT();

    for (int chunk = 0; chunk < 8; chunk++) {
        if (chunk < 7) { issue(chunk + 1); CP_COMMIT(); CP_WAIT1(); }
        else           { CP_WAIT0(); }
        __syncthreads();

        const int s = chunk & 1;
        const __half* ab = reinterpret_cast<const __half*>(smem + s * H_STAGEB);
        const __half* bb = ab + 128 * ASTR;

#pragma unroll
        for (int ks = 0; ks < 32; ks += 16) {
            wmma::fragment<wmma::matrix_a, 16, 16, 16, __half, wmma::row_major> fa[2];
            wmma::fragment<wmma::matrix_b, 16, 16, 16, __half, wmma::col_major> fb[4];
#pragma unroll
            for (int i = 0; i < 2; i++)
                wmma::load_matrix_sync(fa[i], ab + (wm * 32 + i * 16) * ASTR + ks, ASTR);
#pragma unroll
            for (int j = 0; j < 4; j++)
                wmma::load_matrix_sync(fb[j], bb + (wn * 64 + j * 16) * ASTR + ks, ASTR);
#pragma unroll
            for (int i = 0; i < 2; i++)
#pragma unroll
                for (int j = 0; j < 4; j++) wmma::mma_sync(acc[i][j], fa[i], fb[j], acc[i][j]);
        }
        __syncthreads();
    }

    float* stage = reinterpret_cast<float*>(smem);
#pragma unroll
    for (int i = 0; i < 2; i++)
#pragma unroll
        for (int j = 0; j < 4; j++)
            wmma::store_matrix_sync(stage + (wm * 32 + i * 16) * CSTRIDE + wn * 64 + j * 16,
                                    acc[i][j], CSTRIDE, wmma::mem_row_major);
    __syncthreads();
}

// ---------------------------------------------------------------------------
// Fused projection kernel: blockIdx.x in [0,2) -> value proj (A=inflat_h),
// blockIdx.x in [2,5) -> offsets/attn dual proj (A=query_h).
// ---------------------------------------------------------------------------
__global__ __launch_bounds__(256, 2)
void proj_fused_kernel(const __half* __restrict__ Af,   // inflat fp16
                       const __half* __restrict__ Aq,   // query fp16
                       const __half* __restrict__ Bv,   // W_val^T
                       const __half* __restrict__ Boa,  // [W_off|W_attn]^T
                       const float* __restrict__ b_val,
                       const float* __restrict__ b_off,
                       const float* __restrict__ b_attn,
                       const unsigned char* __restrict__ mask,
                       __half* __restrict__ Cval,
                       float* __restrict__ Coff,
                       float* __restrict__ Cattn,
                       int Mrows)
{
    extern __shared__ char smem[];
    const bool is_val = (blockIdx.x < 2);
    const int  bx     = is_val ? blockIdx.x : blockIdx.x - 2;
    const int  block_m = blockIdx.y * 128;
    const int  block_n = bx * 128;

    gemm_body(is_val ? Af : Aq, is_val ? Bv : Boa, smem, block_m, block_n, Mrows);

    const float* stage = reinterpret_cast<const float*>(smem);
    const int tid = threadIdx.x;
    const int r   = tid >> 1;
    const int gr  = block_m + r;
    if (gr >= Mrows) return;
    const int colb = (tid & 1) * 64;

#pragma unroll
    for (int g = 0; g < 64; g += 16) {
        const int gcol = block_n + colb + g;
        float v[16];
        if (is_val) {
#pragma unroll
            for (int c = 0; c < 16; c++)
                v[c] = stage[r * CSTRIDE + colb + g + c] + __ldg(b_val + gcol + c);
            float scale = (mask != nullptr && mask[gr]) ? 0.f : 1.f;
            __half hbuf[16];
#pragma unroll
            for (int c = 0; c < 16; c++) hbuf[c] = __float2half_rn(v[c] * scale);
#pragma unroll
            for (int c = 0; c < 16; c += 8)
                *reinterpret_cast<uint4*>(Cval + (size_t)gr * 256 + gcol + c) =
                    *reinterpret_cast<uint4*>(hbuf + c);
        } else if (gcol < 256) {
#pragma unroll
            for (int c = 0; c < 16; c++)
                v[c] = stage[r * CSTRIDE + colb + g + c] + __ldg(b_off + gcol + c);
#pragma unroll
            for (int c = 0; c < 16; c += 4) {
                float4 o = make_float4(v[c], v[c+1], v[c+2], v[c+3]);
                *reinterpret_cast<float4*>(Coff + (size_t)gr * 256 + gcol + c) = o;
            }
        } else {
#pragma unroll
            for (int c = 0; c < 16; c++)
                v[c] = stage[r * CSTRIDE + colb + g + c] + __ldg(b_attn + gcol - 256 + c);
            float mx = -1e30f;
#pragma unroll
            for (int c = 0; c < 16; c++) mx = fmaxf(mx, v[c]);
            float sum = 0.f;
#pragma unroll
            for (int c = 0; c < 16; c++) { v[c] = __expf(v[c] - mx); sum += v[c]; }
            float inv = 1.f / sum;
#pragma unroll
            for (int c = 0; c < 16; c += 4) {
                float4 o = make_float4(v[c]*inv, v[c+1]*inv, v[c+2]*inv, v[c+3]*inv);
                *reinterpret_cast<float4*>(Cattn + (size_t)gr * 128 + gcol - 256 + c) = o;
            }
        }
    }
}

// ---------------------------------------------------------------------------
// Output projection kernel: fp16 GEMM, float out + bias.
// ---------------------------------------------------------------------------
__global__ __launch_bounds__(256, 2)
void proj_out_kernel(const __half* __restrict__ A,
                     const __half* __restrict__ B,
                     const float* __restrict__ bias,
                     float* __restrict__ C,
                     int Mrows)
{
    extern __shared__ char smem[];
    const int block_m = blockIdx.y * 128;
    const int block_n = blockIdx.x * 128;

    gemm_body(A, B, smem, block_m, block_n, Mrows);

    const float* stage = reinterpret_cast<const float*>(smem);
    const int tid = threadIdx.x;
    const int r   = tid >> 1;
    const int gr  = block_m + r;
    if (gr >= Mrows) return;
    const int colb = (tid & 1) * 64;
#pragma unroll
    for (int g = 0; g < 64; g += 16) {
        const int gcol = block_n + colb + g;
        float v[16];
#pragma unroll
        for (int c = 0; c < 16; c++)
            v[c] = stage[r * CSTRIDE + colb + g + c] + __ldg(bias + gcol + c);
#pragma unroll
        for (int c = 0; c < 16; c += 4) {
            float4 o = make_float4(v[c], v[c+1], v[c+2], v[c+3]);
            *reinterpret_cast<float4*>(C + (size_t)gr * 256 + gcol + c) = o;
        }
    }
}

// ---------------------------------------------------------------------------
// Sampler v4: warp = (q, head). lane = (p2, c4): p2 = point-in-level (0..3),
// c4 = channel quad (4 channels, 8-byte uint2 gathers). 4 level-iterations,
// 16 independent LDG.64 per thread, branch-free.
// ---------------------------------------------------------------------------
__global__ __launch_bounds__(256)
void sample_kernel(const __half* __restrict__ value,
                   const float* __restrict__ off,
                   const float* __restrict__ aw,
                   const float* __restrict__ refp,
                   __half* __restrict__ mid)
{
    const int q    = blockIdx.x;
    const int m    = threadIdx.x >> 5;
    const int lane = threadIdx.x & 31;
    const int p2   = lane >> 3;     // point within level
    const int c4   = lane & 7;      // channel quad

    const float offv = __ldg(off  + (size_t)q * 256 + m * 32 + lane);
    const float awv  = __ldg(aw   + (size_t)q * 128 + m * 16 + (lane & 15));
    const float rfv  = __ldg(refp + (size_t)q * 8 + (lane & 7));

    const __half* vbase = value + m * DH + c4 * 4;
    float acc0 = 0.f, acc1 = 0.f, acc2 = 0.f, acc3 = 0.f;

    const int HH[NLVL] = {100, 50, 25, 13};
    const int WW[NLVL] = {150, 75, 38, 19};
    const int ST[NLVL] = {0, 15000, 18750, 19700};

#pragma unroll
    for (int l = 0; l < NLVL; l++) {
        const int pt = l * 4 + p2;
        const float rx = __shfl_sync(0xffffffffu, rfv, l * 2 + 0);
        const float ry = __shfl_sync(0xffffffffu, rfv, l * 2 + 1);
        const float ox = __shfl_sync(0xffffffffu, offv, pt * 2 + 0);
        const float oy = __shfl_sync(0xffffffffu, offv, pt * 2 + 1);
        const float a  = __shfl_sync(0xffffffffu, awv,  pt);

        const int W = WW[l], H = HH[l], start = ST[l];
        const float Wf = (float)W, Hf = (float)H;

        float gx = 2.f * (rx + ox / Wf) - 1.f;
        float gy = 2.f * (ry + oy / Hf) - 1.f;
        gx = fminf(fmaxf(gx, -2.f), 2.f);
        gy = fminf(fmaxf(gy, -2.f), 2.f);

        const float x = (gx + 1.f) * (Wf * 0.5f) - 0.5f;
        const float y = (gy + 1.f) * (Hf * 0.5f) - 0.5f;

        const float x0f = floorf(x), y0f = floorf(y);
        const float wx1 = x - x0f, wx0 = 1.f - wx1;
        const float wy1 = y - y0f, wy0 = 1.f - wy1;
        const int x0 = (int)x0f, y0 = (int)y0f;
        const int x1 = x0 + 1,  y1 = y0 + 1;

        const float fx0 = (x0 >= 0 && x0 < W) ? wx0 : 0.f;
        const float fx1 = (x1 >= 0 && x1 < W) ? wx1 : 0.f;
        const float fy0 = (y0 >= 0 && y0 < H) ? wy0 : 0.f;
        const float fy1 = (y1 >= 0 && y1 < H) ? wy1 : 0.f;

        const int cx0 = min(max(x0, 0), W - 1);
        const int cx1 = min(max(x1, 0), W - 1);
        const int cy0 = min(max(y0, 0), H - 1);
        const int cy1 = min(max(y1, 0), H - 1);

        const uint2 u00 = __ldg(reinterpret_cast<const uint2*>(vbase + (size_t)(start + cy0 * W + cx0) * 256));
        const uint2 u01 = __ldg(reinterpret_cast<const uint2*>(vbase + (size_t)(start + cy0 * W + cx1) * 256));
        const uint2 u10 = __ldg(reinterpret_cast<const uint2*>(vbase + (size_t)(start + cy1 * W + cx0) * 256));
        const uint2 u11 = __ldg(reinterpret_cast<const uint2*>(vbase + (size_t)(start + cy1 * W + cx1) * 256));

        const float w00 = fx0 * fy0, w01 = fx1 * fy0;
        const float w10 = fx0 * fy1, w11 = fx1 * fy1;

        const float2 a00 = __half22float2(*reinterpret_cast<const __half2*>(&u00.x));
        const float2 b00 = __half22float2(*reinterpret_cast<const __half2*>(&u00.y));
        const float2 a01 = __half22float2(*reinterpret_cast<const __half2*>(&u01.x));
        const float2 b01 = __half22float2(*reinterpret_cast<const __half2*>(&u01.y));
        const float2 a10 = __half22float2(*reinterpret_cast<const __half2*>(&u10.x));
        const float2 b10 = __half22float2(*reinterpret_cast<const __half2*>(&u10.y));
        const float2 a11 = __half22float2(*reinterpret_cast<const __half2*>(&u11.x));
        const float2 b11 = __half22float2(*reinterpret_cast<const __half2*>(&u11.y));

        float s0 = w00 * a00.x; s0 = fmaf(w01, a01.x, s0); s0 = fmaf(w10, a10.x, s0); s0 = fmaf(w11, a11.x, s0);
        float s1 = w00 * a00.y; s1 = fmaf(w01, a01.y, s1); s1 = fmaf(w10, a10.y, s1); s1 = fmaf(w11, a11.y, s1);
        float s2 = w00 * b00.x; s2 = fmaf(w01, b01.x, s2); s2 = fmaf(w10, b10.x, s2); s2 = fmaf(w11, b11.x, s2);
        float s3 = w00 * b00.y; s3 = fmaf(w01, b01.y, s3); s3 = fmaf(w10, b10.y, s3); s3 = fmaf(w11, b11.y, s3);

        acc0 = fmaf(a, s0, acc0);
        acc1 = fmaf(a, s1, acc1);
        acc2 = fmaf(a, s2, acc2);
        acc3 = fmaf(a, s3, acc3);
    }

    // reduce across the 4 point-subsets
    acc0 += __shfl_xor_sync(0xffffffffu, acc0, 8);
    acc1 += __shfl_xor_sync(0xffffffffu, acc1, 8);
    acc2 += __shfl_xor_sync(0xffffffffu, acc2, 8);
    acc3 += __shfl_xor_sync(0xffffffffu, acc3, 8);
    acc0 += __shfl_xor_sync(0xffffffffu, acc0, 16);
    acc1 += __shfl_xor_sync(0xffffffffu, acc1, 16);
    acc2 += __shfl_xor_sync(0xffffffffu, acc2, 16);
    acc3 += __shfl_xor_sync(0xffffffffu, acc3, 16);

    if (lane < 8) {
        __half2 h0 = __floats2half2_rn(acc0, acc1);
        __half2 h1 = __floats2half2_rn(acc2, acc3);
        uint2 u;
        u.x = *reinterpret_cast<uint32_t*>(&h0);
        u.y = *reinterpret_cast<uint32_t*>(&h1);
        *reinterpret_cast<uint2*>(mid + (size_t)q * 256 + m * DH + c4 * 4) = u;
    }
}

// ---------------------------------------------------------------------------
// Launch
// ---------------------------------------------------------------------------
extern "C" void kernel_launch(void* const* d_in, const int* in_sizes, int n_in,
                              void* d_out, int out_size)
{
    const float* query  = (const float*)d_in[0];
    const float* refp   = (const float*)d_in[1];
    const float* inflat = (const float*)d_in[2];
    const unsigned char* pmask = (const unsigned char*)d_in[3];
    const float* W_off  = (const float*)d_in[4];
    const float* b_off  = (const float*)d_in[5];
    const float* W_attn = (const float*)d_in[6];
    const float* b_attn = (const float*)d_in[7];
    const float* W_val  = (const float*)d_in[8];
    const float* b_val  = (const float*)d_in[9];
    const float* W_out  = (const float*)d_in[10];
    const float* b_out  = (const float*)d_in[11];
    float* out = (float*)d_out;

    __half* pval;  cudaGetSymbolAddress((void**)&pval,  g_value_h);
    float*  poff;  cudaGetSymbolAddress((void**)&poff,  g_off);
    float*  pattn; cudaGetSymbolAddress((void**)&pattn, g_attn);
    __half *q_h, *f_h, *w_h, *mid_h;
    cudaGetSymbolAddress((void**)&q_h,   g_q_h);
    cudaGetSymbolAddress((void**)&f_h,   g_f_h);
    cudaGetSymbolAddress((void**)&w_h,   g_w_h);
    cudaGetSymbolAddress((void**)&mid_h, g_mid_h);

    cudaFuncSetAttribute(proj_fused_kernel,
                         cudaFuncAttributeMaxDynamicSharedMemorySize, H_SMEM);
    cudaFuncSetAttribute(proj_out_kernel,
                         cudaFuncAttributeMaxDynamicSharedMemorySize, H_SMEM);

    const int Mr = LEN;
    const int mtiles = (Mr + 127) / 128;

    prep_weights_kernel<<<(896 * 256 + 255) / 256, 256>>>(W_val, W_off, W_attn, W_out, w_h);
    prep_split_kernel<<<(2 * LEN * 64 + 255) / 256, 256>>>(query, inflat, q_h, f_h);

    const __half* wv  = w_h;
    const __half* woa = w_h + 256 * 256;
    const __half* wu  = w_h + 640 * 256;

    // 1. fused: value projection + offsets/attn projections (+softmax)
    proj_fused_kernel<<<dim3(5, mtiles), 256, H_SMEM>>>(
        f_h, q_h, wv, woa, b_val, b_off, b_attn, pmask, pval, poff, pattn, Mr);
    // 2. sampler
    sample_kernel<<<Mr, 256>>>(pval, poff, pattn, refp, mid_h);
    // 3. output projection
    proj_out_kernel<<<dim3(2, mtiles), 256, H_SMEM>>>(mid_h, wu, b_out, out, Mr);
}

// round 9
// speedup vs baseline: 3.0400x; 1.1796x over previous
#include <cuda_runtime.h>
#include <cuda_fp16.h>
#include <mma.h>
#include <cstdint>
#include <math.h>

using namespace nvcuda;

#define LEN    19947
#define NHEAD  8
#define DH     32
#define NLVL   4
#define NPTS   4

// Padded value tensor geometry (pad: +1 top/left, +2 bottom/right)
// L0: 153x103 @0, L1: 78x53 @15759, L2: 41x28 @19893, L3: 22x16 @21041
#define PAD_ROWS 21393

// ---------------------------------------------------------------------------
// Scratch (device globals)
// ---------------------------------------------------------------------------
__device__ __half g_value_pad[PAD_ROWS * 256];
__device__ float  g_off [LEN * 256];
__device__ float  g_attn[LEN * 128];
__device__ __half g_mid_h[LEN * 256];
__device__ __half g_q_h[LEN * 256];
__device__ __half g_f_h[LEN * 256];
// fp16 weights: [0,256)=W_val^T, [256,640)=[W_off|W_attn]^T, [640,896)=W_out^T
__device__ __half g_w_h[896 * 256];

__device__ __forceinline__ uint32_t smem_u32(const void* p) {
    uint32_t a;
    asm("{ .reg .u64 t; cvta.to.shared.u64 t, %1; cvt.u32.u64 %0, t; }" : "=r"(a) : "l"(p));
    return a;
}

// logical value row (0..LEN) -> padded row index
__device__ __forceinline__ int pad_row(int gr) {
    int l, r, W, Wp, st;
    if (gr < 15000)      { r = gr;          W = 150; Wp = 153; st = 0; }
    else if (gr < 18750) { r = gr - 15000;  W = 75;  Wp = 78;  st = 15759; }
    else if (gr < 19700) { r = gr - 18750;  W = 38;  Wp = 41;  st = 19893; }
    else                 { r = gr - 19700;  W = 19;  Wp = 22;  st = 21041; }
    int y = r / W, x = r - y * W;
    return st + (y + 1) * Wp + (x + 1);
}

// ---------------------------------------------------------------------------
// Prep kernels
// ---------------------------------------------------------------------------
__global__ void zero_pad_kernel(__half* __restrict__ vp) {
    int id = blockIdx.x * blockDim.x + threadIdx.x;      // uint4 = 8 halves
    if (id < PAD_ROWS * 32)
        *reinterpret_cast<uint4*>(vp + (size_t)id * 8) = make_uint4(0, 0, 0, 0);
}

__global__ void prep_weights_kernel(const float* __restrict__ W_val,
                                    const float* __restrict__ W_off,
                                    const float* __restrict__ W_attn,
                                    const float* __restrict__ W_out,
                                    __half* __restrict__ wh)
{
    int id = blockIdx.x * blockDim.x + threadIdx.x;
    if (id >= 896 * 256) return;
    int n = id >> 8;
    int k = id & 255;
    float x;
    if (n < 256)      x = W_val [k * 256 + n];
    else if (n < 512) x = W_off [k * 256 + (n - 256)];
    else if (n < 640) x = W_attn[k * 128 + (n - 512)];
    else              x = W_out [k * 256 + (n - 640)];
    wh[id] = __float2half_rn(x);
}

__global__ void prep_split_kernel(const float* __restrict__ query,
                                  const float* __restrict__ inflat,
                                  __half* __restrict__ qh,
                                  __half* __restrict__ fh)
{
    const int total4 = LEN * 256 / 4;
    int id = blockIdx.x * blockDim.x + threadIdx.x;
    if (id >= 2 * total4) return;
    const float* src;
    __half* dst;
    int i4 = id;
    if (id < total4) { src = query;  dst = qh; }
    else             { src = inflat; dst = fh; i4 -= total4; }
    float4 v = *reinterpret_cast<const float4*>(src + (size_t)i4 * 4);
    __half h[4] = {__float2half_rn(v.x), __float2half_rn(v.y),
                   __float2half_rn(v.z), __float2half_rn(v.w)};
    *reinterpret_cast<uint2*>(dst + (size_t)i4 * 4) = *reinterpret_cast<uint2*>(h);
}

// ---------------------------------------------------------------------------
// cp.async macros
// ---------------------------------------------------------------------------
#define CP16(dst, src, sz) \
    asm volatile("cp.async.cg.shared.global [%0], [%1], 16, %2;" \
                 :: "r"(dst), "l"(src), "r"(sz))
#define CP_COMMIT() asm volatile("cp.async.commit_group;")
#define CP_WAIT1()  asm volatile("cp.async.wait_group 1;")
#define CP_WAIT0()  asm volatile("cp.async.wait_group 0;")

#define ASTR 40
#define BUFB 10240
#define CSTRIDE 132
#define H_STAGEB (2 * BUFB)
#define H_SMEM   (128 * CSTRIDE * 4)
#define PGRID 296          // persistent grid: 2 CTAs x 148 SMs

// ---------------------------------------------------------------------------
// GEMM body: 2-stage cp.async pipeline, result staged fp32 in smem.
// ---------------------------------------------------------------------------
__device__ __forceinline__ void gemm_body(const __half* __restrict__ A,
                                          const __half* __restrict__ B,
                                          char* smem, int block_m, int block_n,
                                          int Mrows)
{
    const int tid  = threadIdx.x;
    const int warp = tid >> 5;
    const int wm   = warp & 3;
    const int wn   = warp >> 2;
    const uint32_t sb = smem_u32(smem);

    wmma::fragment<wmma::accumulator, 16, 16, 16, float> acc[2][4];
#pragma unroll
    for (int i = 0; i < 2; i++)
#pragma unroll
        for (int j = 0; j < 4; j++) wmma::fill_fragment(acc[i][j], 0.f);

    auto issue = [&](int chunk) {
        const int s = chunk & 1;
        const int k0 = chunk * 32;
        const uint32_t sbase = sb + s * H_STAGEB;
#pragma unroll
        for (int h = 0; h < 2; h++) {
            const int c   = tid + h * 256;
            const int row = c >> 2;
            const int prt = (c & 3) * 8;
            const uint32_t so = (uint32_t)(row * ASTR + prt) * 2;
            const int ga  = block_m + row;
            const int asz = (ga < Mrows) ? 16 : 0;
            CP16(sbase + 0 * BUFB + so, A + (size_t)ga * 256 + k0 + prt, asz);
            CP16(sbase + 1 * BUFB + so, B + (size_t)(block_n + row) * 256 + k0 + prt, 16);
        }
    };

    issue(0);
    CP_COMMIT();

    for (int chunk = 0; chunk < 8; chunk++) {
        if (chunk < 7) { issue(chunk + 1); CP_COMMIT(); CP_WAIT1(); }
        else           { CP_WAIT0(); }
        __syncthreads();

        const int s = chunk & 1;
        const __half* ab = reinterpret_cast<const __half*>(smem + s * H_STAGEB);
        const __half* bb = ab + 128 * ASTR;

#pragma unroll
        for (int ks = 0; ks < 32; ks += 16) {
            wmma::fragment<wmma::matrix_a, 16, 16, 16, __half, wmma::row_major> fa[2];
            wmma::fragment<wmma::matrix_b, 16, 16, 16, __half, wmma::col_major> fb[4];
#pragma unroll
            for (int i = 0; i < 2; i++)
                wmma::load_matrix_sync(fa[i], ab + (wm * 32 + i * 16) * ASTR + ks, ASTR);
#pragma unroll
            for (int j = 0; j < 4; j++)
                wmma::load_matrix_sync(fb[j], bb + (wn * 64 + j * 16) * ASTR + ks, ASTR);
#pragma unroll
            for (int i = 0; i < 2; i++)
#pragma unroll
                for (int j = 0; j < 4; j++) wmma::mma_sync(acc[i][j], fa[i], fb[j], acc[i][j]);
        }
        __syncthreads();
    }

    float* stage = reinterpret_cast<float*>(smem);
#pragma unroll
    for (int i = 0; i < 2; i++)
#pragma unroll
        for (int j = 0; j < 4; j++)
            wmma::store_matrix_sync(stage + (wm * 32 + i * 16) * CSTRIDE + wn * 64 + j * 16,
                                    acc[i][j], CSTRIDE, wmma::mem_row_major);
    __syncthreads();
}

// ---------------------------------------------------------------------------
// Fused projection kernel (persistent): 780 tiles. Tile t: bx = t % 5,
// mt = t / 5. bx<2 -> value proj (padded output), bx>=2 -> off/attn proj.
// ---------------------------------------------------------------------------
__global__ __launch_bounds__(256, 2)
void proj_fused_kernel(const __half* __restrict__ Af,
                       const __half* __restrict__ Aq,
                       const __half* __restrict__ Bv,
                       const __half* __restrict__ Boa,
                       const float* __restrict__ b_val,
                       const float* __restrict__ b_off,
                       const float* __restrict__ b_attn,
                       const unsigned char* __restrict__ mask,
                       __half* __restrict__ Cval,      // padded layout
                       float* __restrict__ Coff,
                       float* __restrict__ Cattn,
                       int Mrows, int ntiles)
{
    extern __shared__ char smem[];
    const int tid = threadIdx.x;

    for (int t = blockIdx.x; t < ntiles; t += PGRID) {
        const int bx = t % 5;
        const int mt = t / 5;
        const bool is_val = (bx < 2);
        const int block_m = mt * 128;
        const int block_n = (is_val ? bx : bx - 2) * 128;

        gemm_body(is_val ? Af : Aq, is_val ? Bv : Boa, smem, block_m, block_n, Mrows);

        const float* stage = reinterpret_cast<const float*>(smem);
        const int r   = tid >> 1;
        const int gr  = block_m + r;
        if (gr < Mrows) {
            const int colb = (tid & 1) * 64;
            const int prow = is_val ? pad_row(gr) : 0;
#pragma unroll
            for (int g = 0; g < 64; g += 16) {
                const int gcol = block_n + colb + g;
                float v[16];
                if (is_val) {
#pragma unroll
                    for (int c = 0; c < 16; c++)
                        v[c] = stage[r * CSTRIDE + colb + g + c] + __ldg(b_val + gcol + c);
                    float scale = (mask != nullptr && mask[gr]) ? 0.f : 1.f;
                    __half hbuf[16];
#pragma unroll
                    for (int c = 0; c < 16; c++) hbuf[c] = __float2half_rn(v[c] * scale);
#pragma unroll
                    for (int c = 0; c < 16; c += 8)
                        *reinterpret_cast<uint4*>(Cval + (size_t)prow * 256 + gcol + c) =
                            *reinterpret_cast<uint4*>(hbuf + c);
                } else if (gcol < 256) {
#pragma unroll
                    for (int c = 0; c < 16; c++)
                        v[c] = stage[r * CSTRIDE + colb + g + c] + __ldg(b_off + gcol + c);
#pragma unroll
                    for (int c = 0; c < 16; c += 4) {
                        float4 o = make_float4(v[c], v[c+1], v[c+2], v[c+3]);
                        *reinterpret_cast<float4*>(Coff + (size_t)gr * 256 + gcol + c) = o;
                    }
                } else {
#pragma unroll
                    for (int c = 0; c < 16; c++)
                        v[c] = stage[r * CSTRIDE + colb + g + c] + __ldg(b_attn + gcol - 256 + c);
                    float mx = -1e30f;
#pragma unroll
                    for (int c = 0; c < 16; c++) mx = fmaxf(mx, v[c]);
                    float sum = 0.f;
#pragma unroll
                    for (int c = 0; c < 16; c++) { v[c] = __expf(v[c] - mx); sum += v[c]; }
                    float inv = 1.f / sum;
#pragma unroll
                    for (int c = 0; c < 16; c += 4) {
                        float4 o = make_float4(v[c]*inv, v[c+1]*inv, v[c+2]*inv, v[c+3]*inv);
                        *reinterpret_cast<float4*>(Cattn + (size_t)gr * 128 + gcol - 256 + c) = o;
                    }
                }
            }
        }
        __syncthreads();   // protect stage before next tile's pipeline writes
    }
}

// ---------------------------------------------------------------------------
// Output projection kernel (persistent): 312 tiles.
// ---------------------------------------------------------------------------
__global__ __launch_bounds__(256, 2)
void proj_out_kernel(const __half* __restrict__ A,
                     const __half* __restrict__ B,
                     const float* __restrict__ bias,
                     float* __restrict__ C,
                     int Mrows, int ntiles)
{
    extern __shared__ char smem[];
    const int tid = threadIdx.x;

    for (int t = blockIdx.x; t < ntiles; t += PGRID) {
        const int block_n = (t & 1) * 128;
        const int block_m = (t >> 1) * 128;

        gemm_body(A, B, smem, block_m, block_n, Mrows);

        const float* stage = reinterpret_cast<const float*>(smem);
        const int r  = tid >> 1;
        const int gr = block_m + r;
        if (gr < Mrows) {
            const int colb = (tid & 1) * 64;
#pragma unroll
            for (int g = 0; g < 64; g += 16) {
                const int gcol = block_n + colb + g;
                float v[16];
#pragma unroll
                for (int c = 0; c < 16; c++)
                    v[c] = stage[r * CSTRIDE + colb + g + c] + __ldg(bias + gcol + c);
#pragma unroll
                for (int c = 0; c < 16; c += 4) {
                    float4 o = make_float4(v[c], v[c+1], v[c+2], v[c+3]);
                    *reinterpret_cast<float4*>(C + (size_t)gr * 256 + gcol + c) = o;
                }
            }
        }
        __syncthreads();
    }
}

// ---------------------------------------------------------------------------
// Sampler v5: padded value -> no validity masks, no index clamps.
// warp = (q, head), lane = (p2, c4). x = clip(rx*W + ox - 0.5, -1, W).
// ---------------------------------------------------------------------------
__global__ __launch_bounds__(256)
void sample_kernel(const __half* __restrict__ value,   // padded
                   const float* __restrict__ off,
                   const float* __restrict__ aw,
                   const float* __restrict__ refp,
                   __half* __restrict__ mid)
{
    const int q    = blockIdx.x;
    const int m    = threadIdx.x >> 5;
    const int lane = threadIdx.x & 31;
    const int p2   = lane >> 3;
    const int c4   = lane & 7;

    const float offv = __ldg(off  + (size_t)q * 256 + m * 32 + lane);
    const float awv  = __ldg(aw   + (size_t)q * 128 + m * 16 + (lane & 15));
    const float rfv  = __ldg(refp + (size_t)q * 8 + (lane & 7));

    const __half* vbase = value + m * DH + c4 * 4;
    float acc0 = 0.f, acc1 = 0.f, acc2 = 0.f, acc3 = 0.f;

    // padded geometry: SB = level_start + Wp + 1 (folds the +1/+1 shift)
    const float WFT[NLVL] = {150.f, 75.f, 38.f, 19.f};
    const float HFT[NLVL] = {100.f, 50.f, 25.f, 13.f};
    const int   WPT[NLVL] = {153, 78, 41, 22};
    const int   SBT[NLVL] = {154, 15838, 19935, 21064};

#pragma unroll
    for (int l = 0; l < NLVL; l++) {
        const int pt = l * 4 + p2;
        const float rx = __shfl_sync(0xffffffffu, rfv, l * 2 + 0);
        const float ry = __shfl_sync(0xffffffffu, rfv, l * 2 + 1);
        const float ox = __shfl_sync(0xffffffffu, offv, pt * 2 + 0);
        const float oy = __shfl_sync(0xffffffffu, offv, pt * 2 + 1);
        const float a  = __shfl_sync(0xffffffffu, awv,  pt);

        const float Wf = WFT[l], Hf = HFT[l];
        const int   Wp = WPT[l], SB = SBT[l];

        float x = fmaf(rx, Wf, ox) - 0.5f;
        float y = fmaf(ry, Hf, oy) - 0.5f;
        x = fminf(fmaxf(x, -1.f), Wf);
        y = fminf(fmaxf(y, -1.f), Hf);

        const float x0f = floorf(x), y0f = floorf(y);
        const float wx1 = x - x0f, wx0 = 1.f - wx1;
        const float wy1 = y - y0f, wy0 = 1.f - wy1;

        const int i00 = SB + (int)y0f * Wp + (int)x0f;
        const __half* p00 = vbase + (size_t)i00 * 256;

        const uint2 u00 = __ldg(reinterpret_cast<const uint2*>(p00));
        const uint2 u01 = __ldg(reinterpret_cast<const uint2*>(p00 + 256));
        const uint2 u10 = __ldg(reinterpret_cast<const uint2*>(p00 + Wp * 256));
        const uint2 u11 = __ldg(reinterpret_cast<const uint2*>(p00 + (Wp + 1) * 256));

        const float w00 = wx0 * wy0, w01 = wx1 * wy0;
        const float w10 = wx0 * wy1, w11 = wx1 * wy1;

        const float2 a00 = __half22float2(*reinterpret_cast<const __half2*>(&u00.x));
        const float2 b00 = __half22float2(*reinterpret_cast<const __half2*>(&u00.y));
        const float2 a01 = __half22float2(*reinterpret_cast<const __half2*>(&u01.x));
        const float2 b01 = __half22float2(*reinterpret_cast<const __half2*>(&u01.y));
        const float2 a10 = __half22float2(*reinterpret_cast<const __half2*>(&u10.x));
        const float2 b10 = __half22float2(*reinterpret_cast<const __half2*>(&u10.y));
        const float2 a11 = __half22float2(*reinterpret_cast<const __half2*>(&u11.x));
        const float2 b11 = __half22float2(*reinterpret_cast<const __half2*>(&u11.y));

        float s0 = w00 * a00.x; s0 = fmaf(w01, a01.x, s0); s0 = fmaf(w10, a10.x, s0); s0 = fmaf(w11, a11.x, s0);
        float s1 = w00 * a00.y; s1 = fmaf(w01, a01.y, s1); s1 = fmaf(w10, a10.y, s1); s1 = fmaf(w11, a11.y, s1);
        float s2 = w00 * b00.x; s2 = fmaf(w01, b01.x, s2); s2 = fmaf(w10, b10.x, s2); s2 = fmaf(w11, b11.x, s2);
        float s3 = w00 * b00.y; s3 = fmaf(w01, b01.y, s3); s3 = fmaf(w10, b10.y, s3); s3 = fmaf(w11, b11.y, s3);

        acc0 = fmaf(a, s0, acc0);
        acc1 = fmaf(a, s1, acc1);
        acc2 = fmaf(a, s2, acc2);
        acc3 = fmaf(a, s3, acc3);
    }

    acc0 += __shfl_xor_sync(0xffffffffu, acc0, 8);
    acc1 += __shfl_xor_sync(0xffffffffu, acc1, 8);
    acc2 += __shfl_xor_sync(0xffffffffu, acc2, 8);
    acc3 += __shfl_xor_sync(0xffffffffu, acc3, 8);
    acc0 += __shfl_xor_sync(0xffffffffu, acc0, 16);
    acc1 += __shfl_xor_sync(0xffffffffu, acc1, 16);
    acc2 += __shfl_xor_sync(0xffffffffu, acc2, 16);
    acc3 += __shfl_xor_sync(0xffffffffu, acc3, 16);

    if (lane < 8) {
        __half2 h0 = __floats2half2_rn(acc0, acc1);
        __half2 h1 = __floats2half2_rn(acc2, acc3);
        uint2 u;
        u.x = *reinterpret_cast<uint32_t*>(&h0);
        u.y = *reinterpret_cast<uint32_t*>(&h1);
        *reinterpret_cast<uint2*>(mid + (size_t)q * 256 + m * DH + c4 * 4) = u;
    }
}

// ---------------------------------------------------------------------------
// Launch
// ---------------------------------------------------------------------------
extern "C" void kernel_launch(void* const* d_in, const int* in_sizes, int n_in,
                              void* d_out, int out_size)
{
    const float* query  = (const float*)d_in[0];
    const float* refp   = (const float*)d_in[1];
    const float* inflat = (const float*)d_in[2];
    const unsigned char* pmask = (const unsigned char*)d_in[3];
    const float* W_off  = (const float*)d_in[4];
    const float* b_off  = (const float*)d_in[5];
    const float* W_attn = (const float*)d_in[6];
    const float* b_attn = (const float*)d_in[7];
    const float* W_val  = (const float*)d_in[8];
    const float* b_val  = (const float*)d_in[9];
    const float* W_out  = (const float*)d_in[10];
    const float* b_out  = (const float*)d_in[11];
    float* out = (float*)d_out;

    __half* pvalp; cudaGetSymbolAddress((void**)&pvalp, g_value_pad);
    float*  poff;  cudaGetSymbolAddress((void**)&poff,  g_off);
    float*  pattn; cudaGetSymbolAddress((void**)&pattn, g_attn);
    __half *q_h, *f_h, *w_h, *mid_h;
    cudaGetSymbolAddress((void**)&q_h,   g_q_h);
    cudaGetSymbolAddress((void**)&f_h,   g_f_h);
    cudaGetSymbolAddress((void**)&w_h,   g_w_h);
    cudaGetSymbolAddress((void**)&mid_h, g_mid_h);

    cudaFuncSetAttribute(proj_fused_kernel,
                         cudaFuncAttributeMaxDynamicSharedMemorySize, H_SMEM);
    cudaFuncSetAttribute(proj_out_kernel,
                         cudaFuncAttributeMaxDynamicSharedMemorySize, H_SMEM);

    const int Mr = LEN;
    const int mtiles = (Mr + 127) / 128;          // 156

    zero_pad_kernel<<<(PAD_ROWS * 32 + 255) / 256, 256>>>(pvalp);
    prep_weights_kernel<<<(896 * 256 + 255) / 256, 256>>>(W_val, W_off, W_attn, W_out, w_h);
    prep_split_kernel<<<(2 * LEN * 64 + 255) / 256, 256>>>(query, inflat, q_h, f_h);

    const __half* wv  = w_h;
    const __half* woa = w_h + 256 * 256;
    const __half* wu  = w_h + 640 * 256;

    // 1. fused projections (persistent, 5*mtiles tiles)
    proj_fused_kernel<<<PGRID, 256, H_SMEM>>>(
        f_h, q_h, wv, woa, b_val, b_off, b_attn, pmask, pvalp, poff, pattn,
        Mr, 5 * mtiles);
    // 2. sampler (padded value)
    sample_kernel<<<Mr, 256>>>(pvalp, poff, pattn, refp, mid_h);
    // 3. output projection (persistent, 2*mtiles tiles)
    proj_out_kernel<<<PGRID, 256, H_SMEM>>>(mid_h, wu, b_out, out, Mr, 2 * mtiles);
}

// round 10
// speedup vs baseline: 3.1746x; 1.0443x over previous
#include <cuda_runtime.h>
#include <cuda_fp16.h>
#include <mma.h>
#include <cstdint>
#include <math.h>

using namespace nvcuda;

#define LEN    19947
#define NHEAD  8
#define DH     32
#define NLVL   4
#define NPTS   4

// Padded value tensor geometry (pad: +1 top/left, +2 bottom/right)
#define PAD_ROWS 21393

// ---------------------------------------------------------------------------
// Scratch (device globals)
// ---------------------------------------------------------------------------
__device__ __half g_value_pad[PAD_ROWS * 256];
__device__ float  g_off [LEN * 256];
__device__ float  g_attn[LEN * 128];
__device__ __half g_mid_h[LEN * 256];
__device__ __half g_q_h[LEN * 256];
__device__ __half g_f_h[LEN * 256];
__device__ __half g_w_h[896 * 256];

__device__ __forceinline__ uint32_t smem_u32(const void* p) {
    uint32_t a;
    asm("{ .reg .u64 t; cvta.to.shared.u64 t, %1; cvt.u32.u64 %0, t; }" : "=r"(a) : "l"(p));
    return a;
}

// logical value row (0..LEN) -> padded row index
__device__ __forceinline__ int pad_row(int gr) {
    int r, W, Wp, st;
    if (gr < 15000)      { r = gr;          W = 150; Wp = 153; st = 0; }
    else if (gr < 18750) { r = gr - 15000;  W = 75;  Wp = 78;  st = 15759; }
    else if (gr < 19700) { r = gr - 18750;  W = 38;  Wp = 41;  st = 19893; }
    else                 { r = gr - 19700;  W = 19;  Wp = 22;  st = 21041; }
    int y = r / W, x = r - y * W;
    return st + (y + 1) * Wp + (x + 1);
}

// ---------------------------------------------------------------------------
// Prep kernels
// ---------------------------------------------------------------------------
__global__ void zero_pad_kernel(__half* __restrict__ vp) {
    int id = blockIdx.x * blockDim.x + threadIdx.x;
    if (id < PAD_ROWS * 32)
        *reinterpret_cast<uint4*>(vp + (size_t)id * 8) = make_uint4(0, 0, 0, 0);
}

__global__ void prep_weights_kernel(const float* __restrict__ W_val,
                                    const float* __restrict__ W_off,
                                    const float* __restrict__ W_attn,
                                    const float* __restrict__ W_out,
                                    __half* __restrict__ wh)
{
    int id = blockIdx.x * blockDim.x + threadIdx.x;
    if (id >= 896 * 256) return;
    int n = id >> 8;
    int k = id & 255;
    float x;
    if (n < 256)      x = W_val [k * 256 + n];
    else if (n < 512) x = W_off [k * 256 + (n - 256)];
    else if (n < 640) x = W_attn[k * 128 + (n - 512)];
    else              x = W_out [k * 256 + (n - 640)];
    wh[id] = __float2half_rn(x);
}

__global__ void prep_split_kernel(const float* __restrict__ query,
                                  const float* __restrict__ inflat,
                                  __half* __restrict__ qh,
                                  __half* __restrict__ fh)
{
    const int total4 = LEN * 256 / 4;
    int id = blockIdx.x * blockDim.x + threadIdx.x;
    if (id >= 2 * total4) return;
    const float* src;
    __half* dst;
    int i4 = id;
    if (id < total4) { src = query;  dst = qh; }
    else             { src = inflat; dst = fh; i4 -= total4; }
    float4 v = *reinterpret_cast<const float4*>(src + (size_t)i4 * 4);
    __half h[4] = {__float2half_rn(v.x), __float2half_rn(v.y),
                   __float2half_rn(v.z), __float2half_rn(v.w)};
    *reinterpret_cast<uint2*>(dst + (size_t)i4 * 4) = *reinterpret_cast<uint2*>(h);
}

// ---------------------------------------------------------------------------
// cp.async macros
// ---------------------------------------------------------------------------
#define CP16(dst, src, sz) \
    asm volatile("cp.async.cg.shared.global [%0], [%1], 16, %2;" \
                 :: "r"(dst), "l"(src), "r"(sz))
#define CP_COMMIT() asm volatile("cp.async.commit_group;")
#define CP_WAIT1()  asm volatile("cp.async.wait_group 1;")
#define CP_WAIT0()  asm volatile("cp.async.wait_group 0;")

// BK = 64 config
#define ASTR 72
#define BUFB (128 * ASTR * 2)          // 18432 bytes per operand
#define H_STAGEB (2 * BUFB)            // 36864 per pipeline stage (A+B)
#define CSTRIDE 132
#define H_SMEM (2 * H_STAGEB)          // 73728 (epilogue stage 67584 fits)
#define PGRID 296

// ---------------------------------------------------------------------------
// GEMM body: BK=64, 2-stage cp.async pipeline, result staged fp32 in smem.
// ---------------------------------------------------------------------------
__device__ __forceinline__ void gemm_body(const __half* __restrict__ A,
                                          const __half* __restrict__ B,
                                          char* smem, int block_m, int block_n,
                                          int Mrows)
{
    const int tid  = threadIdx.x;
    const int warp = tid >> 5;
    const int wm   = warp & 3;
    const int wn   = warp >> 2;
    const uint32_t sb = smem_u32(smem);

    wmma::fragment<wmma::accumulator, 16, 16, 16, float> acc[2][4];
#pragma unroll
    for (int i = 0; i < 2; i++)
#pragma unroll
        for (int j = 0; j < 4; j++) wmma::fill_fragment(acc[i][j], 0.f);

    auto issue = [&](int chunk) {
        const int s = chunk & 1;
        const int k0 = chunk * 64;
        const uint32_t sbase = sb + s * H_STAGEB;
#pragma unroll
        for (int h = 0; h < 4; h++) {
            const int c   = tid + h * 256;       // 0..1023
            const int row = c >> 3;
            const int prt = (c & 7) * 8;         // halves within 64
            const uint32_t so = (uint32_t)(row * ASTR + prt) * 2;
            const int ga  = block_m + row;
            const int asz = (ga < Mrows) ? 16 : 0;
            CP16(sbase + so,        A + (size_t)ga * 256 + k0 + prt, asz);
            CP16(sbase + BUFB + so, B + (size_t)(block_n + row) * 256 + k0 + prt, 16);
        }
    };

    issue(0);
    CP_COMMIT();

    for (int chunk = 0; chunk < 4; chunk++) {
        if (chunk < 3) { issue(chunk + 1); CP_COMMIT(); CP_WAIT1(); }
        else           { CP_WAIT0(); }
        __syncthreads();

        const int s = chunk & 1;
        const __half* ab = reinterpret_cast<const __half*>(smem + s * H_STAGEB);
        const __half* bb = ab + 128 * ASTR;

#pragma unroll
        for (int ks = 0; ks < 64; ks += 16) {
            wmma::fragment<wmma::matrix_a, 16, 16, 16, __half, wmma::row_major> fa[2];
            wmma::fragment<wmma::matrix_b, 16, 16, 16, __half, wmma::col_major> fb[4];
#pragma unroll
            for (int i = 0; i < 2; i++)
                wmma::load_matrix_sync(fa[i], ab + (wm * 32 + i * 16) * ASTR + ks, ASTR);
#pragma unroll
            for (int j = 0; j < 4; j++)
                wmma::load_matrix_sync(fb[j], bb + (wn * 64 + j * 16) * ASTR + ks, ASTR);
#pragma unroll
            for (int i = 0; i < 2; i++)
#pragma unroll
                for (int j = 0; j < 4; j++) wmma::mma_sync(acc[i][j], fa[i], fb[j], acc[i][j]);
        }
        __syncthreads();
    }

    float* stage = reinterpret_cast<float*>(smem);
#pragma unroll
    for (int i = 0; i < 2; i++)
#pragma unroll
        for (int j = 0; j < 4; j++)
            wmma::store_matrix_sync(stage + (wm * 32 + i * 16) * CSTRIDE + wn * 64 + j * 16,
                                    acc[i][j], CSTRIDE, wmma::mem_row_major);
    __syncthreads();
}

// ---------------------------------------------------------------------------
// Fused projection kernel (persistent): 780 tiles.
// ---------------------------------------------------------------------------
__global__ __launch_bounds__(256, 2)
void proj_fused_kernel(const __half* __restrict__ Af,
                       const __half* __restrict__ Aq,
                       const __half* __restrict__ Bv,
                       const __half* __restrict__ Boa,
                       const float* __restrict__ b_val,
                       const float* __restrict__ b_off,
                       const float* __restrict__ b_attn,
                       const unsigned char* __restrict__ mask,
                       __half* __restrict__ Cval,
                       float* __restrict__ Coff,
                       float* __restrict__ Cattn,
                       int Mrows, int ntiles)
{
    extern __shared__ char smem[];
    const int tid = threadIdx.x;

    for (int t = blockIdx.x; t < ntiles; t += PGRID) {
        const int bx = t % 5;
        const int mt = t / 5;
        const bool is_val = (bx < 2);
        const int block_m = mt * 128;
        const int block_n = (is_val ? bx : bx - 2) * 128;

        gemm_body(is_val ? Af : Aq, is_val ? Bv : Boa, smem, block_m, block_n, Mrows);

        const float* stage = reinterpret_cast<const float*>(smem);
        const int r   = tid >> 1;
        const int gr  = block_m + r;
        if (gr < Mrows) {
            const int colb = (tid & 1) * 64;
            const int prow = is_val ? pad_row(gr) : 0;
#pragma unroll
            for (int g = 0; g < 64; g += 16) {
                const int gcol = block_n + colb + g;
                float v[16];
                if (is_val) {
#pragma unroll
                    for (int c = 0; c < 16; c++)
                        v[c] = stage[r * CSTRIDE + colb + g + c] + __ldg(b_val + gcol + c);
                    float scale = (mask != nullptr && mask[gr]) ? 0.f : 1.f;
                    __half hbuf[16];
#pragma unroll
                    for (int c = 0; c < 16; c++) hbuf[c] = __float2half_rn(v[c] * scale);
#pragma unroll
                    for (int c = 0; c < 16; c += 8)
                        *reinterpret_cast<uint4*>(Cval + (size_t)prow * 256 + gcol + c) =
                            *reinterpret_cast<uint4*>(hbuf + c);
                } else if (gcol < 256) {
#pragma unroll
                    for (int c = 0; c < 16; c++)
                        v[c] = stage[r * CSTRIDE + colb + g + c] + __ldg(b_off + gcol + c);
#pragma unroll
                    for (int c = 0; c < 16; c += 4) {
                        float4 o = make_float4(v[c], v[c+1], v[c+2], v[c+3]);
                        *reinterpret_cast<float4*>(Coff + (size_t)gr * 256 + gcol + c) = o;
                    }
                } else {
#pragma unroll
                    for (int c = 0; c < 16; c++)
                        v[c] = stage[r * CSTRIDE + colb + g + c] + __ldg(b_attn + gcol - 256 + c);
                    float mx = -1e30f;
#pragma unroll
                    for (int c = 0; c < 16; c++) mx = fmaxf(mx, v[c]);
                    float sum = 0.f;
#pragma unroll
                    for (int c = 0; c < 16; c++) { v[c] = __expf(v[c] - mx); sum += v[c]; }
                    float inv = 1.f / sum;
#pragma unroll
                    for (int c = 0; c < 16; c += 4) {
                        float4 o = make_float4(v[c]*inv, v[c+1]*inv, v[c+2]*inv, v[c+3]*inv);
                        *reinterpret_cast<float4*>(Cattn + (size_t)gr * 128 + gcol - 256 + c) = o;
                    }
                }
            }
        }
        __syncthreads();
    }
}

// ---------------------------------------------------------------------------
// Output projection kernel (persistent): 312 tiles.
// ---------------------------------------------------------------------------
__global__ __launch_bounds__(256, 2)
void proj_out_kernel(const __half* __restrict__ A,
                     const __half* __restrict__ B,
                     const float* __restrict__ bias,
                     float* __restrict__ C,
                     int Mrows, int ntiles)
{
    extern __shared__ char smem[];
    const int tid = threadIdx.x;

    for (int t = blockIdx.x; t < ntiles; t += PGRID) {
        const int block_n = (t & 1) * 128;
        const int block_m = (t >> 1) * 128;

        gemm_body(A, B, smem, block_m, block_n, Mrows);

        const float* stage = reinterpret_cast<const float*>(smem);
        const int r  = tid >> 1;
        const int gr = block_m + r;
        if (gr < Mrows) {
            const int colb = (tid & 1) * 64;
#pragma unroll
            for (int g = 0; g < 64; g += 16) {
                const int gcol = block_n + colb + g;
                float v[16];
#pragma unroll
                for (int c = 0; c < 16; c++)
                    v[c] = stage[r * CSTRIDE + colb + g + c] + __ldg(bias + gcol + c);
#pragma unroll
                for (int c = 0; c < 16; c += 4) {
                    float4 o = make_float4(v[c], v[c+1], v[c+2], v[c+3]);
                    *reinterpret_cast<float4*>(C + (size_t)gr * 256 + gcol + c) = o;
                }
            }
        }
        __syncthreads();
    }
}

// ---------------------------------------------------------------------------
// Sampler v6: padded value, half2 corner interpolation (HFMA2), fp32 attn
// accumulation. warp = (q, head), lane = (p2, c4).
// ---------------------------------------------------------------------------
__global__ __launch_bounds__(256)
void sample_kernel(const __half* __restrict__ value,
                   const float* __restrict__ off,
                   const float* __restrict__ aw,
                   const float* __restrict__ refp,
                   __half* __restrict__ mid)
{
    const int q    = blockIdx.x;
    const int m    = threadIdx.x >> 5;
    const int lane = threadIdx.x & 31;
    const int p2   = lane >> 3;
    const int c4   = lane & 7;

    const float offv = __ldg(off  + (size_t)q * 256 + m * 32 + lane);
    const float awv  = __ldg(aw   + (size_t)q * 128 + m * 16 + (lane & 15));
    const float rfv  = __ldg(refp + (size_t)q * 8 + (lane & 7));

    const __half* vbase = value + m * DH + c4 * 4;
    float acc0 = 0.f, acc1 = 0.f, acc2 = 0.f, acc3 = 0.f;

    const float WFT[NLVL] = {150.f, 75.f, 38.f, 19.f};
    const float HFT[NLVL] = {100.f, 50.f, 25.f, 13.f};
    const int   WPT[NLVL] = {153, 78, 41, 22};
    const int   SBT[NLVL] = {154, 15838, 19935, 21064};

#pragma unroll
    for (int l = 0; l < NLVL; l++) {
        const int pt = l * 4 + p2;
        const float rx = __shfl_sync(0xffffffffu, rfv, l * 2 + 0);
        const float ry = __shfl_sync(0xffffffffu, rfv, l * 2 + 1);
        const float ox = __shfl_sync(0xffffffffu, offv, pt * 2 + 0);
        const float oy = __shfl_sync(0xffffffffu, offv, pt * 2 + 1);
        const float a  = __shfl_sync(0xffffffffu, awv,  pt);

        const float Wf = WFT[l], Hf = HFT[l];
        const int   Wp = WPT[l], SB = SBT[l];

        float x = fmaf(rx, Wf, ox) - 0.5f;
        float y = fmaf(ry, Hf, oy) - 0.5f;
        x = fminf(fmaxf(x, -1.f), Wf);
        y = fminf(fmaxf(y, -1.f), Hf);

        const float x0f = floorf(x), y0f = floorf(y);
        const float wx1 = x - x0f, wx0 = 1.f - wx1;
        const float wy1 = y - y0f, wy0 = 1.f - wy1;

        const int i00 = SB + (int)y0f * Wp + (int)x0f;
        const __half* p00 = vbase + (size_t)i00 * 256;

        const uint2 u00 = __ldg(reinterpret_cast<const uint2*>(p00));
        const uint2 u01 = __ldg(reinterpret_cast<const uint2*>(p00 + 256));
        const uint2 u10 = __ldg(reinterpret_cast<const uint2*>(p00 + Wp * 256));
        const uint2 u11 = __ldg(reinterpret_cast<const uint2*>(p00 + (Wp + 1) * 256));

        const __half2 W00 = __float2half2_rn(wx0 * wy0);
        const __half2 W01 = __float2half2_rn(wx1 * wy0);
        const __half2 W10 = __float2half2_rn(wx0 * wy1);
        const __half2 W11 = __float2half2_rn(wx1 * wy1);

        __half2 sa = __hmul2(W00, *reinterpret_cast<const __half2*>(&u00.x));
        sa = __hfma2(W01, *reinterpret_cast<const __half2*>(&u01.x), sa);
        sa = __hfma2(W10, *reinterpret_cast<const __half2*>(&u10.x), sa);
        sa = __hfma2(W11, *reinterpret_cast<const __half2*>(&u11.x), sa);

        __half2 sb = __hmul2(W00, *reinterpret_cast<const __half2*>(&u00.y));
        sb = __hfma2(W01, *reinterpret_cast<const __half2*>(&u01.y), sb);
        sb = __hfma2(W10, *reinterpret_cast<const __half2*>(&u10.y), sb);
        sb = __hfma2(W11, *reinterpret_cast<const __half2*>(&u11.y), sb);

        const float2 fa = __half22float2(sa);
        const float2 fb = __half22float2(sb);

        acc0 = fmaf(a, fa.x, acc0);
        acc1 = fmaf(a, fa.y, acc1);
        acc2 = fmaf(a, fb.x, acc2);
        acc3 = fmaf(a, fb.y, acc3);
    }

    acc0 += __shfl_xor_sync(0xffffffffu, acc0, 8);
    acc1 += __shfl_xor_sync(0xffffffffu, acc1, 8);
    acc2 += __shfl_xor_sync(0xffffffffu, acc2, 8);
    acc3 += __shfl_xor_sync(0xffffffffu, acc3, 8);
    acc0 += __shfl_xor_sync(0xffffffffu, acc0, 16);
    acc1 += __shfl_xor_sync(0xffffffffu, acc1, 16);
    acc2 += __shfl_xor_sync(0xffffffffu, acc2, 16);
    acc3 += __shfl_xor_sync(0xffffffffu, acc3, 16);

    if (lane < 8) {
        __half2 h0 = __floats2half2_rn(acc0, acc1);
        __half2 h1 = __floats2half2_rn(acc2, acc3);
        uint2 u;
        u.x = *reinterpret_cast<uint32_t*>(&h0);
        u.y = *reinterpret_cast<uint32_t*>(&h1);
        *reinterpret_cast<uint2*>(mid + (size_t)q * 256 + m * DH + c4 * 4) = u;
    }
}

// ---------------------------------------------------------------------------
// Launch
// ---------------------------------------------------------------------------
extern "C" void kernel_launch(void* const* d_in, const int* in_sizes, int n_in,
                              void* d_out, int out_size)
{
    const float* query  = (const float*)d_in[0];
    const float* refp   = (const float*)d_in[1];
    const float* inflat = (const float*)d_in[2];
    const unsigned char* pmask = (const unsigned char*)d_in[3];
    const float* W_off  = (const float*)d_in[4];
    const float* b_off  = (const float*)d_in[5];
    const float* W_attn = (const float*)d_in[6];
    const float* b_attn = (const float*)d_in[7];
    const float* W_val  = (const float*)d_in[8];
    const float* b_val  = (const float*)d_in[9];
    const float* W_out  = (const float*)d_in[10];
    const float* b_out  = (const float*)d_in[11];
    float* out = (float*)d_out;

    __half* pvalp; cudaGetSymbolAddress((void**)&pvalp, g_value_pad);
    float*  poff;  cudaGetSymbolAddress((void**)&poff,  g_off);
    float*  pattn; cudaGetSymbolAddress((void**)&pattn, g_attn);
    __half *q_h, *f_h, *w_h, *mid_h;
    cudaGetSymbolAddress((void**)&q_h,   g_q_h);
    cudaGetSymbolAddress((void**)&f_h,   g_f_h);
    cudaGetSymbolAddress((void**)&w_h,   g_w_h);
    cudaGetSymbolAddress((void**)&mid_h, g_mid_h);

    cudaFuncSetAttribute(proj_fused_kernel,
                         cudaFuncAttributeMaxDynamicSharedMemorySize, H_SMEM);
    cudaFuncSetAttribute(proj_out_kernel,
                         cudaFuncAttributeMaxDynamicSharedMemorySize, H_SMEM);

    const int Mr = LEN;
    const int mtiles = (Mr + 127) / 128;          // 156

    zero_pad_kernel<<<(PAD_ROWS * 32 + 255) / 256, 256>>>(pvalp);
    prep_weights_kernel<<<(896 * 256 + 255) / 256, 256>>>(W_val, W_off, W_attn, W_out, w_h);
    prep_split_kernel<<<(2 * LEN * 64 + 255) / 256, 256>>>(query, inflat, q_h, f_h);

    const __half* wv  = w_h;
    const __half* woa = w_h + 256 * 256;
    const __half* wu  = w_h + 640 * 256;

    // 1. fused projections (persistent)
    proj_fused_kernel<<<PGRID, 256, H_SMEM>>>(
        f_h, q_h, wv, woa, b_val, b_off, b_attn, pmask, pvalp, poff, pattn,
        Mr, 5 * mtiles);
    // 2. sampler (padded value, half2 interp)
    sample_kernel<<<Mr, 256>>>(pvalp, poff, pattn, refp, mid_h);
    // 3. output projection (persistent)
    proj_out_kernel<<<PGRID, 256, H_SMEM>>>(mid_h, wu, b_out, out, Mr, 2 * mtiles);
}

// round 11
// speedup vs baseline: 3.2365x; 1.0195x over previous
#include <cuda_runtime.h>
#include <cuda_fp16.h>
#include <mma.h>
#include <cstdint>
#include <math.h>

using namespace nvcuda;

#define LEN    19947
#define NHEAD  8
#define DH     32
#define NLVL   4
#define NPTS   4

// Padded value tensor geometry (pad: +1 top/left, +2 bottom/right)
#define PAD_ROWS 21393

// ---------------------------------------------------------------------------
// Scratch (device globals)
// ---------------------------------------------------------------------------
__device__ __half g_value_pad[PAD_ROWS * 256];
__device__ float  g_off [LEN * 256];
__device__ float  g_attn[LEN * 128];
__device__ __half g_mid_h[LEN * 256];
__device__ __half g_q_h[LEN * 256];
__device__ __half g_f_h[LEN * 256];
__device__ __half g_w_h[896 * 256];

__device__ __forceinline__ uint32_t smem_u32(const void* p) {
    uint32_t a;
    asm("{ .reg .u64 t; cvta.to.shared.u64 t, %1; cvt.u32.u64 %0, t; }" : "=r"(a) : "l"(p));
    return a;
}

// logical value row (0..LEN) -> padded row index
__device__ __forceinline__ int pad_row(int gr) {
    int r, W, Wp, st;
    if (gr < 15000)      { r = gr;          W = 150; Wp = 153; st = 0; }
    else if (gr < 18750) { r = gr - 15000;  W = 75;  Wp = 78;  st = 15759; }
    else if (gr < 19700) { r = gr - 18750;  W = 38;  Wp = 41;  st = 19893; }
    else                 { r = gr - 19700;  W = 19;  Wp = 22;  st = 21041; }
    int y = r / W, x = r - y * W;
    return st + (y + 1) * Wp + (x + 1);
}

// ---------------------------------------------------------------------------
// Single fused prep kernel: id-ranges -> zero pad | weights | activations
// ---------------------------------------------------------------------------
#define PREP_A (PAD_ROWS * 32)                 // uint4 zero units
#define PREP_B (896 * 256)                     // weight elements
#define PREP_C (2 * LEN * 64)                  // float4 split units
#define PREP_TOTAL (PREP_A + PREP_B + PREP_C)

__global__ void prep_all_kernel(const float* __restrict__ W_val,
                                const float* __restrict__ W_off,
                                const float* __restrict__ W_attn,
                                const float* __restrict__ W_out,
                                const float* __restrict__ query,
                                const float* __restrict__ inflat,
                                __half* __restrict__ vp,
                                __half* __restrict__ wh,
                                __half* __restrict__ qh,
                                __half* __restrict__ fh)
{
    int id = blockIdx.x * blockDim.x + threadIdx.x;
    if (id < PREP_A) {
        *reinterpret_cast<uint4*>(vp + (size_t)id * 8) = make_uint4(0, 0, 0, 0);
    } else if (id < PREP_A + PREP_B) {
        int e = id - PREP_A;
        int n = e >> 8;
        int k = e & 255;
        float x;
        if (n < 256)      x = W_val [k * 256 + n];
        else if (n < 512) x = W_off [k * 256 + (n - 256)];
        else if (n < 640) x = W_attn[k * 128 + (n - 512)];
        else              x = W_out [k * 256 + (n - 640)];
        wh[e] = __float2half_rn(x);
    } else if (id < PREP_TOTAL) {
        int e = id - PREP_A - PREP_B;
        const int total4 = LEN * 64;
        const float* src;
        __half* dst;
        int i4 = e;
        if (e < total4) { src = query;  dst = qh; }
        else            { src = inflat; dst = fh; i4 -= total4; }
        float4 v = *reinterpret_cast<const float4*>(src + (size_t)i4 * 4);
        __half h[4] = {__float2half_rn(v.x), __float2half_rn(v.y),
                       __float2half_rn(v.z), __float2half_rn(v.w)};
        *reinterpret_cast<uint2*>(dst + (size_t)i4 * 4) = *reinterpret_cast<uint2*>(h);
    }
}

// ---------------------------------------------------------------------------
// cp.async macros
// ---------------------------------------------------------------------------
#define CP16(dst, src, sz) \
    asm volatile("cp.async.cg.shared.global [%0], [%1], 16, %2;" \
                 :: "r"(dst), "l"(src), "r"(sz))
#define CP_COMMIT() asm volatile("cp.async.commit_group;")
#define CP_WAIT1()  asm volatile("cp.async.wait_group 1;")
#define CP_WAIT0()  asm volatile("cp.async.wait_group 0;")

// BK = 64, 3-stage pipeline
#define ASTR 72
#define BUFB (128 * ASTR * 2)          // 18432 bytes per operand
#define H_STAGEB (2 * BUFB)            // 36864 per pipeline stage
#define CSTRIDE 132
#define H_SMEM (3 * H_STAGEB)          // 110592 (epilogue stage 67584 fits)
#define PGRID 296

// ---------------------------------------------------------------------------
// GEMM body: BK=64, 3-stage cp.async pipeline, result staged fp32 in smem.
// ---------------------------------------------------------------------------
__device__ __forceinline__ void gemm_body(const __half* __restrict__ A,
                                          const __half* __restrict__ B,
                                          char* smem, int block_m, int block_n,
                                          int Mrows)
{
    const int tid  = threadIdx.x;
    const int warp = tid >> 5;
    const int wm   = warp & 3;
    const int wn   = warp >> 2;
    const uint32_t sb = smem_u32(smem);

    wmma::fragment<wmma::accumulator, 16, 16, 16, float> acc[2][4];
#pragma unroll
    for (int i = 0; i < 2; i++)
#pragma unroll
        for (int j = 0; j < 4; j++) wmma::fill_fragment(acc[i][j], 0.f);

    auto issue = [&](int chunk) {
        const int s = chunk % 3;
        const int k0 = chunk * 64;
        const uint32_t sbase = sb + s * H_STAGEB;
#pragma unroll
        for (int h = 0; h < 4; h++) {
            const int c   = tid + h * 256;
            const int row = c >> 3;
            const int prt = (c & 7) * 8;
            const uint32_t so = (uint32_t)(row * ASTR + prt) * 2;
            const int ga  = block_m + row;
            const int asz = (ga < Mrows) ? 16 : 0;
            CP16(sbase + so,        A + (size_t)ga * 256 + k0 + prt, asz);
            CP16(sbase + BUFB + so, B + (size_t)(block_n + row) * 256 + k0 + prt, 16);
        }
    };

    issue(0);
    CP_COMMIT();
    issue(1);
    CP_COMMIT();

    for (int chunk = 0; chunk < 4; chunk++) {
        if (chunk < 3) { CP_WAIT1(); } else { CP_WAIT0(); }
        __syncthreads();

        const int s = chunk % 3;
        const __half* ab = reinterpret_cast<const __half*>(smem + s * H_STAGEB);
        const __half* bb = ab + 128 * ASTR;

#pragma unroll
        for (int ks = 0; ks < 64; ks += 16) {
            wmma::fragment<wmma::matrix_a, 16, 16, 16, __half, wmma::row_major> fa[2];
            wmma::fragment<wmma::matrix_b, 16, 16, 16, __half, wmma::col_major> fb[4];
#pragma unroll
            for (int i = 0; i < 2; i++)
                wmma::load_matrix_sync(fa[i], ab + (wm * 32 + i * 16) * ASTR + ks, ASTR);
#pragma unroll
            for (int j = 0; j < 4; j++)
                wmma::load_matrix_sync(fb[j], bb + (wn * 64 + j * 16) * ASTR + ks, ASTR);
#pragma unroll
            for (int i = 0; i < 2; i++)
#pragma unroll
                for (int j = 0; j < 4; j++) wmma::mma_sync(acc[i][j], fa[i], fb[j], acc[i][j]);
        }
        __syncthreads();

        if (chunk < 2) { issue(chunk + 2); CP_COMMIT(); }
    }

    float* stage = reinterpret_cast<float*>(smem);
#pragma unroll
    for (int i = 0; i < 2; i++)
#pragma unroll
        for (int j = 0; j < 4; j++)
            wmma::store_matrix_sync(stage + (wm * 32 + i * 16) * CSTRIDE + wn * 64 + j * 16,
                                    acc[i][j], CSTRIDE, wmma::mem_row_major);
    __syncthreads();
}

// ---------------------------------------------------------------------------
// Fused projection kernel (persistent): 780 tiles.
// ---------------------------------------------------------------------------
__global__ __launch_bounds__(256, 2)
void proj_fused_kernel(const __half* __restrict__ Af,
                       const __half* __restrict__ Aq,
                       const __half* __restrict__ Bv,
                       const __half* __restrict__ Boa,
                       const float* __restrict__ b_val,
                       const float* __restrict__ b_off,
                       const float* __restrict__ b_attn,
                       const unsigned char* __restrict__ mask,
                       __half* __restrict__ Cval,
                       float* __restrict__ Coff,
                       float* __restrict__ Cattn,
                       int Mrows, int ntiles)
{
    extern __shared__ char smem[];
    const int tid = threadIdx.x;

    for (int t = blockIdx.x; t < ntiles; t += PGRID) {
        const int bx = t % 5;
        const int mt = t / 5;
        const bool is_val = (bx < 2);
        const int block_m = mt * 128;
        const int block_n = (is_val ? bx : bx - 2) * 128;

        gemm_body(is_val ? Af : Aq, is_val ? Bv : Boa, smem, block_m, block_n, Mrows);

        const float* stage = reinterpret_cast<const float*>(smem);
        const int r   = tid >> 1;
        const int gr  = block_m + r;
        if (gr < Mrows) {
            const int colb = (tid & 1) * 64;
            const int prow = is_val ? pad_row(gr) : 0;
#pragma unroll
            for (int g = 0; g < 64; g += 16) {
                const int gcol = block_n + colb + g;
                float v[16];
                if (is_val) {
#pragma unroll
                    for (int c = 0; c < 16; c++)
                        v[c] = stage[r * CSTRIDE + colb + g + c] + __ldg(b_val + gcol + c);
                    float scale = (mask != nullptr && mask[gr]) ? 0.f : 1.f;
                    __half hbuf[16];
#pragma unroll
                    for (int c = 0; c < 16; c++) hbuf[c] = __float2half_rn(v[c] * scale);
#pragma unroll
                    for (int c = 0; c < 16; c += 8)
                        *reinterpret_cast<uint4*>(Cval + (size_t)prow * 256 + gcol + c) =
                            *reinterpret_cast<uint4*>(hbuf + c);
                } else if (gcol < 256) {
#pragma unroll
                    for (int c = 0; c < 16; c++)
                        v[c] = stage[r * CSTRIDE + colb + g + c] + __ldg(b_off + gcol + c);
#pragma unroll
                    for (int c = 0; c < 16; c += 4) {
                        float4 o = make_float4(v[c], v[c+1], v[c+2], v[c+3]);
                        *reinterpret_cast<float4*>(Coff + (size_t)gr * 256 + gcol + c) = o;
                    }
                } else {
#pragma unroll
                    for (int c = 0; c < 16; c++)
                        v[c] = stage[r * CSTRIDE + colb + g + c] + __ldg(b_attn + gcol - 256 + c);
                    float mx = -1e30f;
#pragma unroll
                    for (int c = 0; c < 16; c++) mx = fmaxf(mx, v[c]);
                    float sum = 0.f;
#pragma unroll
                    for (int c = 0; c < 16; c++) { v[c] = __expf(v[c] - mx); sum += v[c]; }
                    float inv = 1.f / sum;
#pragma unroll
                    for (int c = 0; c < 16; c += 4) {
                        float4 o = make_float4(v[c]*inv, v[c+1]*inv, v[c+2]*inv, v[c+3]*inv);
                        *reinterpret_cast<float4*>(Cattn + (size_t)gr * 128 + gcol - 256 + c) = o;
                    }
                }
            }
        }
        __syncthreads();
    }
}

// ---------------------------------------------------------------------------
// Output projection kernel (persistent): 312 tiles.
// ---------------------------------------------------------------------------
__global__ __launch_bounds__(256, 2)
void proj_out_kernel(const __half* __restrict__ A,
                     const __half* __restrict__ B,
                     const float* __restrict__ bias,
                     float* __restrict__ C,
                     int Mrows, int ntiles)
{
    extern __shared__ char smem[];
    const int tid = threadIdx.x;

    for (int t = blockIdx.x; t < ntiles; t += PGRID) {
        const int block_n = (t & 1) * 128;
        const int block_m = (t >> 1) * 128;

        gemm_body(A, B, smem, block_m, block_n, Mrows);

        const float* stage = reinterpret_cast<const float*>(smem);
        const int r  = tid >> 1;
        const int gr = block_m + r;
        if (gr < Mrows) {
            const int colb = (tid & 1) * 64;
#pragma unroll
            for (int g = 0; g < 64; g += 16) {
                const int gcol = block_n + colb + g;
                float v[16];
#pragma unroll
                for (int c = 0; c < 16; c++)
                    v[c] = stage[r * CSTRIDE + colb + g + c] + __ldg(bias + gcol + c);
#pragma unroll
                for (int c = 0; c < 16; c += 4) {
                    float4 o = make_float4(v[c], v[c+1], v[c+2], v[c+3]);
                    *reinterpret_cast<float4*>(C + (size_t)gr * 256 + gcol + c) = o;
                }
            }
        }
        __syncthreads();
    }
}

// ---------------------------------------------------------------------------
// Sampler v7: phase-split. Phase 1: lane k (k=lane&15) computes point-k's
// padded index + attention-scaled bilinear weights (packed half2x2).
// Phase 2: per level, 3 shfls + 4 LDG.64 + HFMA2 interp + fp32 accumulate.
// ---------------------------------------------------------------------------
__global__ __launch_bounds__(256)
void sample_kernel(const __half* __restrict__ value,
                   const float* __restrict__ off,
                   const float* __restrict__ aw,
                   const float* __restrict__ refp,
                   __half* __restrict__ mid)
{
    const int q    = blockIdx.x;
    const int m    = threadIdx.x >> 5;
    const int lane = threadIdx.x & 31;
    const int p2   = lane >> 3;
    const int c4   = lane & 7;

    const float offv = __ldg(off  + (size_t)q * 256 + m * 32 + lane);
    const float awv  = __ldg(aw   + (size_t)q * 128 + m * 16 + (lane & 15));
    const float rfv  = __ldg(refp + (size_t)q * 8 + (lane & 7));

    // ---- phase 1: per-lane point pt0 = lane & 15 ----
    const int pt0 = lane & 15;
    const int l0  = pt0 >> 2;
    const float rx = __shfl_sync(0xffffffffu, rfv, l0 * 2 + 0);
    const float ry = __shfl_sync(0xffffffffu, rfv, l0 * 2 + 1);
    const float ox = __shfl_sync(0xffffffffu, offv, pt0 * 2 + 0);
    const float oy = __shfl_sync(0xffffffffu, offv, pt0 * 2 + 1);

    const float Wf = (l0 == 0) ? 150.f : (l0 == 1) ? 75.f : (l0 == 2) ? 38.f : 19.f;
    const float Hf = (l0 == 0) ? 100.f : (l0 == 1) ? 50.f : (l0 == 2) ? 25.f : 13.f;
    const int   Wp0 = (l0 == 0) ? 153 : (l0 == 1) ? 78 : (l0 == 2) ? 41 : 22;
    const int   SB0 = (l0 == 0) ? 154 : (l0 == 1) ? 15838 : (l0 == 2) ? 19935 : 21064;

    float x = fmaf(rx, Wf, ox) - 0.5f;
    float y = fmaf(ry, Hf, oy) - 0.5f;
    x = fminf(fmaxf(x, -1.f), Wf);
    y = fminf(fmaxf(y, -1.f), Hf);

    const float x0f = floorf(x), y0f = floorf(y);
    const float wx1 = x - x0f, wx0 = 1.f - wx1;
    const float wy1 = y - y0f, wy0 = 1.f - wy1;
    const int i00r = SB0 + (int)y0f * Wp0 + (int)x0f;

    // attention weight folded into corner weights, packed as half2 pairs
    __half2 pk01h = __floats2half2_rn(wx0 * wy0 * awv, wx1 * wy0 * awv);
    __half2 pk23h = __floats2half2_rn(wx0 * wy1 * awv, wx1 * wy1 * awv);
    const uint32_t pk01 = *reinterpret_cast<uint32_t*>(&pk01h);
    const uint32_t pk23 = *reinterpret_cast<uint32_t*>(&pk23h);

    const __half* vbase = value + m * DH + c4 * 4;
    float acc0 = 0.f, acc1 = 0.f, acc2 = 0.f, acc3 = 0.f;

    const int WPT[NLVL] = {153, 78, 41, 22};

    // ---- phase 2 ----
#pragma unroll
    for (int l = 0; l < NLVL; l++) {
        const int src = l * 4 + p2;
        const int i00 = __shfl_sync(0xffffffffu, i00r, src);
        const uint32_t a01 = __shfl_sync(0xffffffffu, pk01, src);
        const uint32_t a23 = __shfl_sync(0xffffffffu, pk23, src);

        const __half2 h01 = *reinterpret_cast<const __half2*>(&a01);
        const __half2 h23 = *reinterpret_cast<const __half2*>(&a23);
        const __half2 W00 = __low2half2(h01),  W01 = __high2half2(h01);
        const __half2 W10 = __low2half2(h23),  W11 = __high2half2(h23);

        const int Wp = WPT[l];
        const __half* p00 = vbase + (size_t)i00 * 256;

        const uint2 u00 = __ldg(reinterpret_cast<const uint2*>(p00));
        const uint2 u01 = __ldg(reinterpret_cast<const uint2*>(p00 + 256));
        const uint2 u10 = __ldg(reinterpret_cast<const uint2*>(p00 + Wp * 256));
        const uint2 u11 = __ldg(reinterpret_cast<const uint2*>(p00 + (Wp + 1) * 256));

        __half2 sa = __hmul2(W00, *reinterpret_cast<const __half2*>(&u00.x));
        sa = __hfma2(W01, *reinterpret_cast<const __half2*>(&u01.x), sa);
        sa = __hfma2(W10, *reinterpret_cast<const __half2*>(&u10.x), sa);
        sa = __hfma2(W11, *reinterpret_cast<const __half2*>(&u11.x), sa);

        __half2 sb = __hmul2(W00, *reinterpret_cast<const __half2*>(&u00.y));
        sb = __hfma2(W01, *reinterpret_cast<const __half2*>(&u01.y), sb);
        sb = __hfma2(W10, *reinterpret_cast<const __half2*>(&u10.y), sb);
        sb = __hfma2(W11, *reinterpret_cast<const __half2*>(&u11.y), sb);

        const float2 fa = __half22float2(sa);
        const float2 fb = __half22float2(sb);
        acc0 += fa.x;
        acc1 += fa.y;
        acc2 += fb.x;
        acc3 += fb.y;
    }

    acc0 += __shfl_xor_sync(0xffffffffu, acc0, 8);
    acc1 += __shfl_xor_sync(0xffffffffu, acc1, 8);
    acc2 += __shfl_xor_sync(0xffffffffu, acc2, 8);
    acc3 += __shfl_xor_sync(0xffffffffu, acc3, 8);
    acc0 += __shfl_xor_sync(0xffffffffu, acc0, 16);
    acc1 += __shfl_xor_sync(0xffffffffu, acc1, 16);
    acc2 += __shfl_xor_sync(0xffffffffu, acc2, 16);
    acc3 += __shfl_xor_sync(0xffffffffu, acc3, 16);

    if (lane < 8) {
        __half2 h0 = __floats2half2_rn(acc0, acc1);
        __half2 h1 = __floats2half2_rn(acc2, acc3);
        uint2 u;
        u.x = *reinterpret_cast<uint32_t*>(&h0);
        u.y = *reinterpret_cast<uint32_t*>(&h1);
        *reinterpret_cast<uint2*>(mid + (size_t)q * 256 + m * DH + c4 * 4) = u;
    }
}

// ---------------------------------------------------------------------------
// Launch
// ---------------------------------------------------------------------------
extern "C" void kernel_launch(void* const* d_in, const int* in_sizes, int n_in,
                              void* d_out, int out_size)
{
    const float* query  = (const float*)d_in[0];
    const float* refp   = (const float*)d_in[1];
    const float* inflat = (const float*)d_in[2];
    const unsigned char* pmask = (const unsigned char*)d_in[3];
    const float* W_off  = (const float*)d_in[4];
    const float* b_off  = (const float*)d_in[5];
    const float* W_attn = (const float*)d_in[6];
    const float* b_attn = (const float*)d_in[7];
    const float* W_val  = (const float*)d_in[8];
    const float* b_val  = (const float*)d_in[9];
    const float* W_out  = (const float*)d_in[10];
    const float* b_out  = (const float*)d_in[11];
    float* out = (float*)d_out;

    __half* pvalp; cudaGetSymbolAddress((void**)&pvalp, g_value_pad);
    float*  poff;  cudaGetSymbolAddress((void**)&poff,  g_off);
    float*  pattn; cudaGetSymbolAddress((void**)&pattn, g_attn);
    __half *q_h, *f_h, *w_h, *mid_h;
    cudaGetSymbolAddress((void**)&q_h,   g_q_h);
    cudaGetSymbolAddress((void**)&f_h,   g_f_h);
    cudaGetSymbolAddress((void**)&w_h,   g_w_h);
    cudaGetSymbolAddress((void**)&mid_h, g_mid_h);

    cudaFuncSetAttribute(proj_fused_kernel,
                         cudaFuncAttributeMaxDynamicSharedMemorySize, H_SMEM);
    cudaFuncSetAttribute(proj_out_kernel,
                         cudaFuncAttributeMaxDynamicSharedMemorySize, H_SMEM);

    const int Mr = LEN;
    const int mtiles = (Mr + 127) / 128;          // 156

    prep_all_kernel<<<(PREP_TOTAL + 255) / 256, 256>>>(
        W_val, W_off, W_attn, W_out, query, inflat, pvalp, w_h, q_h, f_h);

    const __half* wv  = w_h;
    const __half* woa = w_h + 256 * 256;
    const __half* wu  = w_h + 640 * 256;

    // 1. fused projections (persistent)
    proj_fused_kernel<<<PGRID, 256, H_SMEM>>>(
        f_h, q_h, wv, woa, b_val, b_off, b_attn, pmask, pvalp, poff, pattn,
        Mr, 5 * mtiles);
    // 2. sampler (padded value, phase-split)
    sample_kernel<<<Mr, 256>>>(pvalp, poff, pattn, refp, mid_h);
    // 3. output projection (persistent)
    proj_out_kernel<<<PGRID, 256, H_SMEM>>>(mid_h, wu, b_out, out, Mr, 2 * mtiles);
}

// round 12
// speedup vs baseline: 3.4643x; 1.0704x over previous
#include <cuda_runtime.h>
#include <cuda_fp16.h>
#include <mma.h>
#include <cstdint>
#include <math.h>

using namespace nvcuda;

#define LEN    19947
#define NHEAD  8
#define DH     32
#define NLVL   4
#define NPTS   4

#define PAD_ROWS 21393

// ---------------------------------------------------------------------------
// Scratch (device globals)
// ---------------------------------------------------------------------------
__device__ __half g_value_pad[PAD_ROWS * 256];
__device__ float  g_off [LEN * 256];
__device__ float  g_attn[LEN * 128];
__device__ __half g_mid_h[LEN * 256];
__device__ __half g_q_h[LEN * 256];
__device__ __half g_f_h[LEN * 256];
__device__ __half g_w_h[896 * 256];

__device__ __forceinline__ uint32_t smem_u32(const void* p) {
    uint32_t a;
    asm("{ .reg .u64 t; cvta.to.shared.u64 t, %1; cvt.u32.u64 %0, t; }" : "=r"(a) : "l"(p));
    return a;
}

__device__ __forceinline__ int pad_row(int gr) {
    int r, W, Wp, st;
    if (gr < 15000)      { r = gr;          W = 150; Wp = 153; st = 0; }
    else if (gr < 18750) { r = gr - 15000;  W = 75;  Wp = 78;  st = 15759; }
    else if (gr < 19700) { r = gr - 18750;  W = 38;  Wp = 41;  st = 19893; }
    else                 { r = gr - 19700;  W = 19;  Wp = 22;  st = 21041; }
    int y = r / W, x = r - y * W;
    return st + (y + 1) * Wp + (x + 1);
}

// ---------------------------------------------------------------------------
// Single fused prep kernel
// ---------------------------------------------------------------------------
#define PREP_A (PAD_ROWS * 32)
#define PREP_B (896 * 256)
#define PREP_C (2 * LEN * 64)
#define PREP_TOTAL (PREP_A + PREP_B + PREP_C)

__global__ void prep_all_kernel(const float* __restrict__ W_val,
                                const float* __restrict__ W_off,
                                const float* __restrict__ W_attn,
                                const float* __restrict__ W_out,
                                const float* __restrict__ query,
                                const float* __restrict__ inflat,
                                __half* __restrict__ vp,
                                __half* __restrict__ wh,
                                __half* __restrict__ qh,
                                __half* __restrict__ fh)
{
    int id = blockIdx.x * blockDim.x + threadIdx.x;
    if (id < PREP_A) {
        *reinterpret_cast<uint4*>(vp + (size_t)id * 8) = make_uint4(0, 0, 0, 0);
    } else if (id < PREP_A + PREP_B) {
        int e = id - PREP_A;
        int n = e >> 8;
        int k = e & 255;
        float x;
        if (n < 256)      x = W_val [k * 256 + n];
        else if (n < 512) x = W_off [k * 256 + (n - 256)];
        else if (n < 640) x = W_attn[k * 128 + (n - 512)];
        else              x = W_out [k * 256 + (n - 640)];
        wh[e] = __float2half_rn(x);
    } else if (id < PREP_TOTAL) {
        int e = id - PREP_A - PREP_B;
        const int total4 = LEN * 64;
        const float* src;
        __half* dst;
        int i4 = e;
        if (e < total4) { src = query;  dst = qh; }
        else            { src = inflat; dst = fh; i4 -= total4; }
        float4 v = *reinterpret_cast<const float4*>(src + (size_t)i4 * 4);
        __half h[4] = {__float2half_rn(v.x), __float2half_rn(v.y),
                       __float2half_rn(v.z), __float2half_rn(v.w)};
        *reinterpret_cast<uint2*>(dst + (size_t)i4 * 4) = *reinterpret_cast<uint2*>(h);
    }
}

// ---------------------------------------------------------------------------
// cp.async macros
// ---------------------------------------------------------------------------
#define CP16(dst, src, sz) \
    asm volatile("cp.async.cg.shared.global [%0], [%1], 16, %2;" \
                 :: "r"(dst), "l"(src), "r"(sz))
#define CP_COMMIT() asm volatile("cp.async.commit_group;")
#define CP_WAIT1()  asm volatile("cp.async.wait_group 1;")
#define CP_WAIT0()  asm volatile("cp.async.wait_group 0;")

// BK=64, 2-stage, 128 threads / 4 warps, warp tile 64x64
#define ASTR 72
#define BUFB (128 * ASTR * 2)
#define H_STAGEB (2 * BUFB)
#define CSTRIDE 132
#define H_SMEM (2 * H_STAGEB)          // 73728 (epilogue stage 67584 fits)
#define PGRID 296

// ---------------------------------------------------------------------------
// GEMM body: 4 warps, warp tile 64x64 (16 HMMA per 8 LDSM per K-step).
// ---------------------------------------------------------------------------
__device__ __forceinline__ void gemm_body(const __half* __restrict__ A,
                                          const __half* __restrict__ B,
                                          char* smem, int block_m, int block_n,
                                          int Mrows)
{
    const int tid  = threadIdx.x;
    const int warp = tid >> 5;
    const int wm   = warp & 1;     // 2 m-tiles of 64
    const int wn   = warp >> 1;    // 2 n-tiles of 64
    const uint32_t sb = smem_u32(smem);

    wmma::fragment<wmma::accumulator, 16, 16, 16, float> acc[4][4];
#pragma unroll
    for (int i = 0; i < 4; i++)
#pragma unroll
        for (int j = 0; j < 4; j++) wmma::fill_fragment(acc[i][j], 0.f);

    auto issue = [&](int chunk) {
        const int s = chunk & 1;
        const int k0 = chunk * 64;
        const uint32_t sbase = sb + s * H_STAGEB;
#pragma unroll
        for (int h = 0; h < 8; h++) {
            const int c   = tid + h * 128;       // 0..1023
            const int row = c >> 3;
            const int prt = (c & 7) * 8;
            const uint32_t so = (uint32_t)(row * ASTR + prt) * 2;
            const int ga  = block_m + row;
            const int asz = (ga < Mrows) ? 16 : 0;
            CP16(sbase + so,        A + (size_t)ga * 256 + k0 + prt, asz);
            CP16(sbase + BUFB + so, B + (size_t)(block_n + row) * 256 + k0 + prt, 16);
        }
    };

    issue(0);
    CP_COMMIT();

    for (int chunk = 0; chunk < 4; chunk++) {
        if (chunk < 3) { issue(chunk + 1); CP_COMMIT(); CP_WAIT1(); }
        else           { CP_WAIT0(); }
        __syncthreads();

        const int s = chunk & 1;
        const __half* ab = reinterpret_cast<const __half*>(smem + s * H_STAGEB);
        const __half* bb = ab + 128 * ASTR;

#pragma unroll
        for (int ks = 0; ks < 64; ks += 16) {
            wmma::fragment<wmma::matrix_a, 16, 16, 16, __half, wmma::row_major> fa[4];
            wmma::fragment<wmma::matrix_b, 16, 16, 16, __half, wmma::col_major> fb[4];
#pragma unroll
            for (int i = 0; i < 4; i++)
                wmma::load_matrix_sync(fa[i], ab + (wm * 64 + i * 16) * ASTR + ks, ASTR);
#pragma unroll
            for (int j = 0; j < 4; j++)
                wmma::load_matrix_sync(fb[j], bb + (wn * 64 + j * 16) * ASTR + ks, ASTR);
#pragma unroll
            for (int i = 0; i < 4; i++)
#pragma unroll
                for (int j = 0; j < 4; j++) wmma::mma_sync(acc[i][j], fa[i], fb[j], acc[i][j]);
        }
        __syncthreads();
    }

    float* stage = reinterpret_cast<float*>(smem);
#pragma unroll
    for (int i = 0; i < 4; i++)
#pragma unroll
        for (int j = 0; j < 4; j++)
            wmma::store_matrix_sync(stage + (wm * 64 + i * 16) * CSTRIDE + wn * 64 + j * 16,
                                    acc[i][j], CSTRIDE, wmma::mem_row_major);
    __syncthreads();
}

// ---------------------------------------------------------------------------
// Fused projection kernel (persistent): 780 tiles. 128 threads.
// ---------------------------------------------------------------------------
__global__ __launch_bounds__(128, 2)
void proj_fused_kernel(const __half* __restrict__ Af,
                       const __half* __restrict__ Aq,
                       const __half* __restrict__ Bv,
                       const __half* __restrict__ Boa,
                       const float* __restrict__ b_val,
                       const float* __restrict__ b_off,
                       const float* __restrict__ b_attn,
                       const unsigned char* __restrict__ mask,
                       __half* __restrict__ Cval,
                       float* __restrict__ Coff,
                       float* __restrict__ Cattn,
                       int Mrows, int ntiles)
{
    extern __shared__ char smem[];
    const int tid = threadIdx.x;

    for (int t = blockIdx.x; t < ntiles; t += PGRID) {
        const int bx = t % 5;
        const int mt = t / 5;
        const bool is_val = (bx < 2);
        const int block_m = mt * 128;
        const int block_n = (is_val ? bx : bx - 2) * 128;

        gemm_body(is_val ? Af : Aq, is_val ? Bv : Boa, smem, block_m, block_n, Mrows);

        const float* stage = reinterpret_cast<const float*>(smem);
        const int r   = tid;                  // 1 row per thread
        const int gr  = block_m + r;
        if (gr < Mrows) {
            const int prow = is_val ? pad_row(gr) : 0;
#pragma unroll
            for (int g = 0; g < 128; g += 16) {
                const int gcol = block_n + g;
                float v[16];
                if (is_val) {
#pragma unroll
                    for (int c = 0; c < 16; c++)
                        v[c] = stage[r * CSTRIDE + g + c] + __ldg(b_val + gcol + c);
                    float scale = (mask != nullptr && mask[gr]) ? 0.f : 1.f;
                    __half hbuf[16];
#pragma unroll
                    for (int c = 0; c < 16; c++) hbuf[c] = __float2half_rn(v[c] * scale);
#pragma unroll
                    for (int c = 0; c < 16; c += 8)
                        *reinterpret_cast<uint4*>(Cval + (size_t)prow * 256 + gcol + c) =
                            *reinterpret_cast<uint4*>(hbuf + c);
                } else if (gcol < 256) {
#pragma unroll
                    for (int c = 0; c < 16; c++)
                        v[c] = stage[r * CSTRIDE + g + c] + __ldg(b_off + gcol + c);
#pragma unroll
                    for (int c = 0; c < 16; c += 4) {
                        float4 o = make_float4(v[c], v[c+1], v[c+2], v[c+3]);
                        *reinterpret_cast<float4*>(Coff + (size_t)gr * 256 + gcol + c) = o;
                    }
                } else {
#pragma unroll
                    for (int c = 0; c < 16; c++)
                        v[c] = stage[r * CSTRIDE + g + c] + __ldg(b_attn + gcol - 256 + c);
                    float mx = -1e30f;
#pragma unroll
                    for (int c = 0; c < 16; c++) mx = fmaxf(mx, v[c]);
                    float sum = 0.f;
#pragma unroll
                    for (int c = 0; c < 16; c++) { v[c] = __expf(v[c] - mx); sum += v[c]; }
                    float inv = 1.f / sum;
#pragma unroll
                    for (int c = 0; c < 16; c += 4) {
                        float4 o = make_float4(v[c]*inv, v[c+1]*inv, v[c+2]*inv, v[c+3]*inv);
                        *reinterpret_cast<float4*>(Cattn + (size_t)gr * 128 + gcol - 256 + c) = o;
                    }
                }
            }
        }
        __syncthreads();
    }
}

// ---------------------------------------------------------------------------
// Output projection kernel (persistent): 312 tiles. 128 threads.
// ---------------------------------------------------------------------------
__global__ __launch_bounds__(128, 2)
void proj_out_kernel(const __half* __restrict__ A,
                     const __half* __restrict__ B,
                     const float* __restrict__ bias,
                     float* __restrict__ C,
                     int Mrows, int ntiles)
{
    extern __shared__ char smem[];
    const int tid = threadIdx.x;

    for (int t = blockIdx.x; t < ntiles; t += PGRID) {
        const int block_n = (t & 1) * 128;
        const int block_m = (t >> 1) * 128;

        gemm_body(A, B, smem, block_m, block_n, Mrows);

        const float* stage = reinterpret_cast<const float*>(smem);
        const int r  = tid;
        const int gr = block_m + r;
        if (gr < Mrows) {
#pragma unroll
            for (int g = 0; g < 128; g += 16) {
                const int gcol = block_n + g;
                float v[16];
#pragma unroll
                for (int c = 0; c < 16; c++)
                    v[c] = stage[r * CSTRIDE + g + c] + __ldg(bias + gcol + c);
#pragma unroll
                for (int c = 0; c < 16; c += 4) {
                    float4 o = make_float4(v[c], v[c+1], v[c+2], v[c+3]);
                    *reinterpret_cast<float4*>(C + (size_t)gr * 256 + gcol + c) = o;
                }
            }
        }
        __syncthreads();
    }
}

// ---------------------------------------------------------------------------
// Sampler v7 (unchanged from round 11)
// ---------------------------------------------------------------------------
__global__ __launch_bounds__(256)
void sample_kernel(const __half* __restrict__ value,
                   const float* __restrict__ off,
                   const float* __restrict__ aw,
                   const float* __restrict__ refp,
                   __half* __restrict__ mid)
{
    const int q    = blockIdx.x;
    const int m    = threadIdx.x >> 5;
    const int lane = threadIdx.x & 31;
    const int p2   = lane >> 3;
    const int c4   = lane & 7;

    const float offv = __ldg(off  + (size_t)q * 256 + m * 32 + lane);
    const float awv  = __ldg(aw   + (size_t)q * 128 + m * 16 + (lane & 15));
    const float rfv  = __ldg(refp + (size_t)q * 8 + (lane & 7));

    const int pt0 = lane & 15;
    const int l0  = pt0 >> 2;
    const float rx = __shfl_sync(0xffffffffu, rfv, l0 * 2 + 0);
    const float ry = __shfl_sync(0xffffffffu, rfv, l0 * 2 + 1);
    const float ox = __shfl_sync(0xffffffffu, offv, pt0 * 2 + 0);
    const float oy = __shfl_sync(0xffffffffu, offv, pt0 * 2 + 1);

    const float Wf = (l0 == 0) ? 150.f : (l0 == 1) ? 75.f : (l0 == 2) ? 38.f : 19.f;
    const float Hf = (l0 == 0) ? 100.f : (l0 == 1) ? 50.f : (l0 == 2) ? 25.f : 13.f;
    const int   Wp0 = (l0 == 0) ? 153 : (l0 == 1) ? 78 : (l0 == 2) ? 41 : 22;
    const int   SB0 = (l0 == 0) ? 154 : (l0 == 1) ? 15838 : (l0 == 2) ? 19935 : 21064;

    float x = fmaf(rx, Wf, ox) - 0.5f;
    float y = fmaf(ry, Hf, oy) - 0.5f;
    x = fminf(fmaxf(x, -1.f), Wf);
    y = fminf(fmaxf(y, -1.f), Hf);

    const float x0f = floorf(x), y0f = floorf(y);
    const float wx1 = x - x0f, wx0 = 1.f - wx1;
    const float wy1 = y - y0f, wy0 = 1.f - wy1;
    const int i00r = SB0 + (int)y0f * Wp0 + (int)x0f;

    __half2 pk01h = __floats2half2_rn(wx0 * wy0 * awv, wx1 * wy0 * awv);
    __half2 pk23h = __floats2half2_rn(wx0 * wy1 * awv, wx1 * wy1 * awv);
    const uint32_t pk01 = *reinterpret_cast<uint32_t*>(&pk01h);
    const uint32_t pk23 = *reinterpret_cast<uint32_t*>(&pk23h);

    const __half* vbase = value + m * DH + c4 * 4;
    float acc0 = 0.f, acc1 = 0.f, acc2 = 0.f, acc3 = 0.f;

    const int WPT[NLVL] = {153, 78, 41, 22};

#pragma unroll
    for (int l = 0; l < NLVL; l++) {
        const int src = l * 4 + p2;
        const int i00 = __shfl_sync(0xffffffffu, i00r, src);
        const uint32_t a01 = __shfl_sync(0xffffffffu, pk01, src);
        const uint32_t a23 = __shfl_sync(0xffffffffu, pk23, src);

        const __half2 h01 = *reinterpret_cast<const __half2*>(&a01);
        const __half2 h23 = *reinterpret_cast<const __half2*>(&a23);
        const __half2 W00 = __low2half2(h01),  W01 = __high2half2(h01);
        const __half2 W10 = __low2half2(h23),  W11 = __high2half2(h23);

        const int Wp = WPT[l];
        const __half* p00 = vbase + (size_t)i00 * 256;

        const uint2 u00 = __ldg(reinterpret_cast<const uint2*>(p00));
        const uint2 u01 = __ldg(reinterpret_cast<const uint2*>(p00 + 256));
        const uint2 u10 = __ldg(reinterpret_cast<const uint2*>(p00 + Wp * 256));
        const uint2 u11 = __ldg(reinterpret_cast<const uint2*>(p00 + (Wp + 1) * 256));

        __half2 sa = __hmul2(W00, *reinterpret_cast<const __half2*>(&u00.x));
        sa = __hfma2(W01, *reinterpret_cast<const __half2*>(&u01.x), sa);
        sa = __hfma2(W10, *reinterpret_cast<const __half2*>(&u10.x), sa);
        sa = __hfma2(W11, *reinterpret_cast<const __half2*>(&u11.x), sa);

        __half2 sb = __hmul2(W00, *reinterpret_cast<const __half2*>(&u00.y));
        sb = __hfma2(W01, *reinterpret_cast<const __half2*>(&u01.y), sb);
        sb = __hfma2(W10, *reinterpret_cast<const __half2*>(&u10.y), sb);
        sb = __hfma2(W11, *reinterpret_cast<const __half2*>(&u11.y), sb);

        const float2 fa = __half22float2(sa);
        const float2 fb = __half22float2(sb);
        acc0 += fa.x;
        acc1 += fa.y;
        acc2 += fb.x;
        acc3 += fb.y;
    }

    acc0 += __shfl_xor_sync(0xffffffffu, acc0, 8);
    acc1 += __shfl_xor_sync(0xffffffffu, acc1, 8);
    acc2 += __shfl_xor_sync(0xffffffffu, acc2, 8);
    acc3 += __shfl_xor_sync(0xffffffffu, acc3, 8);
    acc0 += __shfl_xor_sync(0xffffffffu, acc0, 16);
    acc1 += __shfl_xor_sync(0xffffffffu, acc1, 16);
    acc2 += __shfl_xor_sync(0xffffffffu, acc2, 16);
    acc3 += __shfl_xor_sync(0xffffffffu, acc3, 16);

    if (lane < 8) {
        __half2 h0 = __floats2half2_rn(acc0, acc1);
        __half2 h1 = __floats2half2_rn(acc2, acc3);
        uint2 u;
        u.x = *reinterpret_cast<uint32_t*>(&h0);
        u.y = *reinterpret_cast<uint32_t*>(&h1);
        *reinterpret_cast<uint2*>(mid + (size_t)q * 256 + m * DH + c4 * 4) = u;
    }
}

// ---------------------------------------------------------------------------
// Launch
// ---------------------------------------------------------------------------
extern "C" void kernel_launch(void* const* d_in, const int* in_sizes, int n_in,
                              void* d_out, int out_size)
{
    const float* query  = (const float*)d_in[0];
    const float* refp   = (const float*)d_in[1];
    const float* inflat = (const float*)d_in[2];
    const unsigned char* pmask = (const unsigned char*)d_in[3];
    const float* W_off  = (const float*)d_in[4];
    const float* b_off  = (const float*)d_in[5];
    const float* W_attn = (const float*)d_in[6];
    const float* b_attn = (const float*)d_in[7];
    const float* W_val  = (const float*)d_in[8];
    const float* b_val  = (const float*)d_in[9];
    const float* W_out  = (const float*)d_in[10];
    const float* b_out  = (const float*)d_in[11];
    float* out = (float*)d_out;

    __half* pvalp; cudaGetSymbolAddress((void**)&pvalp, g_value_pad);
    float*  poff;  cudaGetSymbolAddress((void**)&poff,  g_off);
    float*  pattn; cudaGetSymbolAddress((void**)&pattn, g_attn);
    __half *q_h, *f_h, *w_h, *mid_h;
    cudaGetSymbolAddress((void**)&q_h,   g_q_h);
    cudaGetSymbolAddress((void**)&f_h,   g_f_h);
    cudaGetSymbolAddress((void**)&w_h,   g_w_h);
    cudaGetSymbolAddress((void**)&mid_h, g_mid_h);

    cudaFuncSetAttribute(proj_fused_kernel,
                         cudaFuncAttributeMaxDynamicSharedMemorySize, H_SMEM);
    cudaFuncSetAttribute(proj_out_kernel,
                         cudaFuncAttributeMaxDynamicSharedMemorySize, H_SMEM);

    const int Mr = LEN;
    const int mtiles = (Mr + 127) / 128;          // 156

    prep_all_kernel<<<(PREP_TOTAL + 255) / 256, 256>>>(
        W_val, W_off, W_attn, W_out, query, inflat, pvalp, w_h, q_h, f_h);

    const __half* wv  = w_h;
    const __half* woa = w_h + 256 * 256;
    const __half* wu  = w_h + 640 * 256;

    // 1. fused projections (persistent, 128-thread CTAs)
    proj_fused_kernel<<<PGRID, 128, H_SMEM>>>(
        f_h, q_h, wv, woa, b_val, b_off, b_attn, pmask, pvalp, poff, pattn,
        Mr, 5 * mtiles);
    // 2. sampler
    sample_kernel<<<Mr, 256>>>(pvalp, poff, pattn, refp, mid_h);
    // 3. output projection (persistent, 128-thread CTAs)
    proj_out_kernel<<<PGRID, 128, H_SMEM>>>(mid_h, wu, b_out, out, Mr, 2 * mtiles);
}

// round 13
// speedup vs baseline: 3.4838x; 1.0056x over previous
#include <cuda_runtime.h>
#include <cuda_fp16.h>
#include <mma.h>
#include <cstdint>
#include <math.h>

using namespace nvcuda;

#define LEN    19947
#define NHEAD  8
#define DH     32
#define NLVL   4
#define NPTS   4

#define PAD_ROWS 21393

// ---------------------------------------------------------------------------
// Scratch (device globals)
// ---------------------------------------------------------------------------
__device__ __half g_value_pad[PAD_ROWS * 256];
__device__ float  g_off [LEN * 256];
__device__ float  g_attn[LEN * 128];
__device__ __half g_mid_h[LEN * 256];
__device__ __half g_q_h[LEN * 256];
__device__ __half g_f_h[LEN * 256];
__device__ __half g_w_h[896 * 256];
__device__ float  g_brep[2 * 16 * 256];   // [0]=b_out rep, [1]=b_off rep (16 rows)

__device__ __forceinline__ uint32_t smem_u32(const void* p) {
    uint32_t a;
    asm("{ .reg .u64 t; cvta.to.shared.u64 t, %1; cvt.u32.u64 %0, t; }" : "=r"(a) : "l"(p));
    return a;
}

__device__ __forceinline__ int pad_row(int gr) {
    int r, W, Wp, st;
    if (gr < 15000)      { r = gr;          W = 150; Wp = 153; st = 0; }
    else if (gr < 18750) { r = gr - 15000;  W = 75;  Wp = 78;  st = 15759; }
    else if (gr < 19700) { r = gr - 18750;  W = 38;  Wp = 41;  st = 19893; }
    else                 { r = gr - 19700;  W = 19;  Wp = 22;  st = 21041; }
    int y = r / W, x = r - y * W;
    return st + (y + 1) * Wp + (x + 1);
}

// ---------------------------------------------------------------------------
// Single fused prep kernel
// ---------------------------------------------------------------------------
#define PREP_A (PAD_ROWS * 32)
#define PREP_B (896 * 256)
#define PREP_C (2 * LEN * 64)
#define PREP_D (2 * 16 * 256)
#define PREP_TOTAL (PREP_A + PREP_B + PREP_C + PREP_D)

__global__ void prep_all_kernel(const float* __restrict__ W_val,
                                const float* __restrict__ W_off,
                                const float* __restrict__ W_attn,
                                const float* __restrict__ W_out,
                                const float* __restrict__ query,
                                const float* __restrict__ inflat,
                                const float* __restrict__ b_out,
                                const float* __restrict__ b_off,
                                __half* __restrict__ vp,
                                __half* __restrict__ wh,
                                __half* __restrict__ qh,
                                __half* __restrict__ fh,
                                float* __restrict__ brep)
{
    int id = blockIdx.x * blockDim.x + threadIdx.x;
    if (id < PREP_A) {
        *reinterpret_cast<uint4*>(vp + (size_t)id * 8) = make_uint4(0, 0, 0, 0);
    } else if (id < PREP_A + PREP_B) {
        int e = id - PREP_A;
        int n = e >> 8;
        int k = e & 255;
        float x;
        if (n < 256)      x = W_val [k * 256 + n];
        else if (n < 512) x = W_off [k * 256 + (n - 256)];
        else if (n < 640) x = W_attn[k * 128 + (n - 512)];
        else              x = W_out [k * 256 + (n - 640)];
        wh[e] = __float2half_rn(x);
    } else if (id < PREP_A + PREP_B + PREP_C) {
        int e = id - PREP_A - PREP_B;
        const int total4 = LEN * 64;
        const float* src;
        __half* dst;
        int i4 = e;
        if (e < total4) { src = query;  dst = qh; }
        else            { src = inflat; dst = fh; i4 -= total4; }
        float4 v = *reinterpret_cast<const float4*>(src + (size_t)i4 * 4);
        __half h[4] = {__float2half_rn(v.x), __float2half_rn(v.y),
                       __float2half_rn(v.z), __float2half_rn(v.w)};
        *reinterpret_cast<uint2*>(dst + (size_t)i4 * 4) = *reinterpret_cast<uint2*>(h);
    } else if (id < PREP_TOTAL) {
        int e = id - PREP_A - PREP_B - PREP_C;
        int half_sel = e >> 12;          // 0: b_out, 1: b_off
        int col = e & 255;
        brep[e] = half_sel ? b_off[col] : b_out[col];
    }
}

// ---------------------------------------------------------------------------
// cp.async macros
// ---------------------------------------------------------------------------
#define CP16(dst, src, sz) \
    asm volatile("cp.async.cg.shared.global [%0], [%1], 16, %2;" \
                 :: "r"(dst), "l"(src), "r"(sz))
#define CP_COMMIT() asm volatile("cp.async.commit_group;")
#define CP_WAIT1()  asm volatile("cp.async.wait_group 1;")
#define CP_WAIT0()  asm volatile("cp.async.wait_group 0;")

#define ASTR 72
#define BUFB (128 * ASTR * 2)
#define H_STAGEB (2 * BUFB)
#define CSTRIDE 132
#define H_SMEM (2 * H_STAGEB)
#define PGRID 296

// ---------------------------------------------------------------------------
// GEMM mainloop: 4 warps, warp tile 64x64, BK=64, 2-stage cp.async.
// Leaves accumulators in registers.
// ---------------------------------------------------------------------------
__device__ __forceinline__ void gemm_mainloop(
    const __half* __restrict__ A, const __half* __restrict__ B,
    char* smem, int block_m, int block_n, int Mrows,
    wmma::fragment<wmma::accumulator, 16, 16, 16, float> (&acc)[4][4])
{
    const int tid  = threadIdx.x;
    const int warp = tid >> 5;
    const int wm   = warp & 1;
    const int wn   = warp >> 1;
    const uint32_t sb = smem_u32(smem);

#pragma unroll
    for (int i = 0; i < 4; i++)
#pragma unroll
        for (int j = 0; j < 4; j++) wmma::fill_fragment(acc[i][j], 0.f);

    auto issue = [&](int chunk) {
        const int s = chunk & 1;
        const int k0 = chunk * 64;
        const uint32_t sbase = sb + s * H_STAGEB;
#pragma unroll
        for (int h = 0; h < 8; h++) {
            const int c   = tid + h * 128;
            const int row = c >> 3;
            const int prt = (c & 7) * 8;
            const uint32_t so = (uint32_t)(row * ASTR + prt) * 2;
            const int ga  = block_m + row;
            const int asz = (ga < Mrows) ? 16 : 0;
            CP16(sbase + so,        A + (size_t)ga * 256 + k0 + prt, asz);
            CP16(sbase + BUFB + so, B + (size_t)(block_n + row) * 256 + k0 + prt, 16);
        }
    };

    issue(0);
    CP_COMMIT();

    for (int chunk = 0; chunk < 4; chunk++) {
        if (chunk < 3) { issue(chunk + 1); CP_COMMIT(); CP_WAIT1(); }
        else           { CP_WAIT0(); }
        __syncthreads();

        const int s = chunk & 1;
        const __half* ab = reinterpret_cast<const __half*>(smem + s * H_STAGEB);
        const __half* bb = ab + 128 * ASTR;

#pragma unroll
        for (int ks = 0; ks < 64; ks += 16) {
            wmma::fragment<wmma::matrix_a, 16, 16, 16, __half, wmma::row_major> fa[4];
            wmma::fragment<wmma::matrix_b, 16, 16, 16, __half, wmma::col_major> fb[4];
#pragma unroll
            for (int i = 0; i < 4; i++)
                wmma::load_matrix_sync(fa[i], ab + (wm * 64 + i * 16) * ASTR + ks, ASTR);
#pragma unroll
            for (int j = 0; j < 4; j++)
                wmma::load_matrix_sync(fb[j], bb + (wn * 64 + j * 16) * ASTR + ks, ASTR);
#pragma unroll
            for (int i = 0; i < 4; i++)
#pragma unroll
                for (int j = 0; j < 4; j++) wmma::mma_sync(acc[i][j], fa[i], fb[j], acc[i][j]);
        }
        __syncthreads();
    }
}

// Stage accumulators into smem (fp32, CSTRIDE)
__device__ __forceinline__ void stage_acc(
    wmma::fragment<wmma::accumulator, 16, 16, 16, float> (&acc)[4][4], char* smem)
{
    const int warp = threadIdx.x >> 5;
    const int wm   = warp & 1;
    const int wn   = warp >> 1;
    float* stage = reinterpret_cast<float*>(smem);
#pragma unroll
    for (int i = 0; i < 4; i++)
#pragma unroll
        for (int j = 0; j < 4; j++)
            wmma::store_matrix_sync(stage + (wm * 64 + i * 16) * CSTRIDE + wn * 64 + j * 16,
                                    acc[i][j], CSTRIDE, wmma::mem_row_major);
    __syncthreads();
}

// Direct epilogue: add replicated bias fragment, store straight to gmem.
// Only safe when the full 128-row tile is in range.
__device__ __forceinline__ void direct_epilogue(
    wmma::fragment<wmma::accumulator, 16, 16, 16, float> (&acc)[4][4],
    const float* __restrict__ brep, float* __restrict__ C,
    int block_m, int block_n)
{
    const int warp = threadIdx.x >> 5;
    const int wm   = warp & 1;
    const int wn   = warp >> 1;
#pragma unroll
    for (int j = 0; j < 4; j++) {
        wmma::fragment<wmma::accumulator, 16, 16, 16, float> bf;
        wmma::load_matrix_sync(bf, brep + block_n + wn * 64 + j * 16, 256, wmma::mem_row_major);
#pragma unroll
        for (int i = 0; i < 4; i++) {
            wmma::fragment<wmma::accumulator, 16, 16, 16, float> t;
#pragma unroll
            for (int e = 0; e < t.num_elements; e++) t.x[e] = acc[i][j].x[e] + bf.x[e];
            wmma::store_matrix_sync(C + (size_t)(block_m + wm * 64 + i * 16) * 256
                                      + block_n + wn * 64 + j * 16,
                                    t, 256, wmma::mem_row_major);
        }
    }
}

// ---------------------------------------------------------------------------
// Fused projection kernel (persistent): 780 tiles. 128 threads.
// ---------------------------------------------------------------------------
__global__ __launch_bounds__(128, 2)
void proj_fused_kernel(const __half* __restrict__ Af,
                       const __half* __restrict__ Aq,
                       const __half* __restrict__ Bv,
                       const __half* __restrict__ Boa,
                       const float* __restrict__ b_val,
                       const float* __restrict__ b_attn,
                       const float* __restrict__ brep_off,
                       const unsigned char* __restrict__ mask,
                       __half* __restrict__ Cval,
                       float* __restrict__ Coff,
                       float* __restrict__ Cattn,
                       int Mrows, int ntiles)
{
    extern __shared__ char smem[];
    const int tid = threadIdx.x;

    for (int t = blockIdx.x; t < ntiles; t += PGRID) {
        const int bx = t % 5;
        const int mt = t / 5;
        const bool is_val = (bx < 2);
        const int block_m = mt * 128;
        const int block_n = (is_val ? bx : bx - 2) * 128;

        wmma::fragment<wmma::accumulator, 16, 16, 16, float> acc[4][4];
        gemm_mainloop(is_val ? Af : Aq, is_val ? Bv : Boa, smem, block_m, block_n, Mrows, acc);

        if (bx == 2 || bx == 3) {
            // pure offset tile -> direct store when fully in range
            if (block_m + 128 <= Mrows) {
                direct_epilogue(acc, brep_off, Coff, block_m, block_n);
                __syncthreads();
                continue;
            }
        }

        stage_acc(acc, smem);
        const float* stage = reinterpret_cast<const float*>(smem);
        const int r  = tid;
        const int gr = block_m + r;
        if (gr < Mrows) {
            if (is_val) {
                const int prow = pad_row(gr);
                const float scale = (mask != nullptr && mask[gr]) ? 0.f : 1.f;
#pragma unroll
                for (int g = 0; g < 128; g += 16) {
                    const int gcol = block_n + g;
                    __half hbuf[16];
#pragma unroll
                    for (int c = 0; c < 16; c++)
                        hbuf[c] = __float2half_rn((stage[r * CSTRIDE + g + c] + __ldg(b_val + gcol + c)) * scale);
#pragma unroll
                    for (int c = 0; c < 16; c += 8)
                        *reinterpret_cast<uint4*>(Cval + (size_t)prow * 256 + gcol + c) =
                            *reinterpret_cast<uint4*>(hbuf + c);
                }
            } else if (bx == 4) {
#pragma unroll
                for (int g = 0; g < 128; g += 16) {
                    const int gc = g;   // attn col base (block_n=256 is implicit)
                    float v[16];
#pragma unroll
                    for (int c = 0; c < 16; c++)
                        v[c] = stage[r * CSTRIDE + g + c] + __ldg(b_attn + gc + c);
                    float mx = -1e30f;
#pragma unroll
                    for (int c = 0; c < 16; c++) mx = fmaxf(mx, v[c]);
                    float sum = 0.f;
#pragma unroll
                    for (int c = 0; c < 16; c++) { v[c] = __expf(v[c] - mx); sum += v[c]; }
                    float inv = 1.f / sum;
#pragma unroll
                    for (int c = 0; c < 16; c += 4) {
                        float4 o = make_float4(v[c]*inv, v[c+1]*inv, v[c+2]*inv, v[c+3]*inv);
                        *reinterpret_cast<float4*>(Cattn + (size_t)gr * 128 + gc + c) = o;
                    }
                }
            } else {
                // boundary offset tile
#pragma unroll
                for (int g = 0; g < 128; g += 16) {
                    const int gcol = block_n + g;
                    float v[16];
#pragma unroll
                    for (int c = 0; c < 16; c++)
                        v[c] = stage[r * CSTRIDE + g + c] + __ldg(brep_off + gcol + c);
#pragma unroll
                    for (int c = 0; c < 16; c += 4) {
                        float4 o = make_float4(v[c], v[c+1], v[c+2], v[c+3]);
                        *reinterpret_cast<float4*>(Coff + (size_t)gr * 256 + gcol + c) = o;
                    }
                }
            }
        }
        __syncthreads();
    }
}

// ---------------------------------------------------------------------------
// Output projection kernel (persistent): 312 tiles. 128 threads.
// ---------------------------------------------------------------------------
__global__ __launch_bounds__(128, 2)
void proj_out_kernel(const __half* __restrict__ A,
                     const __half* __restrict__ B,
                     const float* __restrict__ brep_out,
                     float* __restrict__ C,
                     int Mrows, int ntiles)
{
    extern __shared__ char smem[];
    const int tid = threadIdx.x;

    for (int t = blockIdx.x; t < ntiles; t += PGRID) {
        const int block_n = (t & 1) * 128;
        const int block_m = (t >> 1) * 128;

        wmma::fragment<wmma::accumulator, 16, 16, 16, float> acc[4][4];
        gemm_mainloop(A, B, smem, block_m, block_n, Mrows, acc);

        if (block_m + 128 <= Mrows) {
            direct_epilogue(acc, brep_out, C, block_m, block_n);
        } else {
            stage_acc(acc, smem);
            const float* stage = reinterpret_cast<const float*>(smem);
            const int r  = tid;
            const int gr = block_m + r;
            if (gr < Mrows) {
#pragma unroll
                for (int g = 0; g < 128; g += 16) {
                    const int gcol = block_n + g;
                    float v[16];
#pragma unroll
                    for (int c = 0; c < 16; c++)
                        v[c] = stage[r * CSTRIDE + g + c] + __ldg(brep_out + gcol + c);
#pragma unroll
                    for (int c = 0; c < 16; c += 4) {
                        float4 o = make_float4(v[c], v[c+1], v[c+2], v[c+3]);
                        *reinterpret_cast<float4*>(C + (size_t)gr * 256 + gcol + c) = o;
                    }
                }
            }
        }
        __syncthreads();
    }
}

// ---------------------------------------------------------------------------
// Sampler v8: lane = (p3 in [0,8), c8 in [0,4)). 8 points in flight,
// 2 level-pair iterations, LDG.128 gathers (16B = 8 channels per lane).
// ---------------------------------------------------------------------------
__global__ __launch_bounds__(256)
void sample_kernel(const __half* __restrict__ value,
                   const float* __restrict__ off,
                   const float* __restrict__ aw,
                   const float* __restrict__ refp,
                   __half* __restrict__ mid)
{
    const int q    = blockIdx.x;
    const int m    = threadIdx.x >> 5;
    const int lane = threadIdx.x & 31;
    const int p3   = lane >> 2;     // point-in-flight (0..7)
    const int c8   = lane & 3;      // 16B channel quad

    const float offv = __ldg(off  + (size_t)q * 256 + m * 32 + lane);
    const float awv  = __ldg(aw   + (size_t)q * 128 + m * 16 + (lane & 15));
    const float rfv  = __ldg(refp + (size_t)q * 8 + (lane & 7));

    // ---- phase 1: per-lane point pt0 = lane & 15 ----
    const int pt0 = lane & 15;
    const int l0  = pt0 >> 2;
    const float rx = __shfl_sync(0xffffffffu, rfv, l0 * 2 + 0);
    const float ry = __shfl_sync(0xffffffffu, rfv, l0 * 2 + 1);
    const float ox = __shfl_sync(0xffffffffu, offv, pt0 * 2 + 0);
    const float oy = __shfl_sync(0xffffffffu, offv, pt0 * 2 + 1);

    const float Wf = (l0 == 0) ? 150.f : (l0 == 1) ? 75.f : (l0 == 2) ? 38.f : 19.f;
    const float Hf = (l0 == 0) ? 100.f : (l0 == 1) ? 50.f : (l0 == 2) ? 25.f : 13.f;
    const int   Wp0 = (l0 == 0) ? 153 : (l0 == 1) ? 78 : (l0 == 2) ? 41 : 22;
    const int   SB0 = (l0 == 0) ? 154 : (l0 == 1) ? 15838 : (l0 == 2) ? 19935 : 21064;

    float x = fmaf(rx, Wf, ox) - 0.5f;
    float y = fmaf(ry, Hf, oy) - 0.5f;
    x = fminf(fmaxf(x, -1.f), Wf);
    y = fminf(fmaxf(y, -1.f), Hf);

    const float x0f = floorf(x), y0f = floorf(y);
    const float wx1 = x - x0f, wx0 = 1.f - wx1;
    const float wy1 = y - y0f, wy0 = 1.f - wy1;
    const int i00r = SB0 + (int)y0f * Wp0 + (int)x0f;

    __half2 pk01h = __floats2half2_rn(wx0 * wy0 * awv, wx1 * wy0 * awv);
    __half2 pk23h = __floats2half2_rn(wx0 * wy1 * awv, wx1 * wy1 * awv);
    const uint32_t pk01 = *reinterpret_cast<uint32_t*>(&pk01h);
    const uint32_t pk23 = *reinterpret_cast<uint32_t*>(&pk23h);

    const __half* vbase = value + m * DH + c8 * 8;
    float acc[8];
#pragma unroll
    for (int e = 0; e < 8; e++) acc[e] = 0.f;

    // ---- phase 2: 2 iterations, 8 points each ----
#pragma unroll
    for (int it = 0; it < 2; it++) {
        const int pt = it * 8 + p3;
        const int i00 = __shfl_sync(0xffffffffu, i00r, pt);
        const uint32_t a01 = __shfl_sync(0xffffffffu, pk01, pt);
        const uint32_t a23 = __shfl_sync(0xffffffffu, pk23, pt);

        const __half2 h01 = *reinterpret_cast<const __half2*>(&a01);
        const __half2 h23 = *reinterpret_cast<const __half2*>(&a23);
        const __half2 W00 = __low2half2(h01),  W01 = __high2half2(h01);
        const __half2 W10 = __low2half2(h23),  W11 = __high2half2(h23);

        const int Wp = (it == 0) ? ((p3 < 4) ? 153 : 78) : ((p3 < 4) ? 41 : 22);
        const __half* p00 = vbase + (size_t)i00 * 256;

        const uint4 u00 = __ldg(reinterpret_cast<const uint4*>(p00));
        const uint4 u01 = __ldg(reinterpret_cast<const uint4*>(p00 + 256));
        const uint4 u10 = __ldg(reinterpret_cast<const uint4*>(p00 + Wp * 256));
        const uint4 u11 = __ldg(reinterpret_cast<const uint4*>(p00 + (Wp + 1) * 256));

        const uint32_t c00[4] = {u00.x, u00.y, u00.z, u00.w};
        const uint32_t c01[4] = {u01.x, u01.y, u01.z, u01.w};
        const uint32_t c10[4] = {u10.x, u10.y, u10.z, u10.w};
        const uint32_t c11[4] = {u11.x, u11.y, u11.z, u11.w};

#pragma unroll
        for (int j = 0; j < 4; j++) {
            __half2 s = __hmul2(W00, *reinterpret_cast<const __half2*>(&c00[j]));
            s = __hfma2(W01, *reinterpret_cast<const __half2*>(&c01[j]), s);
            s = __hfma2(W10, *reinterpret_cast<const __half2*>(&c10[j]), s);
            s = __hfma2(W11, *reinterpret_cast<const __half2*>(&c11[j]), s);
            const float2 f = __half22float2(s);
            acc[j * 2 + 0] += f.x;
            acc[j * 2 + 1] += f.y;
        }
    }

    // reduce across p3 (lane bits 2,3,4)
#pragma unroll
    for (int d = 4; d <= 16; d <<= 1)
#pragma unroll
        for (int e = 0; e < 8; e++)
            acc[e] += __shfl_xor_sync(0xffffffffu, acc[e], d);

    if (p3 == 0) {
        __half2 h[4];
#pragma unroll
        for (int j = 0; j < 4; j++) h[j] = __floats2half2_rn(acc[j * 2], acc[j * 2 + 1]);
        uint4 u;
        u.x = *reinterpret_cast<uint32_t*>(&h[0]);
        u.y = *reinterpret_cast<uint32_t*>(&h[1]);
        u.z = *reinterpret_cast<uint32_t*>(&h[2]);
        u.w = *reinterpret_cast<uint32_t*>(&h[3]);
        *reinterpret_cast<uint4*>(mid + (size_t)q * 256 + m * DH + c8 * 8) = u;
    }
}

// ---------------------------------------------------------------------------
// Launch
// ---------------------------------------------------------------------------
extern "C" void kernel_launch(void* const* d_in, const int* in_sizes, int n_in,
                              void* d_out, int out_size)
{
    const float* query  = (const float*)d_in[0];
    const float* refp   = (const float*)d_in[1];
    const float* inflat = (const float*)d_in[2];
    const unsigned char* pmask = (const unsigned char*)d_in[3];
    const float* W_off  = (const float*)d_in[4];
    const float* b_off  = (const float*)d_in[5];
    const float* W_attn = (const float*)d_in[6];
    const float* b_attn = (const float*)d_in[7];
    const float* W_val  = (const float*)d_in[8];
    const float* b_val  = (const float*)d_in[9];
    const float* W_out  = (const float*)d_in[10];
    const float* b_out  = (const float*)d_in[11];
    float* out = (float*)d_out;

    __half* pvalp; cudaGetSymbolAddress((void**)&pvalp, g_value_pad);
    float*  poff;  cudaGetSymbolAddress((void**)&poff,  g_off);
    float*  pattn; cudaGetSymbolAddress((void**)&pattn, g_attn);
    float*  brep;  cudaGetSymbolAddress((void**)&brep,  g_brep);
    __half *q_h, *f_h, *w_h, *mid_h;
    cudaGetSymbolAddress((void**)&q_h,   g_q_h);
    cudaGetSymbolAddress((void**)&f_h,   g_f_h);
    cudaGetSymbolAddress((void**)&w_h,   g_w_h);
    cudaGetSymbolAddress((void**)&mid_h, g_mid_h);

    cudaFuncSetAttribute(proj_fused_kernel,
                         cudaFuncAttributeMaxDynamicSharedMemorySize, H_SMEM);
    cudaFuncSetAttribute(proj_out_kernel,
                         cudaFuncAttributeMaxDynamicSharedMemorySize, H_SMEM);

    const int Mr = LEN;
    const int mtiles = (Mr + 127) / 128;          // 156

    prep_all_kernel<<<(PREP_TOTAL + 255) / 256, 256>>>(
        W_val, W_off, W_attn, W_out, query, inflat, b_out, b_off,
        pvalp, w_h, q_h, f_h, brep);

    const __half* wv  = w_h;
    const __half* woa = w_h + 256 * 256;
    const __half* wu  = w_h + 640 * 256;
    const float* brep_out = brep;
    const float* brep_off = brep + 16 * 256;

    // 1. fused projections (persistent)
    proj_fused_kernel<<<PGRID, 128, H_SMEM>>>(
        f_h, q_h, wv, woa, b_val, b_attn, brep_off, pmask, pvalp, poff, pattn,
        Mr, 5 * mtiles);
    // 2. sampler (LDG.128)
    sample_kernel<<<Mr, 256>>>(pvalp, poff, pattn, refp, mid_h);
    // 3. output projection (persistent, direct epilogue)
    proj_out_kernel<<<PGRID, 128, H_SMEM>>>(mid_h, wu, brep_out, out, Mr, 2 * mtiles);
}

// round 14
// speedup vs baseline: 3.7131x; 1.0658x over previous
#include <cuda_runtime.h>
#include <cuda_fp16.h>
#include <mma.h>
#include <cstdint>
#include <math.h>

using namespace nvcuda;

#define LEN    19947
#define NHEAD  8
#define DH     32
#define NLVL   4
#define NPTS   4

#define PAD_ROWS 21393

// ---------------------------------------------------------------------------
// Scratch (device globals)
// ---------------------------------------------------------------------------
__device__ __half g_value_pad[PAD_ROWS * 256];
__device__ float  g_off [LEN * 256];
__device__ float  g_attn[LEN * 128];
__device__ __half g_mid_h[LEN * 256];
__device__ __half g_q_h[LEN * 256];
__device__ __half g_f_h[LEN * 256];
__device__ __half g_w_h[896 * 256];
__device__ float  g_brep[2 * 16 * 256];   // [0]=b_out rep, [1]=b_off rep (16 rows)

__device__ __forceinline__ uint32_t smem_u32(const void* p) {
    uint32_t a;
    asm("{ .reg .u64 t; cvta.to.shared.u64 t, %1; cvt.u32.u64 %0, t; }" : "=r"(a) : "l"(p));
    return a;
}

__device__ __forceinline__ int pad_row(int gr) {
    int r, W, Wp, st;
    if (gr < 15000)      { r = gr;          W = 150; Wp = 153; st = 0; }
    else if (gr < 18750) { r = gr - 15000;  W = 75;  Wp = 78;  st = 15759; }
    else if (gr < 19700) { r = gr - 18750;  W = 38;  Wp = 41;  st = 19893; }
    else                 { r = gr - 19700;  W = 19;  Wp = 22;  st = 21041; }
    int y = r / W, x = r - y * W;
    return st + (y + 1) * Wp + (x + 1);
}

// ---------------------------------------------------------------------------
// Single fused prep kernel
// ---------------------------------------------------------------------------
#define PREP_A (PAD_ROWS * 32)
#define PREP_B (896 * 256)
#define PREP_C (2 * LEN * 64)
#define PREP_D (2 * 16 * 256)
#define PREP_TOTAL (PREP_A + PREP_B + PREP_C + PREP_D)

__global__ void prep_all_kernel(const float* __restrict__ W_val,
                                const float* __restrict__ W_off,
                                const float* __restrict__ W_attn,
                                const float* __restrict__ W_out,
                                const float* __restrict__ query,
                                const float* __restrict__ inflat,
                                const float* __restrict__ b_out,
                                const float* __restrict__ b_off,
                                __half* __restrict__ vp,
                                __half* __restrict__ wh,
                                __half* __restrict__ qh,
                                __half* __restrict__ fh,
                                float* __restrict__ brep)
{
    int id = blockIdx.x * blockDim.x + threadIdx.x;
    if (id < PREP_A) {
        *reinterpret_cast<uint4*>(vp + (size_t)id * 8) = make_uint4(0, 0, 0, 0);
    } else if (id < PREP_A + PREP_B) {
        int e = id - PREP_A;
        int n = e >> 8;
        int k = e & 255;
        float x;
        if (n < 256)      x = W_val [k * 256 + n];
        else if (n < 512) x = W_off [k * 256 + (n - 256)];
        else if (n < 640) x = W_attn[k * 128 + (n - 512)];
        else              x = W_out [k * 256 + (n - 640)];
        wh[e] = __float2half_rn(x);
    } else if (id < PREP_A + PREP_B + PREP_C) {
        int e = id - PREP_A - PREP_B;
        const int total4 = LEN * 64;
        const float* src;
        __half* dst;
        int i4 = e;
        if (e < total4) { src = query;  dst = qh; }
        else            { src = inflat; dst = fh; i4 -= total4; }
        float4 v = *reinterpret_cast<const float4*>(src + (size_t)i4 * 4);
        __half h[4] = {__float2half_rn(v.x), __float2half_rn(v.y),
                       __float2half_rn(v.z), __float2half_rn(v.w)};
        *reinterpret_cast<uint2*>(dst + (size_t)i4 * 4) = *reinterpret_cast<uint2*>(h);
    } else if (id < PREP_TOTAL) {
        int e = id - PREP_A - PREP_B - PREP_C;
        int half_sel = e >> 12;          // 0: b_out, 1: b_off
        int col = e & 255;
        brep[e] = half_sel ? b_off[col] : b_out[col];
    }
}

// ---------------------------------------------------------------------------
// cp.async macros
// ---------------------------------------------------------------------------
#define CP16(dst, src, sz) \
    asm volatile("cp.async.cg.shared.global [%0], [%1], 16, %2;" \
                 :: "r"(dst), "l"(src), "r"(sz))
#define CP_COMMIT() asm volatile("cp.async.commit_group;")
#define CP_WAIT1()  asm volatile("cp.async.wait_group 1;")
#define CP_WAIT0()  asm volatile("cp.async.wait_group 0;")

#define ASTR 72
#define BUFB (128 * ASTR * 2)
#define H_STAGEB (2 * BUFB)
#define CSTRIDE 132
#define H_SMEM (2 * H_STAGEB)
#define PGRID 296

// ---------------------------------------------------------------------------
// GEMM mainloop: 4 warps, warp tile 64x64, BK=64, 2-stage cp.async.
// ---------------------------------------------------------------------------
__device__ __forceinline__ void gemm_mainloop(
    const __half* __restrict__ A, const __half* __restrict__ B,
    char* smem, int block_m, int block_n, int Mrows,
    wmma::fragment<wmma::accumulator, 16, 16, 16, float> (&acc)[4][4])
{
    const int tid  = threadIdx.x;
    const int warp = tid >> 5;
    const int wm   = warp & 1;
    const int wn   = warp >> 1;
    const uint32_t sb = smem_u32(smem);

#pragma unroll
    for (int i = 0; i < 4; i++)
#pragma unroll
        for (int j = 0; j < 4; j++) wmma::fill_fragment(acc[i][j], 0.f);

    auto issue = [&](int chunk) {
        const int s = chunk & 1;
        const int k0 = chunk * 64;
        const uint32_t sbase = sb + s * H_STAGEB;
#pragma unroll
        for (int h = 0; h < 8; h++) {
            const int c   = tid + h * 128;
            const int row = c >> 3;
            const int prt = (c & 7) * 8;
            const uint32_t so = (uint32_t)(row * ASTR + prt) * 2;
            const int ga  = block_m + row;
            const int asz = (ga < Mrows) ? 16 : 0;
            CP16(sbase + so,        A + (size_t)ga * 256 + k0 + prt, asz);
            CP16(sbase + BUFB + so, B + (size_t)(block_n + row) * 256 + k0 + prt, 16);
        }
    };

    issue(0);
    CP_COMMIT();

    for (int chunk = 0; chunk < 4; chunk++) {
        if (chunk < 3) { issue(chunk + 1); CP_COMMIT(); CP_WAIT1(); }
        else           { CP_WAIT0(); }
        __syncthreads();

        const int s = chunk & 1;
        const __half* ab = reinterpret_cast<const __half*>(smem + s * H_STAGEB);
        const __half* bb = ab + 128 * ASTR;

#pragma unroll
        for (int ks = 0; ks < 64; ks += 16) {
            wmma::fragment<wmma::matrix_a, 16, 16, 16, __half, wmma::row_major> fa[4];
            wmma::fragment<wmma::matrix_b, 16, 16, 16, __half, wmma::col_major> fb[4];
#pragma unroll
            for (int i = 0; i < 4; i++)
                wmma::load_matrix_sync(fa[i], ab + (wm * 64 + i * 16) * ASTR + ks, ASTR);
#pragma unroll
            for (int j = 0; j < 4; j++)
                wmma::load_matrix_sync(fb[j], bb + (wn * 64 + j * 16) * ASTR + ks, ASTR);
#pragma unroll
            for (int i = 0; i < 4; i++)
#pragma unroll
                for (int j = 0; j < 4; j++) wmma::mma_sync(acc[i][j], fa[i], fb[j], acc[i][j]);
        }
        __syncthreads();
    }
}

__device__ __forceinline__ void stage_acc(
    wmma::fragment<wmma::accumulator, 16, 16, 16, float> (&acc)[4][4], char* smem)
{
    const int warp = threadIdx.x >> 5;
    const int wm   = warp & 1;
    const int wn   = warp >> 1;
    float* stage = reinterpret_cast<float*>(smem);
#pragma unroll
    for (int i = 0; i < 4; i++)
#pragma unroll
        for (int j = 0; j < 4; j++)
            wmma::store_matrix_sync(stage + (wm * 64 + i * 16) * CSTRIDE + wn * 64 + j * 16,
                                    acc[i][j], CSTRIDE, wmma::mem_row_major);
    __syncthreads();
}

__device__ __forceinline__ void direct_epilogue(
    wmma::fragment<wmma::accumulator, 16, 16, 16, float> (&acc)[4][4],
    const float* __restrict__ brep, float* __restrict__ C,
    int block_m, int block_n)
{
    const int warp = threadIdx.x >> 5;
    const int wm   = warp & 1;
    const int wn   = warp >> 1;
#pragma unroll
    for (int j = 0; j < 4; j++) {
        wmma::fragment<wmma::accumulator, 16, 16, 16, float> bf;
        wmma::load_matrix_sync(bf, brep + block_n + wn * 64 + j * 16, 256, wmma::mem_row_major);
#pragma unroll
        for (int i = 0; i < 4; i++) {
            wmma::fragment<wmma::accumulator, 16, 16, 16, float> t;
#pragma unroll
            for (int e = 0; e < t.num_elements; e++) t.x[e] = acc[i][j].x[e] + bf.x[e];
            wmma::store_matrix_sync(C + (size_t)(block_m + wm * 64 + i * 16) * 256
                                      + block_n + wn * 64 + j * 16,
                                    t, 256, wmma::mem_row_major);
        }
    }
}

// ---------------------------------------------------------------------------
// Fused projection kernel (persistent): 780 tiles. 128 threads.
// ---------------------------------------------------------------------------
__global__ __launch_bounds__(128, 2)
void proj_fused_kernel(const __half* __restrict__ Af,
                       const __half* __restrict__ Aq,
                       const __half* __restrict__ Bv,
                       const __half* __restrict__ Boa,
                       const float* __restrict__ b_val,
                       const float* __restrict__ b_attn,
                       const float* __restrict__ brep_off,
                       const unsigned char* __restrict__ mask,
                       __half* __restrict__ Cval,
                       float* __restrict__ Coff,
                       float* __restrict__ Cattn,
                       int Mrows, int ntiles)
{
    extern __shared__ char smem[];
    const int tid = threadIdx.x;

    for (int t = blockIdx.x; t < ntiles; t += PGRID) {
        const int bx = t % 5;
        const int mt = t / 5;
        const bool is_val = (bx < 2);
        const int block_m = mt * 128;
        const int block_n = (is_val ? bx : bx - 2) * 128;

        wmma::fragment<wmma::accumulator, 16, 16, 16, float> acc[4][4];
        gemm_mainloop(is_val ? Af : Aq, is_val ? Bv : Boa, smem, block_m, block_n, Mrows, acc);

        if (bx == 2 || bx == 3) {
            if (block_m + 128 <= Mrows) {
                direct_epilogue(acc, brep_off, Coff, block_m, block_n);
                __syncthreads();
                continue;
            }
        }

        stage_acc(acc, smem);
        const float* stage = reinterpret_cast<const float*>(smem);
        const int r  = tid;
        const int gr = block_m + r;
        if (gr < Mrows) {
            if (is_val) {
                const int prow = pad_row(gr);
                const float scale = (mask != nullptr && mask[gr]) ? 0.f : 1.f;
#pragma unroll
                for (int g = 0; g < 128; g += 16) {
                    const int gcol = block_n + g;
                    __half hbuf[16];
#pragma unroll
                    for (int c = 0; c < 16; c++)
                        hbuf[c] = __float2half_rn((stage[r * CSTRIDE + g + c] + __ldg(b_val + gcol + c)) * scale);
#pragma unroll
                    for (int c = 0; c < 16; c += 8)
                        *reinterpret_cast<uint4*>(Cval + (size_t)prow * 256 + gcol + c) =
                            *reinterpret_cast<uint4*>(hbuf + c);
                }
            } else if (bx == 4) {
#pragma unroll
                for (int g = 0; g < 128; g += 16) {
                    const int gc = g;
                    float v[16];
#pragma unroll
                    for (int c = 0; c < 16; c++)
                        v[c] = stage[r * CSTRIDE + g + c] + __ldg(b_attn + gc + c);
                    float mx = -1e30f;
#pragma unroll
                    for (int c = 0; c < 16; c++) mx = fmaxf(mx, v[c]);
                    float sum = 0.f;
#pragma unroll
                    for (int c = 0; c < 16; c++) { v[c] = __expf(v[c] - mx); sum += v[c]; }
                    float inv = 1.f / sum;
#pragma unroll
                    for (int c = 0; c < 16; c += 4) {
                        float4 o = make_float4(v[c]*inv, v[c+1]*inv, v[c+2]*inv, v[c+3]*inv);
                        *reinterpret_cast<float4*>(Cattn + (size_t)gr * 128 + gc + c) = o;
                    }
                }
            } else {
#pragma unroll
                for (int g = 0; g < 128; g += 16) {
                    const int gcol = block_n + g;
                    float v[16];
#pragma unroll
                    for (int c = 0; c < 16; c++)
                        v[c] = stage[r * CSTRIDE + g + c] + __ldg(brep_off + gcol + c);
#pragma unroll
                    for (int c = 0; c < 16; c += 4) {
                        float4 o = make_float4(v[c], v[c+1], v[c+2], v[c+3]);
                        *reinterpret_cast<float4*>(Coff + (size_t)gr * 256 + gcol + c) = o;
                    }
                }
            }
        }
        __syncthreads();
    }
}

// ---------------------------------------------------------------------------
// Output projection kernel (persistent): 312 tiles. 128 threads.
// ---------------------------------------------------------------------------
__global__ __launch_bounds__(128, 2)
void proj_out_kernel(const __half* __restrict__ A,
                     const __half* __restrict__ B,
                     const float* __restrict__ brep_out,
                     float* __restrict__ C,
                     int Mrows, int ntiles)
{
    extern __shared__ char smem[];
    const int tid = threadIdx.x;

    for (int t = blockIdx.x; t < ntiles; t += PGRID) {
        const int block_n = (t & 1) * 128;
        const int block_m = (t >> 1) * 128;

        wmma::fragment<wmma::accumulator, 16, 16, 16, float> acc[4][4];
        gemm_mainloop(A, B, smem, block_m, block_n, Mrows, acc);

        if (block_m + 128 <= Mrows) {
            direct_epilogue(acc, brep_out, C, block_m, block_n);
        } else {
            stage_acc(acc, smem);
            const float* stage = reinterpret_cast<const float*>(smem);
            const int r  = tid;
            const int gr = block_m + r;
            if (gr < Mrows) {
#pragma unroll
                for (int g = 0; g < 128; g += 16) {
                    const int gcol = block_n + g;
                    float v[16];
#pragma unroll
                    for (int c = 0; c < 16; c++)
                        v[c] = stage[r * CSTRIDE + g + c] + __ldg(brep_out + gcol + c);
#pragma unroll
                    for (int c = 0; c < 16; c += 4) {
                        float4 o = make_float4(v[c], v[c+1], v[c+2], v[c+3]);
                        *reinterpret_cast<float4*>(C + (size_t)gr * 256 + gcol + c) = o;
                    }
                }
            }
        }
        __syncthreads();
    }
}

// ---------------------------------------------------------------------------
// Sampler v7 (proven best): phase-split, lane = (p2, c4), LDG.64 gathers,
// 4 accumulators, 2-hop reduce.
// ---------------------------------------------------------------------------
__global__ __launch_bounds__(256)
void sample_kernel(const __half* __restrict__ value,
                   const float* __restrict__ off,
                   const float* __restrict__ aw,
                   const float* __restrict__ refp,
                   __half* __restrict__ mid)
{
    const int q    = blockIdx.x;
    const int m    = threadIdx.x >> 5;
    const int lane = threadIdx.x & 31;
    const int p2   = lane >> 3;
    const int c4   = lane & 7;

    const float offv = __ldg(off  + (size_t)q * 256 + m * 32 + lane);
    const float awv  = __ldg(aw   + (size_t)q * 128 + m * 16 + (lane & 15));
    const float rfv  = __ldg(refp + (size_t)q * 8 + (lane & 7));

    const int pt0 = lane & 15;
    const int l0  = pt0 >> 2;
    const float rx = __shfl_sync(0xffffffffu, rfv, l0 * 2 + 0);
    const float ry = __shfl_sync(0xffffffffu, rfv, l0 * 2 + 1);
    const float ox = __shfl_sync(0xffffffffu, offv, pt0 * 2 + 0);
    const float oy = __shfl_sync(0xffffffffu, offv, pt0 * 2 + 1);

    const float Wf = (l0 == 0) ? 150.f : (l0 == 1) ? 75.f : (l0 == 2) ? 38.f : 19.f;
    const float Hf = (l0 == 0) ? 100.f : (l0 == 1) ? 50.f : (l0 == 2) ? 25.f : 13.f;
    const int   Wp0 = (l0 == 0) ? 153 : (l0 == 1) ? 78 : (l0 == 2) ? 41 : 22;
    const int   SB0 = (l0 == 0) ? 154 : (l0 == 1) ? 15838 : (l0 == 2) ? 19935 : 21064;

    float x = fmaf(rx, Wf, ox) - 0.5f;
    float y = fmaf(ry, Hf, oy) - 0.5f;
    x = fminf(fmaxf(x, -1.f), Wf);
    y = fminf(fmaxf(y, -1.f), Hf);

    const float x0f = floorf(x), y0f = floorf(y);
    const float wx1 = x - x0f, wx0 = 1.f - wx1;
    const float wy1 = y - y0f, wy0 = 1.f - wy1;
    const int i00r = SB0 + (int)y0f * Wp0 + (int)x0f;

    __half2 pk01h = __floats2half2_rn(wx0 * wy0 * awv, wx1 * wy0 * awv);
    __half2 pk23h = __floats2half2_rn(wx0 * wy1 * awv, wx1 * wy1 * awv);
    const uint32_t pk01 = *reinterpret_cast<uint32_t*>(&pk01h);
    const uint32_t pk23 = *reinterpret_cast<uint32_t*>(&pk23h);

    const __half* vbase = value + m * DH + c4 * 4;
    float acc0 = 0.f, acc1 = 0.f, acc2 = 0.f, acc3 = 0.f;

    const int WPT[NLVL] = {153, 78, 41, 22};

#pragma unroll
    for (int l = 0; l < NLVL; l++) {
        const int src = l * 4 + p2;
        const int i00 = __shfl_sync(0xffffffffu, i00r, src);
        const uint32_t a01 = __shfl_sync(0xffffffffu, pk01, src);
        const uint32_t a23 = __shfl_sync(0xffffffffu, pk23, src);

        const __half2 h01 = *reinterpret_cast<const __half2*>(&a01);
        const __half2 h23 = *reinterpret_cast<const __half2*>(&a23);
        const __half2 W00 = __low2half2(h01),  W01 = __high2half2(h01);
        const __half2 W10 = __low2half2(h23),  W11 = __high2half2(h23);

        const int Wp = WPT[l];
        const __half* p00 = vbase + (size_t)i00 * 256;

        const uint2 u00 = __ldg(reinterpret_cast<const uint2*>(p00));
        const uint2 u01 = __ldg(reinterpret_cast<const uint2*>(p00 + 256));
        const uint2 u10 = __ldg(reinterpret_cast<const uint2*>(p00 + Wp * 256));
        const uint2 u11 = __ldg(reinterpret_cast<const uint2*>(p00 + (Wp + 1) * 256));

        __half2 sa = __hmul2(W00, *reinterpret_cast<const __half2*>(&u00.x));
        sa = __hfma2(W01, *reinterpret_cast<const __half2*>(&u01.x), sa);
        sa = __hfma2(W10, *reinterpret_cast<const __half2*>(&u10.x), sa);
        sa = __hfma2(W11, *reinterpret_cast<const __half2*>(&u11.x), sa);

        __half2 sb = __hmul2(W00, *reinterpret_cast<const __half2*>(&u00.y));
        sb = __hfma2(W01, *reinterpret_cast<const __half2*>(&u01.y), sb);
        sb = __hfma2(W10, *reinterpret_cast<const __half2*>(&u10.y), sb);
        sb = __hfma2(W11, *reinterpret_cast<const __half2*>(&u11.y), sb);

        const float2 fa = __half22float2(sa);
        const float2 fb = __half22float2(sb);
        acc0 += fa.x;
        acc1 += fa.y;
        acc2 += fb.x;
        acc3 += fb.y;
    }

    acc0 += __shfl_xor_sync(0xffffffffu, acc0, 8);
    acc1 += __shfl_xor_sync(0xffffffffu, acc1, 8);
    acc2 += __shfl_xor_sync(0xffffffffu, acc2, 8);
    acc3 += __shfl_xor_sync(0xffffffffu, acc3, 8);
    acc0 += __shfl_xor_sync(0xffffffffu, acc0, 16);
    acc1 += __shfl_xor_sync(0xffffffffu, acc1, 16);
    acc2 += __shfl_xor_sync(0xffffffffu, acc2, 16);
    acc3 += __shfl_xor_sync(0xffffffffu, acc3, 16);

    if (lane < 8) {
        __half2 h0 = __floats2half2_rn(acc0, acc1);
        __half2 h1 = __floats2half2_rn(acc2, acc3);
        uint2 u;
        u.x = *reinterpret_cast<uint32_t*>(&h0);
        u.y = *reinterpret_cast<uint32_t*>(&h1);
        *reinterpret_cast<uint2*>(mid + (size_t)q * 256 + m * DH + c4 * 4) = u;
    }
}

// ---------------------------------------------------------------------------
// Launch
// ---------------------------------------------------------------------------
extern "C" void kernel_launch(void* const* d_in, const int* in_sizes, int n_in,
                              void* d_out, int out_size)
{
    const float* query  = (const float*)d_in[0];
    const float* refp   = (const float*)d_in[1];
    const float* inflat = (const float*)d_in[2];
    const unsigned char* pmask = (const unsigned char*)d_in[3];
    const float* W_off  = (const float*)d_in[4];
    const float* b_off  = (const float*)d_in[5];
    const float* W_attn = (const float*)d_in[6];
    const float* b_attn = (const float*)d_in[7];
    const float* W_val  = (const float*)d_in[8];
    const float* b_val  = (const float*)d_in[9];
    const float* W_out  = (const float*)d_in[10];
    const float* b_out  = (const float*)d_in[11];
    float* out = (float*)d_out;

    __half* pvalp; cudaGetSymbolAddress((void**)&pvalp, g_value_pad);
    float*  poff;  cudaGetSymbolAddress((void**)&poff,  g_off);
    float*  pattn; cudaGetSymbolAddress((void**)&pattn, g_attn);
    float*  brep;  cudaGetSymbolAddress((void**)&brep,  g_brep);
    __half *q_h, *f_h, *w_h, *mid_h;
    cudaGetSymbolAddress((void**)&q_h,   g_q_h);
    cudaGetSymbolAddress((void**)&f_h,   g_f_h);
    cudaGetSymbolAddress((void**)&w_h,   g_w_h);
    cudaGetSymbolAddress((void**)&mid_h, g_mid_h);

    cudaFuncSetAttribute(proj_fused_kernel,
                         cudaFuncAttributeMaxDynamicSharedMemorySize, H_SMEM);
    cudaFuncSetAttribute(proj_out_kernel,
                         cudaFuncAttributeMaxDynamicSharedMemorySize, H_SMEM);

    const int Mr = LEN;
    const int mtiles = (Mr + 127) / 128;          // 156

    prep_all_kernel<<<(PREP_TOTAL + 255) / 256, 256>>>(
        W_val, W_off, W_attn, W_out, query, inflat, b_out, b_off,
        pvalp, w_h, q_h, f_h, brep);

    const __half* wv  = w_h;
    const __half* woa = w_h + 256 * 256;
    const __half* wu  = w_h + 640 * 256;
    const float* brep_out = brep;
    const float* brep_off = brep + 16 * 256;

    // 1. fused projections (persistent)
    proj_fused_kernel<<<PGRID, 128, H_SMEM>>>(
        f_h, q_h, wv, woa, b_val, b_attn, brep_off, pmask, pvalp, poff, pattn,
        Mr, 5 * mtiles);
    // 2. sampler (v7)
    sample_kernel<<<Mr, 256>>>(pvalp, poff, pattn, refp, mid_h);
    // 3. output projection (persistent, direct epilogue)
    proj_out_kernel<<<PGRID, 128, H_SMEM>>>(mid_h, wu, brep_out, out, Mr, 2 * mtiles);
}

// round 15
// speedup vs baseline: 3.7769x; 1.0172x over previous
#include <cuda_runtime.h>
#include <cuda_fp16.h>
#include <mma.h>
#include <cstdint>
#include <math.h>

using namespace nvcuda;

#define LEN    19947
#define NHEAD  8
#define DH     32
#define NLVL   4
#define NPTS   4

#define PAD_ROWS 21393

// ---------------------------------------------------------------------------
// Scratch (device globals)
// ---------------------------------------------------------------------------
__device__ __half g_value_pad[PAD_ROWS * 256];
__device__ float  g_off [LEN * 256];
__device__ float  g_attn[LEN * 128];
__device__ __half g_mid_h[LEN * 256];
__device__ __half g_q_h[LEN * 256];
__device__ __half g_f_h[LEN * 256];
__device__ __half g_w_h[896 * 256];
__device__ float  g_brep[2 * 16 * 256];   // [0]=b_out rep, [1]=b_off rep (16 rows)

__device__ __forceinline__ uint32_t smem_u32(const void* p) {
    uint32_t a;
    asm("{ .reg .u64 t; cvta.to.shared.u64 t, %1; cvt.u32.u64 %0, t; }" : "=r"(a) : "l"(p));
    return a;
}

__device__ __forceinline__ int pad_row(int gr) {
    int r, W, Wp, st;
    if (gr < 15000)      { r = gr;          W = 150; Wp = 153; st = 0; }
    else if (gr < 18750) { r = gr - 15000;  W = 75;  Wp = 78;  st = 15759; }
    else if (gr < 19700) { r = gr - 18750;  W = 38;  Wp = 41;  st = 19893; }
    else                 { r = gr - 19700;  W = 19;  Wp = 22;  st = 21041; }
    int y = r / W, x = r - y * W;
    return st + (y + 1) * Wp + (x + 1);
}

// ---------------------------------------------------------------------------
// Single fused prep kernel
// ---------------------------------------------------------------------------
#define PREP_A (PAD_ROWS * 32)
#define PREP_B (896 * 256)
#define PREP_C (2 * LEN * 64)
#define PREP_D (2 * 16 * 256)
#define PREP_TOTAL (PREP_A + PREP_B + PREP_C + PREP_D)

__global__ void prep_all_kernel(const float* __restrict__ W_val,
                                const float* __restrict__ W_off,
                                const float* __restrict__ W_attn,
                                const float* __restrict__ W_out,
                                const float* __restrict__ query,
                                const float* __restrict__ inflat,
                                const float* __restrict__ b_out,
                                const float* __restrict__ b_off,
                                __half* __restrict__ vp,
                                __half* __restrict__ wh,
                                __half* __restrict__ qh,
                                __half* __restrict__ fh,
                                float* __restrict__ brep)
{
    int id = blockIdx.x * blockDim.x + threadIdx.x;
    if (id < PREP_A) {
        *reinterpret_cast<uint4*>(vp + (size_t)id * 8) = make_uint4(0, 0, 0, 0);
    } else if (id < PREP_A + PREP_B) {
        int e = id - PREP_A;
        int n = e >> 8;
        int k = e & 255;
        float x;
        if (n < 256)      x = W_val [k * 256 + n];
        else if (n < 512) x = W_off [k * 256 + (n - 256)];
        else if (n < 640) x = W_attn[k * 128 + (n - 512)];
        else              x = W_out [k * 256 + (n - 640)];
        wh[e] = __float2half_rn(x);
    } else if (id < PREP_A + PREP_B + PREP_C) {
        int e = id - PREP_A - PREP_B;
        const int total4 = LEN * 64;
        const float* src;
        __half* dst;
        int i4 = e;
        if (e < total4) { src = query;  dst = qh; }
        else            { src = inflat; dst = fh; i4 -= total4; }
        float4 v = *reinterpret_cast<const float4*>(src + (size_t)i4 * 4);
        __half h[4] = {__float2half_rn(v.x), __float2half_rn(v.y),
                       __float2half_rn(v.z), __float2half_rn(v.w)};
        *reinterpret_cast<uint2*>(dst + (size_t)i4 * 4) = *reinterpret_cast<uint2*>(h);
    } else if (id < PREP_TOTAL) {
        int e = id - PREP_A - PREP_B - PREP_C;
        int half_sel = e >> 12;          // 0: b_out, 1: b_off
        int col = e & 255;
        brep[e] = half_sel ? b_off[col] : b_out[col];
    }
}

// ---------------------------------------------------------------------------
// cp.async macros
// ---------------------------------------------------------------------------
#define CP16(dst, src, sz) \
    asm volatile("cp.async.cg.shared.global [%0], [%1], 16, %2;" \
                 :: "r"(dst), "l"(src), "r"(sz))
#define CP_COMMIT() asm volatile("cp.async.commit_group;")
#define CP_WAIT1()  asm volatile("cp.async.wait_group 1;")
#define CP_WAIT0()  asm volatile("cp.async.wait_group 0;")

// Block tile 64x128, BK=64, 2-stage, 128 threads / 4 warps, warp tile 32x64
#define ASTR 72
#define A64_BUF (64 * ASTR * 2)        // 9216
#define B64_BUF (128 * ASTR * 2)       // 18432
#define STAGE64 (A64_BUF + B64_BUF)    // 27648
#define CSTRIDE 132
#define H_SMEM (2 * STAGE64)           // 55296 (epilogue stage 64*132*4=33792 fits)
#define PGRID 444                      // 3 CTAs x 148 SMs

// ---------------------------------------------------------------------------
// GEMM mainloop: block tile 64x128, warp tile 32x64, BK=64, 2-stage.
// ---------------------------------------------------------------------------
__device__ __forceinline__ void gemm_mainloop(
    const __half* __restrict__ A, const __half* __restrict__ B,
    char* smem, int block_m, int block_n, int Mrows,
    wmma::fragment<wmma::accumulator, 16, 16, 16, float> (&acc)[2][4])
{
    const int tid  = threadIdx.x;
    const int warp = tid >> 5;
    const int wm   = warp & 1;
    const int wn   = warp >> 1;
    const uint32_t sb = smem_u32(smem);

#pragma unroll
    for (int i = 0; i < 2; i++)
#pragma unroll
        for (int j = 0; j < 4; j++) wmma::fill_fragment(acc[i][j], 0.f);

    auto issue = [&](int chunk) {
        const int s = chunk & 1;
        const int k0 = chunk * 64;
        const uint32_t sbase = sb + s * STAGE64;
        // A: 64 rows -> 512 x 16B chunks
#pragma unroll
        for (int h = 0; h < 4; h++) {
            const int c   = tid + h * 128;
            const int row = c >> 3;
            const int prt = (c & 7) * 8;
            const uint32_t so = (uint32_t)(row * ASTR + prt) * 2;
            const int ga  = block_m + row;
            const int asz = (ga < Mrows) ? 16 : 0;
            CP16(sbase + so, A + (size_t)ga * 256 + k0 + prt, asz);
        }
        // B: 128 rows -> 1024 x 16B chunks
#pragma unroll
        for (int h = 0; h < 8; h++) {
            const int c   = tid + h * 128;
            const int row = c >> 3;
            const int prt = (c & 7) * 8;
            const uint32_t so = (uint32_t)(row * ASTR + prt) * 2;
            CP16(sbase + A64_BUF + so, B + (size_t)(block_n + row) * 256 + k0 + prt, 16);
        }
    };

    issue(0);
    CP_COMMIT();

    for (int chunk = 0; chunk < 4; chunk++) {
        if (chunk < 3) { issue(chunk + 1); CP_COMMIT(); CP_WAIT1(); }
        else           { CP_WAIT0(); }
        __syncthreads();

        const int s = chunk & 1;
        const __half* ab = reinterpret_cast<const __half*>(smem + s * STAGE64);
        const __half* bb = ab + 64 * ASTR;

#pragma unroll
        for (int ks = 0; ks < 64; ks += 16) {
            wmma::fragment<wmma::matrix_a, 16, 16, 16, __half, wmma::row_major> fa[2];
            wmma::fragment<wmma::matrix_b, 16, 16, 16, __half, wmma::col_major> fb[4];
#pragma unroll
            for (int i = 0; i < 2; i++)
                wmma::load_matrix_sync(fa[i], ab + (wm * 32 + i * 16) * ASTR + ks, ASTR);
#pragma unroll
            for (int j = 0; j < 4; j++)
                wmma::load_matrix_sync(fb[j], bb + (wn * 64 + j * 16) * ASTR + ks, ASTR);
#pragma unroll
            for (int i = 0; i < 2; i++)
#pragma unroll
                for (int j = 0; j < 4; j++) wmma::mma_sync(acc[i][j], fa[i], fb[j], acc[i][j]);
        }
        __syncthreads();
    }
}

__device__ __forceinline__ void stage_acc(
    wmma::fragment<wmma::accumulator, 16, 16, 16, float> (&acc)[2][4], char* smem)
{
    const int warp = threadIdx.x >> 5;
    const int wm   = warp & 1;
    const int wn   = warp >> 1;
    float* stage = reinterpret_cast<float*>(smem);
#pragma unroll
    for (int i = 0; i < 2; i++)
#pragma unroll
        for (int j = 0; j < 4; j++)
            wmma::store_matrix_sync(stage + (wm * 32 + i * 16) * CSTRIDE + wn * 64 + j * 16,
                                    acc[i][j], CSTRIDE, wmma::mem_row_major);
    __syncthreads();
}

__device__ __forceinline__ void direct_epilogue(
    wmma::fragment<wmma::accumulator, 16, 16, 16, float> (&acc)[2][4],
    const float* __restrict__ brep, float* __restrict__ C,
    int block_m, int block_n)
{
    const int warp = threadIdx.x >> 5;
    const int wm   = warp & 1;
    const int wn   = warp >> 1;
#pragma unroll
    for (int j = 0; j < 4; j++) {
        wmma::fragment<wmma::accumulator, 16, 16, 16, float> bf;
        wmma::load_matrix_sync(bf, brep + block_n + wn * 64 + j * 16, 256, wmma::mem_row_major);
#pragma unroll
        for (int i = 0; i < 2; i++) {
            wmma::fragment<wmma::accumulator, 16, 16, 16, float> t;
#pragma unroll
            for (int e = 0; e < t.num_elements; e++) t.x[e] = acc[i][j].x[e] + bf.x[e];
            wmma::store_matrix_sync(C + (size_t)(block_m + wm * 32 + i * 16) * 256
                                      + block_n + wn * 64 + j * 16,
                                    t, 256, wmma::mem_row_major);
        }
    }
}

// ---------------------------------------------------------------------------
// Fused projection kernel (persistent): 1560 tiles (312 m-tiles x 5).
// ---------------------------------------------------------------------------
__global__ __launch_bounds__(128, 3)
void proj_fused_kernel(const __half* __restrict__ Af,
                       const __half* __restrict__ Aq,
                       const __half* __restrict__ Bv,
                       const __half* __restrict__ Boa,
                       const float* __restrict__ b_val,
                       const float* __restrict__ b_attn,
                       const float* __restrict__ brep_off,
                       const unsigned char* __restrict__ mask,
                       __half* __restrict__ Cval,
                       float* __restrict__ Coff,
                       float* __restrict__ Cattn,
                       int Mrows, int ntiles)
{
    extern __shared__ char smem[];
    const int tid = threadIdx.x;

    for (int t = blockIdx.x; t < ntiles; t += PGRID) {
        const int bx = t % 5;
        const int mt = t / 5;
        const bool is_val = (bx < 2);
        const int block_m = mt * 64;
        const int block_n = (is_val ? bx : bx - 2) * 128;

        wmma::fragment<wmma::accumulator, 16, 16, 16, float> acc[2][4];
        gemm_mainloop(is_val ? Af : Aq, is_val ? Bv : Boa, smem, block_m, block_n, Mrows, acc);

        if (bx == 2 || bx == 3) {
            if (block_m + 64 <= Mrows) {
                direct_epilogue(acc, brep_off, Coff, block_m, block_n);
                __syncthreads();
                continue;
            }
        }

        stage_acc(acc, smem);
        const float* stage = reinterpret_cast<const float*>(smem);
        const int r    = tid >> 1;                // 0..63
        const int colb = (tid & 1) * 64;
        const int gr   = block_m + r;
        if (gr < Mrows) {
            if (is_val) {
                const int prow = pad_row(gr);
                const float scale = (mask != nullptr && mask[gr]) ? 0.f : 1.f;
#pragma unroll
                for (int g = 0; g < 64; g += 16) {
                    const int gcol = block_n + colb + g;
                    __half hbuf[16];
#pragma unroll
                    for (int c = 0; c < 16; c++)
                        hbuf[c] = __float2half_rn((stage[r * CSTRIDE + colb + g + c] + __ldg(b_val + gcol + c)) * scale);
#pragma unroll
                    for (int c = 0; c < 16; c += 8)
                        *reinterpret_cast<uint4*>(Cval + (size_t)prow * 256 + gcol + c) =
                            *reinterpret_cast<uint4*>(hbuf + c);
                }
            } else if (bx == 4) {
#pragma unroll
                for (int g = 0; g < 64; g += 16) {
                    const int gc = colb + g;      // attn col (block_n=256)
                    float v[16];
#pragma unroll
                    for (int c = 0; c < 16; c++)
                        v[c] = stage[r * CSTRIDE + colb + g + c] + __ldg(b_attn + gc + c);
                    float mx = -1e30f;
#pragma unroll
                    for (int c = 0; c < 16; c++) mx = fmaxf(mx, v[c]);
                    float sum = 0.f;
#pragma unroll
                    for (int c = 0; c < 16; c++) { v[c] = __expf(v[c] - mx); sum += v[c]; }
                    float inv = 1.f / sum;
#pragma unroll
                    for (int c = 0; c < 16; c += 4) {
                        float4 o = make_float4(v[c]*inv, v[c+1]*inv, v[c+2]*inv, v[c+3]*inv);
                        *reinterpret_cast<float4*>(Cattn + (size_t)gr * 128 + gc + c) = o;
                    }
                }
            } else {
#pragma unroll
                for (int g = 0; g < 64; g += 16) {
                    const int gcol = block_n + colb + g;
                    float v[16];
#pragma unroll
                    for (int c = 0; c < 16; c++)
                        v[c] = stage[r * CSTRIDE + colb + g + c] + __ldg(brep_off + gcol + c);
#pragma unroll
                    for (int c = 0; c < 16; c += 4) {
                        float4 o = make_float4(v[c], v[c+1], v[c+2], v[c+3]);
                        *reinterpret_cast<float4*>(Coff + (size_t)gr * 256 + gcol + c) = o;
                    }
                }
            }
        }
        __syncthreads();
    }
}

// ---------------------------------------------------------------------------
// Output projection kernel (persistent): 624 tiles (312 m-tiles x 2).
// ---------------------------------------------------------------------------
__global__ __launch_bounds__(128, 3)
void proj_out_kernel(const __half* __restrict__ A,
                     const __half* __restrict__ B,
                     const float* __restrict__ brep_out,
                     float* __restrict__ C,
                     int Mrows, int ntiles)
{
    extern __shared__ char smem[];
    const int tid = threadIdx.x;

    for (int t = blockIdx.x; t < ntiles; t += PGRID) {
        const int block_n = (t & 1) * 128;
        const int block_m = (t >> 1) * 64;

        wmma::fragment<wmma::accumulator, 16, 16, 16, float> acc[2][4];
        gemm_mainloop(A, B, smem, block_m, block_n, Mrows, acc);

        if (block_m + 64 <= Mrows) {
            direct_epilogue(acc, brep_out, C, block_m, block_n);
        } else {
            stage_acc(acc, smem);
            const float* stage = reinterpret_cast<const float*>(smem);
            const int r    = tid >> 1;
            const int colb = (tid & 1) * 64;
            const int gr   = block_m + r;
            if (gr < Mrows) {
#pragma unroll
                for (int g = 0; g < 64; g += 16) {
                    const int gcol = block_n + colb + g;
                    float v[16];
#pragma unroll
                    for (int c = 0; c < 16; c++)
                        v[c] = stage[r * CSTRIDE + colb + g + c] + __ldg(brep_out + gcol + c);
#pragma unroll
                    for (int c = 0; c < 16; c += 4) {
                        float4 o = make_float4(v[c], v[c+1], v[c+2], v[c+3]);
                        *reinterpret_cast<float4*>(C + (size_t)gr * 256 + gcol + c) = o;
                    }
                }
            }
        }
        __syncthreads();
    }
}

// ---------------------------------------------------------------------------
// Sampler v7 (proven best)
// ---------------------------------------------------------------------------
__global__ __launch_bounds__(256)
void sample_kernel(const __half* __restrict__ value,
                   const float* __restrict__ off,
                   const float* __restrict__ aw,
                   const float* __restrict__ refp,
                   __half* __restrict__ mid)
{
    const int q    = blockIdx.x;
    const int m    = threadIdx.x >> 5;
    const int lane = threadIdx.x & 31;
    const int p2   = lane >> 3;
    const int c4   = lane & 7;

    const float offv = __ldg(off  + (size_t)q * 256 + m * 32 + lane);
    const float awv  = __ldg(aw   + (size_t)q * 128 + m * 16 + (lane & 15));
    const float rfv  = __ldg(refp + (size_t)q * 8 + (lane & 7));

    const int pt0 = lane & 15;
    const int l0  = pt0 >> 2;
    const float rx = __shfl_sync(0xffffffffu, rfv, l0 * 2 + 0);
    const float ry = __shfl_sync(0xffffffffu, rfv, l0 * 2 + 1);
    const float ox = __shfl_sync(0xffffffffu, offv, pt0 * 2 + 0);
    const float oy = __shfl_sync(0xffffffffu, offv, pt0 * 2 + 1);

    const float Wf = (l0 == 0) ? 150.f : (l0 == 1) ? 75.f : (l0 == 2) ? 38.f : 19.f;
    const float Hf = (l0 == 0) ? 100.f : (l0 == 1) ? 50.f : (l0 == 2) ? 25.f : 13.f;
    const int   Wp0 = (l0 == 0) ? 153 : (l0 == 1) ? 78 : (l0 == 2) ? 41 : 22;
    const int   SB0 = (l0 == 0) ? 154 : (l0 == 1) ? 15838 : (l0 == 2) ? 19935 : 21064;

    float x = fmaf(rx, Wf, ox) - 0.5f;
    float y = fmaf(ry, Hf, oy) - 0.5f;
    x = fminf(fmaxf(x, -1.f), Wf);
    y = fminf(fmaxf(y, -1.f), Hf);

    const float x0f = floorf(x), y0f = floorf(y);
    const float wx1 = x - x0f, wx0 = 1.f - wx1;
    const float wy1 = y - y0f, wy0 = 1.f - wy1;
    const int i00r = SB0 + (int)y0f * Wp0 + (int)x0f;

    __half2 pk01h = __floats2half2_rn(wx0 * wy0 * awv, wx1 * wy0 * awv);
    __half2 pk23h = __floats2half2_rn(wx0 * wy1 * awv, wx1 * wy1 * awv);
    const uint32_t pk01 = *reinterpret_cast<uint32_t*>(&pk01h);
    const uint32_t pk23 = *reinterpret_cast<uint32_t*>(&pk23h);

    const __half* vbase = value + m * DH + c4 * 4;
    float acc0 = 0.f, acc1 = 0.f, acc2 = 0.f, acc3 = 0.f;

    const int WPT[NLVL] = {153, 78, 41, 22};

#pragma unroll
    for (int l = 0; l < NLVL; l++) {
        const int src = l * 4 + p2;
        const int i00 = __shfl_sync(0xffffffffu, i00r, src);
        const uint32_t a01 = __shfl_sync(0xffffffffu, pk01, src);
        const uint32_t a23 = __shfl_sync(0xffffffffu, pk23, src);

        const __half2 h01 = *reinterpret_cast<const __half2*>(&a01);
        const __half2 h23 = *reinterpret_cast<const __half2*>(&a23);
        const __half2 W00 = __low2half2(h01),  W01 = __high2half2(h01);
        const __half2 W10 = __low2half2(h23),  W11 = __high2half2(h23);

        const int Wp = WPT[l];
        const __half* p00 = vbase + (size_t)i00 * 256;

        const uint2 u00 = __ldg(reinterpret_cast<const uint2*>(p00));
        const uint2 u01 = __ldg(reinterpret_cast<const uint2*>(p00 + 256));
        const uint2 u10 = __ldg(reinterpret_cast<const uint2*>(p00 + Wp * 256));
        const uint2 u11 = __ldg(reinterpret_cast<const uint2*>(p00 + (Wp + 1) * 256));

        __half2 sa = __hmul2(W00, *reinterpret_cast<const __half2*>(&u00.x));
        sa = __hfma2(W01, *reinterpret_cast<const __half2*>(&u01.x), sa);
        sa = __hfma2(W10, *reinterpret_cast<const __half2*>(&u10.x), sa);
        sa = __hfma2(W11, *reinterpret_cast<const __half2*>(&u11.x), sa);

        __half2 sb = __hmul2(W00, *reinterpret_cast<const __half2*>(&u00.y));
        sb = __hfma2(W01, *reinterpret_cast<const __half2*>(&u01.y), sb);
        sb = __hfma2(W10, *reinterpret_cast<const __half2*>(&u10.y), sb);
        sb = __hfma2(W11, *reinterpret_cast<const __half2*>(&u11.y), sb);

        const float2 fa = __half22float2(sa);
        const float2 fb = __half22float2(sb);
        acc0 += fa.x;
        acc1 += fa.y;
        acc2 += fb.x;
        acc3 += fb.y;
    }

    acc0 += __shfl_xor_sync(0xffffffffu, acc0, 8);
    acc1 += __shfl_xor_sync(0xffffffffu, acc1, 8);
    acc2 += __shfl_xor_sync(0xffffffffu, acc2, 8);
    acc3 += __shfl_xor_sync(0xffffffffu, acc3, 8);
    acc0 += __shfl_xor_sync(0xffffffffu, acc0, 16);
    acc1 += __shfl_xor_sync(0xffffffffu, acc1, 16);
    acc2 += __shfl_xor_sync(0xffffffffu, acc2, 16);
    acc3 += __shfl_xor_sync(0xffffffffu, acc3, 16);

    if (lane < 8) {
        __half2 h0 = __floats2half2_rn(acc0, acc1);
        __half2 h1 = __floats2half2_rn(acc2, acc3);
        uint2 u;
        u.x = *reinterpret_cast<uint32_t*>(&h0);
        u.y = *reinterpret_cast<uint32_t*>(&h1);
        *reinterpret_cast<uint2*>(mid + (size_t)q * 256 + m * DH + c4 * 4) = u;
    }
}

// ---------------------------------------------------------------------------
// Launch
// ---------------------------------------------------------------------------
extern "C" void kernel_launch(void* const* d_in, const int* in_sizes, int n_in,
                              void* d_out, int out_size)
{
    const float* query  = (const float*)d_in[0];
    const float* refp   = (const float*)d_in[1];
    const float* inflat = (const float*)d_in[2];
    const unsigned char* pmask = (const unsigned char*)d_in[3];
    const float* W_off  = (const float*)d_in[4];
    const float* b_off  = (const float*)d_in[5];
    const float* W_attn = (const float*)d_in[6];
    const float* b_attn = (const float*)d_in[7];
    const float* W_val  = (const float*)d_in[8];
    const float* b_val  = (const float*)d_in[9];
    const float* W_out  = (const float*)d_in[10];
    const float* b_out  = (const float*)d_in[11];
    float* out = (float*)d_out;

    __half* pvalp; cudaGetSymbolAddress((void**)&pvalp, g_value_pad);
    float*  poff;  cudaGetSymbolAddress((void**)&poff,  g_off);
    float*  pattn; cudaGetSymbolAddress((void**)&pattn, g_attn);
    float*  brep;  cudaGetSymbolAddress((void**)&brep,  g_brep);
    __half *q_h, *f_h, *w_h, *mid_h;
    cudaGetSymbolAddress((void**)&q_h,   g_q_h);
    cudaGetSymbolAddress((void**)&f_h,   g_f_h);
    cudaGetSymbolAddress((void**)&w_h,   g_w_h);
    cudaGetSymbolAddress((void**)&mid_h, g_mid_h);

    cudaFuncSetAttribute(proj_fused_kernel,
                         cudaFuncAttributeMaxDynamicSharedMemorySize, H_SMEM);
    cudaFuncSetAttribute(proj_out_kernel,
                         cudaFuncAttributeMaxDynamicSharedMemorySize, H_SMEM);

    const int Mr = LEN;
    const int mtiles = (Mr + 63) / 64;            // 312

    prep_all_kernel<<<(PREP_TOTAL + 255) / 256, 256>>>(
        W_val, W_off, W_attn, W_out, query, inflat, b_out, b_off,
        pvalp, w_h, q_h, f_h, brep);

    const __half* wv  = w_h;
    const __half* woa = w_h + 256 * 256;
    const __half* wu  = w_h + 640 * 256;
    const float* brep_out = brep;
    const float* brep_off = brep + 16 * 256;

    // 1. fused projections (persistent, 64-row tiles, 3 CTAs/SM)
    proj_fused_kernel<<<PGRID, 128, H_SMEM>>>(
        f_h, q_h, wv, woa, b_val, b_attn, brep_off, pmask, pvalp, poff, pattn,
        Mr, 5 * mtiles);
    // 2. sampler (v7)
    sample_kernel<<<Mr, 256>>>(pvalp, poff, pattn, refp, mid_h);
    // 3. output projection (persistent, 64-row tiles, 3 CTAs/SM)
    proj_out_kernel<<<PGRID, 128, H_SMEM>>>(mid_h, wu, brep_out, out, Mr, 2 * mtiles);
}